// round 13
// baseline (speedup 1.0000x reference)
#include <cuda_runtime.h>
#include <cuda_bf16.h>
#include <math.h>
#include <stdint.h>

#define Bsz 512
#define Tc  64
#define Ed  512
#define Vd  256

__device__ float g_xgates[67108864];   // (T,B,4E)
__device__ float g_h0    [262144];
__device__ float g_c     [262144];
__device__ float g_hs    [16777216];   // (T,B,E)
__device__ float g_qc    [16777216];
__device__ float g_kc    [16777216];
__device__ float g_vc    [16777216];
__device__ float g_qt    [16777216];
__device__ float g_kt    [4194304];
__device__ float g_vt    [4194304];
__device__ float g_oc    [16777216];
__device__ float g_ot    [16777216];
__device__ float g_lg    [8388608];    // (T,B,V)
__device__ float g_bias2 [2048];
__device__ float g_Wc    [131072];     // (V,E)
__device__ float g_Wt    [131072];
__device__ float g_cwoT  [262144];
__device__ float g_twoT  [262144];
__device__ float g_bcomb [256];

__device__ __nv_bfloat16 g_whhH[1048576], g_whhL[1048576];
__device__ __nv_bfloat16 g_wihH[524288],  g_wihL[524288];
__device__ __nv_bfloat16 g_cwkH[262144],  g_cwkL[262144];
__device__ __nv_bfloat16 g_cwvH[262144],  g_cwvL[262144];
__device__ __nv_bfloat16 g_cwqH[262144],  g_cwqL[262144];
__device__ __nv_bfloat16 g_twkH[262144],  g_twkL[262144];
__device__ __nv_bfloat16 g_twvH[262144],  g_twvL[262144];
__device__ __nv_bfloat16 g_twqH[262144],  g_twqL[262144];
__device__ __nv_bfloat16 g_WcH[131072],   g_WcL[131072];
__device__ __nv_bfloat16 g_WtH[131072],   g_WtL[131072];

__device__ unsigned g_cnt;
__device__ volatile unsigned g_epoch;

// ======================= helpers ===========================================
__device__ __forceinline__ void ffma2(unsigned long long& d, unsigned long long a,
                                      unsigned long long b) {
    asm("fma.rn.f32x2 %0, %1, %2, %0;" : "+l"(d) : "l"(a), "l"(b));
}
__device__ __forceinline__ unsigned long long pack2(float x, float y) {
    unsigned long long r;
    asm("mov.b64 %0, {%1, %2};" : "=l"(r) : "r"(__float_as_uint(x)), "r"(__float_as_uint(y)));
    return r;
}
__device__ __forceinline__ void unpack2(unsigned long long d, float& lo, float& hi) {
    unsigned int l, h;
    asm("mov.b64 {%0, %1}, %2;" : "=r"(l), "=r"(h) : "l"(d));
    lo = __uint_as_float(l); hi = __uint_as_float(h);
}
__device__ __forceinline__ float sigmoidf_(float x) { return 1.0f / (1.0f + expf(-x)); }

__device__ __forceinline__ void mma16816(float* c, const uint32_t* a, uint32_t b0, uint32_t b1) {
    asm volatile(
        "mma.sync.aligned.m16n8k16.row.col.f32.bf16.bf16.f32 "
        "{%0,%1,%2,%3}, {%4,%5,%6,%7}, {%8,%9}, {%0,%1,%2,%3};"
        : "+f"(c[0]), "+f"(c[1]), "+f"(c[2]), "+f"(c[3])
        : "r"(a[0]), "r"(a[1]), "r"(a[2]), "r"(a[3]), "r"(b0), "r"(b1));
}
__device__ __forceinline__ void ldsm_x4(uint32_t* r, uint32_t addr) {
    asm volatile("ldmatrix.sync.aligned.m8n8.x4.shared.b16 {%0,%1,%2,%3}, [%4];"
                 : "=r"(r[0]), "=r"(r[1]), "=r"(r[2]), "=r"(r[3]) : "r"(addr));
}
__device__ __forceinline__ void ldsm_x2(uint32_t& r0, uint32_t& r1, uint32_t addr) {
    asm volatile("ldmatrix.sync.aligned.m8n8.x2.shared.b16 {%0,%1}, [%2];"
                 : "=r"(r0), "=r"(r1) : "r"(addr));
}
__device__ __forceinline__ void cvt_split4(float4 v, uint2& hi, uint2& lo) {
    __nv_bfloat16 h0 = __float2bfloat16(v.x), h1 = __float2bfloat16(v.y);
    __nv_bfloat16 h2 = __float2bfloat16(v.z), h3 = __float2bfloat16(v.w);
    __nv_bfloat16 l0 = __float2bfloat16(v.x - __bfloat162float(h0));
    __nv_bfloat16 l1 = __float2bfloat16(v.y - __bfloat162float(h1));
    __nv_bfloat16 l2 = __float2bfloat16(v.z - __bfloat162float(h2));
    __nv_bfloat16 l3 = __float2bfloat16(v.w - __bfloat162float(h3));
    hi.x = (uint32_t)__bfloat16_as_ushort(h0) | ((uint32_t)__bfloat16_as_ushort(h1) << 16);
    hi.y = (uint32_t)__bfloat16_as_ushort(h2) | ((uint32_t)__bfloat16_as_ushort(h3) << 16);
    lo.x = (uint32_t)__bfloat16_as_ushort(l0) | ((uint32_t)__bfloat16_as_ushort(l1) << 16);
    lo.y = (uint32_t)__bfloat16_as_ushort(l2) | ((uint32_t)__bfloat16_as_ushort(l3) << 16);
}

__global__ void __launch_bounds__(256) conv_split_k(
    const float* __restrict__ s, __nv_bfloat16* __restrict__ h,
    __nv_bfloat16* __restrict__ l, int n)
{
    int i = blockIdx.x * 256 + threadIdx.x;
    if (i < n) {
        float v = s[i];
        __nv_bfloat16 hv = __float2bfloat16(v);
        h[i] = hv;
        l[i] = __float2bfloat16(v - __bfloat162float(hv));
    }
}

// ---------------------------------------------------------------------------
// mma.sync GEMM (NT), CTA 256x128, 512 threads / 16 warps (4m x 4n),
// warp tile 64x32, K-chunk 32. Plane-major MMA order (dep distance 8).
// smem u32: AH 0 (2x5120), AL 10240, BH 20480 (2x2560), BL 25600; tot 30720.
// ---------------------------------------------------------------------------
template <int MODE>
__global__ void __launch_bounds__(512) mma_gemm2(
    float* __restrict__ C, const float* __restrict__ A, const float* __restrict__ A2,
    const __nv_bfloat16* __restrict__ BH, const __nv_bfloat16* __restrict__ BL,
    const __nv_bfloat16* __restrict__ BH2, const __nv_bfloat16* __restrict__ BL2,
    const float* __restrict__ bias, int M, int N, int K, int lda, int ldb, float alpha)
{
    extern __shared__ uint32_t sm[];

    const int tid  = threadIdx.x;
    const int lane = tid & 31, wid = tid >> 5;
    const int wm = wid >> 2, wn = wid & 3;       // 4m x 4n
    const int m0 = blockIdx.y * 256, n0 = blockIdx.x * 128;
    const int gq = lane >> 2, pl = lane & 3;

    const uint32_t sb4 = (uint32_t)__cvta_generic_to_shared(sm);
    const int arow  = (lane & 7) + ((lane >> 3) & 1) * 8;
    const int akoff = (lane >> 4) * 4;
    const int brow  = lane & 7;
    const int bkoff = ((lane >> 3) & 1) * 4;

    float c[4][4][4];
#pragma unroll
    for (int i = 0; i < 4; i++)
#pragma unroll
        for (int j = 0; j < 4; j++)
#pragma unroll
            for (int q = 0; q < 4; q++) c[i][j][q] = 0.f;

    float4 avr[4];
    uint4 bhr, blr;

    auto gload = [&](int ch) {
        const float* Ae = A;
        const __nv_bfloat16 *bh = BH, *bl = BL;
        int k0 = ch << 5;
        if (MODE == 2 && k0 >= 512) { Ae = A2; bh = BH2; bl = BL2; k0 -= 512; }
#pragma unroll
        for (int i = 0; i < 4; i++) {
            int f = tid + i * 512, r = f >> 3, cq = f & 7;
            if constexpr (MODE == 1) {
                int gm = m0 + r, tt = gm >> 9, bb = gm & 511;
                avr[i] = tt ? *reinterpret_cast<const float4*>(Ae + (size_t)bb * 16384 + tt * 256 + k0 + cq * 4)
                            : make_float4(0.f, 0.f, 0.f, 0.f);
            } else {
                avr[i] = *reinterpret_cast<const float4*>(Ae + (size_t)(m0 + r) * lda + k0 + cq * 4);
            }
        }
        {
            int r = tid >> 2, cq = tid & 3;
            bhr = *reinterpret_cast<const uint4*>(bh + (size_t)(n0 + r) * ldb + k0 + cq * 8);
            blr = *reinterpret_cast<const uint4*>(bl + (size_t)(n0 + r) * ldb + k0 + cq * 8);
        }
    };
    auto sstore = [&](int buf) {
        const int ab = buf * 5120;
#pragma unroll
        for (int i = 0; i < 4; i++) {
            int f = tid + i * 512, r = f >> 3, cq = f & 7;
            uint2 hi, lo;
            cvt_split4(avr[i], hi, lo);
            int idx = ab + r * 20 + cq * 2;
            *reinterpret_cast<uint2*>(&sm[idx])         = hi;
            *reinterpret_cast<uint2*>(&sm[10240 + idx]) = lo;
        }
        {
            int r = tid >> 2, cq = tid & 3;
            int idx = buf * 2560 + r * 20 + cq * 4;
            *reinterpret_cast<uint4*>(&sm[20480 + idx]) = bhr;
            *reinterpret_cast<uint4*>(&sm[25600 + idx]) = blr;
        }
    };

    const int nch = K >> 5;
    gload(0);
    sstore(0);
    __syncthreads();

    for (int ch = 0; ch < nch; ch++) {
        const int buf = ch & 1;
        const bool more = (ch + 1 < nch);
        if (more) gload(ch + 1);
        const int ab = buf * 5120;
        const int bb = buf * 2560;
#pragma unroll
        for (int s = 0; s < 2; s++) {
            uint32_t bh0[4], bh1[4], bl0[4], bl1[4];
#pragma unroll
            for (int nf = 0; nf < 4; nf++) {
                uint32_t baddr = sb4 + 4u * (uint32_t)(20480 + bb + (wn * 32 + nf * 8 + brow) * 20 + s * 8 + bkoff);
                ldsm_x2(bh0[nf], bh1[nf], baddr);
                ldsm_x2(bl0[nf], bl1[nf], baddr + 5120u * 4u);
            }
            // process mf in pairs, plane-major (dep distance 8 between reuses of c)
#pragma unroll
            for (int mp = 0; mp < 2; mp++) {
                const int mf0 = mp * 2, mf1 = mp * 2 + 1;
                uint32_t a0[4], a1[4];
                uint32_t aaddr0 = sb4 + 4u * (uint32_t)(ab + (wm * 64 + mf0 * 16 + arow) * 20 + s * 8 + akoff);
                uint32_t aaddr1 = sb4 + 4u * (uint32_t)(ab + (wm * 64 + mf1 * 16 + arow) * 20 + s * 8 + akoff);
                ldsm_x4(a0, aaddr0);
                ldsm_x4(a1, aaddr1);
                // plane hh
#pragma unroll
                for (int nf = 0; nf < 4; nf++) mma16816(c[mf0][nf], a0, bh0[nf], bh1[nf]);
#pragma unroll
                for (int nf = 0; nf < 4; nf++) mma16816(c[mf1][nf], a1, bh0[nf], bh1[nf]);
                // plane hl
#pragma unroll
                for (int nf = 0; nf < 4; nf++) mma16816(c[mf0][nf], a0, bl0[nf], bl1[nf]);
#pragma unroll
                for (int nf = 0; nf < 4; nf++) mma16816(c[mf1][nf], a1, bl0[nf], bl1[nf]);
                // plane lh (reload A as lo, overwriting a0/a1)
                ldsm_x4(a0, aaddr0 + 10240u * 4u);
                ldsm_x4(a1, aaddr1 + 10240u * 4u);
#pragma unroll
                for (int nf = 0; nf < 4; nf++) mma16816(c[mf0][nf], a0, bh0[nf], bh1[nf]);
#pragma unroll
                for (int nf = 0; nf < 4; nf++) mma16816(c[mf1][nf], a1, bh0[nf], bh1[nf]);
            }
        }
        if (more) {
            sstore(buf ^ 1);
            __syncthreads();
        }
    }

#pragma unroll
    for (int mf = 0; mf < 4; mf++) {
#pragma unroll
        for (int nf = 0; nf < 4; nf++) {
            int r  = m0 + wm * 64 + mf * 16 + gq;
            int cc = n0 + wn * 32 + nf * 8 + pl * 2;
            float b0 = 0.f, b1 = 0.f;
            if (bias) { b0 = bias[cc]; b1 = bias[cc + 1]; }
            *reinterpret_cast<float2*>(&C[(size_t)r * N + cc]) =
                make_float2(alpha * (c[mf][nf][0] + b0), alpha * (c[mf][nf][1] + b1));
            *reinterpret_cast<float2*>(&C[(size_t)(r + 8) * N + cc]) =
                make_float2(alpha * (c[mf][nf][2] + b0), alpha * (c[mf][nf][3] + b1));
        }
    }
}

// ---------------------------------------------------------------------------
// Persistent LSTM: 128 CTAs, internal t-loop, software grid barrier.
// Plane-major MMA order (dep distance 8).
// ---------------------------------------------------------------------------
#define LP_BH 0
#define LP_BL 16640
#define LP_A  33280
#define LP_SMEM_BYTES (43520 * 4)

__device__ __forceinline__ void grid_barrier128(int tid) {
    __threadfence();
    __syncthreads();
    if (tid == 0) {
        unsigned e = g_epoch;
        if (atomicAdd(&g_cnt, 1u) == 127u) {
            g_cnt = 0;
            __threadfence();
            g_epoch = e + 1;
        } else {
            while (g_epoch == e) { }
        }
    }
    __syncthreads();
}

__global__ void __launch_bounds__(256) lstm_persist(
    const float* __restrict__ h0,
    const __nv_bfloat16* __restrict__ whhH, const __nv_bfloat16* __restrict__ whhL,
    const float* __restrict__ xg, const float* __restrict__ bias2,
    const float* __restrict__ c0, float* __restrict__ hs)
{
    extern __shared__ uint32_t sm[];
    const int tid  = threadIdx.x;
    const int lane = tid & 31, wid = tid >> 5;
    const int wm = wid >> 2, wn = wid & 3;
    const int e0 = blockIdx.x * 16;
    const int m0 = blockIdx.y * 128;
    const int gq = lane >> 2, pl = lane & 3;

    const uint32_t sb4 = (uint32_t)__cvta_generic_to_shared(sm);
    const int arow  = (lane & 7) + ((lane >> 3) & 1) * 8;
    const int akoff = (lane >> 4) * 4;
    const int brow  = lane & 7;
    const int bkoff = ((lane >> 3) & 1) * 4;

#pragma unroll
    for (int i = 0; i < 16; i++) {
        int f = tid + i * 256;
        int r = f >> 6, q = f & 63;
        int gr = (r >> 4) * 512 + e0 + (r & 15);
        *reinterpret_cast<uint4*>(&sm[LP_BH + r * 260 + q * 4]) =
            *reinterpret_cast<const uint4*>(whhH + (size_t)gr * 512 + q * 8);
        *reinterpret_cast<uint4*>(&sm[LP_BL + r * 260 + q * 4]) =
            *reinterpret_cast<const uint4*>(whhL + (size_t)gr * 512 + q * 8);
    }

    float creg[8];
#pragma unroll
    for (int ir = 0; ir < 8; ir++) {
        int idx = tid + ir * 256;
        int row = idx >> 4, e = idx & 15;
        creg[ir] = c0[(size_t)(m0 + row) * 512 + e0 + e];
    }
    __syncthreads();

    for (int t = 0; t < 64; t++) {
        const float* hprev = (t == 0) ? h0 : (hs + (size_t)(t - 1) * 262144);
        const float* xg_t  = xg + (size_t)t * 1048576;
        float* hout        = hs + (size_t)t * 262144;

        float c[4][2][4];
#pragma unroll
        for (int i = 0; i < 4; i++)
#pragma unroll
            for (int j = 0; j < 2; j++)
#pragma unroll
                for (int q = 0; q < 4; q++) c[i][j][q] = 0.f;

        float4 avr[4];
        auto gloadA = [&](int ch) {
            int k0 = ch << 5;
#pragma unroll
            for (int i = 0; i < 4; i++) {
                int f = tid + i * 256, r = f >> 3, cq = f & 7;
                avr[i] = *reinterpret_cast<const float4*>(hprev + (size_t)(m0 + r) * 512 + k0 + cq * 4);
            }
        };
        auto sstoreA = [&](int buf) {
            const int ab = LP_A + buf * 5120;
#pragma unroll
            for (int i = 0; i < 4; i++) {
                int f = tid + i * 256, r = f >> 3, cq = f & 7;
                uint2 hi, lo;
                cvt_split4(avr[i], hi, lo);
                int idx = ab + r * 20 + cq * 2;
                *reinterpret_cast<uint2*>(&sm[idx])        = hi;
                *reinterpret_cast<uint2*>(&sm[2560 + idx]) = lo;
            }
        };

        gloadA(0);
        sstoreA(0);
        __syncthreads();

        for (int ch = 0; ch < 16; ch++) {
            const int buf = ch & 1;
            const bool more = (ch < 15);
            if (more) gloadA(ch + 1);
            const int ab = LP_A + buf * 5120;
#pragma unroll
            for (int s = 0; s < 2; s++) {
                uint32_t ah[4][4], al4[4][4];
#pragma unroll
                for (int mf = 0; mf < 4; mf++) {
                    uint32_t addr = sb4 + 4u * (uint32_t)(ab + (wm * 64 + mf * 16 + arow) * 20 + s * 8 + akoff);
                    ldsm_x4(ah[mf], addr);
                    ldsm_x4(al4[mf], addr + 2560u * 4u);
                }
                uint32_t bh0[2], bh1[2], bl0[2], bl1[2];
#pragma unroll
                for (int nf = 0; nf < 2; nf++) {
                    uint32_t baddr = sb4 + 4u * (uint32_t)((wn * 16 + nf * 8 + brow) * 260 + ch * 16 + s * 8 + bkoff);
                    ldsm_x2(bh0[nf], bh1[nf], baddr + LP_BH * 4u);
                    ldsm_x2(bl0[nf], bl1[nf], baddr + LP_BL * 4u);
                }
                // plane-major: hh (8), hl (8), lh (8) — dep distance 8
#pragma unroll
                for (int nf = 0; nf < 2; nf++)
#pragma unroll
                    for (int mf = 0; mf < 4; mf++) mma16816(c[mf][nf], ah[mf], bh0[nf], bh1[nf]);
#pragma unroll
                for (int nf = 0; nf < 2; nf++)
#pragma unroll
                    for (int mf = 0; mf < 4; mf++) mma16816(c[mf][nf], ah[mf], bl0[nf], bl1[nf]);
#pragma unroll
                for (int nf = 0; nf < 2; nf++)
#pragma unroll
                    for (int mf = 0; mf < 4; mf++) mma16816(c[mf][nf], al4[mf], bh0[nf], bh1[nf]);
            }
            if (more) {
                sstoreA(buf ^ 1);
                __syncthreads();
            }
        }

        __syncthreads();
        float* Gs = reinterpret_cast<float*>(&sm[LP_A]);
#pragma unroll
        for (int mf = 0; mf < 4; mf++) {
#pragma unroll
            for (int nf = 0; nf < 2; nf++) {
                int rr = wm * 64 + mf * 16 + gq;
                int cc = wn * 16 + nf * 8 + pl * 2;
                Gs[rr * 64 + cc]           = c[mf][nf][0];
                Gs[rr * 64 + cc + 1]       = c[mf][nf][1];
                Gs[(rr + 8) * 64 + cc]     = c[mf][nf][2];
                Gs[(rr + 8) * 64 + cc + 1] = c[mf][nf][3];
            }
        }
        __syncthreads();

#pragma unroll
        for (int ir = 0; ir < 8; ir++) {
            int idx = tid + ir * 256;
            int row = idx >> 4, e = idx & 15;
            int b = m0 + row, ni = e0 + e;
            const float* xr = xg_t + (size_t)b * 2048;
            float gi = Gs[row * 64 + e]      + bias2[ni]        + xr[ni];
            float gf = Gs[row * 64 + 16 + e] + bias2[ni + 512]  + xr[ni + 512];
            float gg = Gs[row * 64 + 32 + e] + bias2[ni + 1024] + xr[ni + 1024];
            float go = Gs[row * 64 + 48 + e] + bias2[ni + 1536] + xr[ni + 1536];
            float cc2 = sigmoidf_(gf) * creg[ir] + sigmoidf_(gi) * tanhf(gg);
            creg[ir] = cc2;
            hout[(size_t)b * 512 + ni] = sigmoidf_(go) * tanhf(cc2);
        }

        if (t < 63) grid_barrier128(tid);
    }
}

// ======================= SIMT gemm (Wc/Wt precompute only) ==================
__global__ void __launch_bounds__(256) gemm3(
    float* __restrict__ C, const float* __restrict__ A,
    const float* __restrict__ Bw, int M, int N, int K, int lda)
{
    __shared__ float As[2][16][128];
    __shared__ float Bs[2][16][64];

    const int tid = threadIdx.x;
    const int m0  = blockIdx.y * 128;
    const int n0  = blockIdx.x * 64;
    const int ty  = tid >> 4;
    const int tx  = tid & 15;
    const int r0 = tid >> 2;
    const int r1 = r0 + 64;
    const int c4 = (tid & 3) << 2;

    float4 pa0, pa1, pb;
    auto loadG = [&](int k0) {
        int gk = k0 + c4;
        pa0 = *reinterpret_cast<const float4*>(A + (size_t)(m0 + r0) * lda + gk);
        pa1 = *reinterpret_cast<const float4*>(A + (size_t)(m0 + r1) * lda + gk);
        pb = *reinterpret_cast<const float4*>(Bw + (size_t)(n0 + r0) * K + gk);
    };
    auto storeS = [&](int buf) {
        As[buf][c4 + 0][r0] = pa0.x; As[buf][c4 + 1][r0] = pa0.y;
        As[buf][c4 + 2][r0] = pa0.z; As[buf][c4 + 3][r0] = pa0.w;
        As[buf][c4 + 0][r1] = pa1.x; As[buf][c4 + 1][r1] = pa1.y;
        As[buf][c4 + 2][r1] = pa1.z; As[buf][c4 + 3][r1] = pa1.w;
        Bs[buf][c4 + 0][r0] = pb.x;  Bs[buf][c4 + 1][r0] = pb.y;
        Bs[buf][c4 + 2][r0] = pb.z;  Bs[buf][c4 + 3][r0] = pb.w;
    };

    unsigned long long acc[4][4];
#pragma unroll
    for (int i = 0; i < 4; i++)
#pragma unroll
        for (int j = 0; j < 4; j++) acc[i][j] = 0ull;

    loadG(0); storeS(0); __syncthreads();

    const int nt = K >> 4;
    for (int kt = 0; kt < nt; kt++) {
        const int cur = kt & 1;
        if (kt + 1 < nt) loadG((kt + 1) << 4);
#pragma unroll
        for (int kk = 0; kk < 16; ++kk) {
            const ulonglong2* ap = reinterpret_cast<const ulonglong2*>(&As[cur][kk][ty * 8]);
            ulonglong2 u0 = ap[0], u1 = ap[1];
            unsigned long long a2[4] = {u0.x, u0.y, u1.x, u1.y};
            float4 b = *reinterpret_cast<const float4*>(&Bs[cur][kk][tx * 4]);
            unsigned long long bd[4] = {pack2(b.x, b.x), pack2(b.y, b.y),
                                        pack2(b.z, b.z), pack2(b.w, b.w)};
#pragma unroll
            for (int i = 0; i < 4; i++)
#pragma unroll
                for (int j = 0; j < 4; j++) ffma2(acc[i][j], a2[i], bd[j]);
        }
        if (kt + 1 < nt) { storeS(cur ^ 1); __syncthreads(); }
    }

#pragma unroll
    for (int i = 0; i < 4; i++) {
        const int gm = m0 + ty * 8 + 2 * i;
#pragma unroll
        for (int j = 0; j < 4; j++) {
            float lo, hi;
            unpack2(acc[i][j], lo, hi);
            const int gn = n0 + tx * 4 + j;
            C[(size_t)gm * N + gn]       = lo;
            C[(size_t)(gm + 1) * N + gn] = hi;
        }
    }
}

__global__ void __launch_bounds__(256) init_h0c0(
    const float* __restrict__ chn, const float* __restrict__ thn,
    const float* __restrict__ ccn, const float* __restrict__ tcn,
    float* __restrict__ h0, float* __restrict__ c0)
{
    int idx = blockIdx.x * 256 + threadIdx.x;
    int bb = idx >> 9, e = idx & 511;
    h0[idx] = (e < 256) ? chn[bb * 256 + e] : thn[bb * 256 + e - 256];
    c0[idx] = (e < 256) ? ccn[bb * 256 + e] : tcn[bb * 256 + e - 256];
}

__global__ void __launch_bounds__(256) bias_add2048(
    const float* __restrict__ a, const float* __restrict__ b, float* __restrict__ o)
{
    int i = blockIdx.x * 256 + threadIdx.x;
    o[i] = a[i] + b[i];
}

__global__ void __launch_bounds__(256) transpose512(
    const float* __restrict__ in, float* __restrict__ out)
{
    __shared__ float t[32][33];
    int tx = threadIdx.x & 31, ty = threadIdx.x >> 5;
    int x0 = blockIdx.x * 32, y0 = blockIdx.y * 32;
#pragma unroll
    for (int iy = 0; iy < 4; iy++)
        t[ty + iy * 8][tx] = in[(size_t)(y0 + ty + iy * 8) * 512 + x0 + tx];
    __syncthreads();
#pragma unroll
    for (int iy = 0; iy < 4; iy++)
        out[(size_t)(x0 + ty + iy * 8) * 512 + y0 + tx] = t[tx][ty + iy * 8];
}

__global__ void __launch_bounds__(256) comb_bias(
    const float* __restrict__ out_w, const float* __restrict__ out_b,
    const float* __restrict__ cbo, const float* __restrict__ tbo,
    float* __restrict__ bp)
{
    int v = threadIdx.x;
    float s = out_b[v];
    const float* row = out_w + (size_t)v * 1024;
    for (int e = 0; e < 512; e++) s += row[e] * cbo[e] + row[512 + e] * tbo[e];
    bp[v] = s;
}

template <int S>
__global__ void __launch_bounds__(256) attn_kernel(
    const float* __restrict__ q, const float* __restrict__ k,
    const float* __restrict__ v, float* __restrict__ o)
{
    constexpr int TN = S / 16;
    __shared__ union SU {
        struct { float qs[16][64]; float ks[16][S]; } a;
        float vs[S][64];
    } u;
    __shared__ float sc[64][S];

    const int b = blockIdx.x;
    const int tid = threadIdx.x;
    const int ty = tid >> 4, tx = tid & 15;

    float acc[4][TN];
#pragma unroll
    for (int r = 0; r < 4; r++)
#pragma unroll
        for (int j = 0; j < TN; j++) acc[r][j] = 0.f;

    for (int k0 = 0; k0 < Ed; k0 += 16) {
        {
            int r = tid >> 2, c4 = (tid & 3) << 2;
            float4 val = *reinterpret_cast<const float4*>(q + ((size_t)r * Bsz + b) * Ed + k0 + c4);
            u.a.qs[c4+0][r] = val.x; u.a.qs[c4+1][r] = val.y;
            u.a.qs[c4+2][r] = val.z; u.a.qs[c4+3][r] = val.w;
        }
        if (tid < S * 4) {
            int r = tid >> 2, c4 = (tid & 3) << 2;
            float4 val = *reinterpret_cast<const float4*>(k + ((size_t)b * S + r) * Ed + k0 + c4);
            u.a.ks[c4+0][r] = val.x; u.a.ks[c4+1][r] = val.y;
            u.a.ks[c4+2][r] = val.z; u.a.ks[c4+3][r] = val.w;
        }
        __syncthreads();
#pragma unroll
        for (int kk = 0; kk < 16; kk++) {
            float av[4], bv[TN];
#pragma unroll
            for (int r = 0; r < 4; r++) av[r] = u.a.qs[kk][ty * 4 + r];
#pragma unroll
            for (int j = 0; j < TN; j++) bv[j] = u.a.ks[kk][tx * TN + j];
#pragma unroll
            for (int r = 0; r < 4; r++)
#pragma unroll
                for (int j = 0; j < TN; j++) acc[r][j] += av[r] * bv[j];
        }
        __syncthreads();
    }
#pragma unroll
    for (int r = 0; r < 4; r++)
#pragma unroll
        for (int j = 0; j < TN; j++) sc[ty * 4 + r][tx * TN + j] = acc[r][j];
    __syncthreads();

    if (tid < 64) {
        float mx = -3.4e38f;
        for (int s = 0; s < S; s++) mx = fmaxf(mx, sc[tid][s]);
        float sum = 0.f;
        for (int s = 0; s < S; s++) { float e = expf(sc[tid][s] - mx); sc[tid][s] = e; sum += e; }
        float inv = 1.f / sum;
        for (int s = 0; s < S; s++) sc[tid][s] *= inv;
    }
    __syncthreads();

    for (int n0 = 0; n0 < Ed; n0 += 64) {
#pragma unroll
        for (int it = 0; it < (S * 16) / 256; ++it) {
            int f = tid + it * 256;
            int r = f >> 4, c4 = (f & 15) << 2;
            *reinterpret_cast<float4*>(&u.vs[r][c4]) =
                *reinterpret_cast<const float4*>(v + ((size_t)b * S + r) * Ed + n0 + c4);
        }
        __syncthreads();
        float oa[4][4] = {};
        for (int sk = 0; sk < S; sk++) {
            float p[4];
#pragma unroll
            for (int r = 0; r < 4; r++) p[r] = sc[ty * 4 + r][sk];
            float4 vv = *reinterpret_cast<const float4*>(&u.vs[sk][tx * 4]);
            float vf[4] = {vv.x, vv.y, vv.z, vv.w};
#pragma unroll
            for (int r = 0; r < 4; r++)
#pragma unroll
                for (int j = 0; j < 4; j++) oa[r][j] += p[r] * vf[j];
        }
#pragma unroll
        for (int r = 0; r < 4; r++) {
            size_t base = ((size_t)(ty * 4 + r) * Bsz + b) * Ed + n0 + tx * 4;
            *reinterpret_cast<float4*>(&o[base]) = make_float4(oa[r][0], oa[r][1], oa[r][2], oa[r][3]);
        }
        __syncthreads();
    }
}

__global__ void __launch_bounds__(256) entmax_kernel(
    const float* __restrict__ logits, float* __restrict__ out)
{
    __shared__ float s[256], cs1[256], cs2[256], taus[256], red[256];
    const int row = blockIdx.x;
    const int tid = threadIdx.x;

    float z = logits[(size_t)row * 256 + tid] * 0.5f;
    red[tid] = z;
    __syncthreads();
    for (int off = 128; off > 0; off >>= 1) {
        if (tid < off) red[tid] = fmaxf(red[tid], red[tid + off]);
        __syncthreads();
    }
    z -= red[0];
    __syncthreads();

    s[tid] = -z;
    __syncthreads();
    for (int kk = 2; kk <= 256; kk <<= 1) {
        for (int j = kk >> 1; j > 0; j >>= 1) {
            int ixj = tid ^ j;
            if (ixj > tid) {
                float a = s[tid], b2 = s[ixj];
                bool swp = ((tid & kk) == 0) ? (a > b2) : (a < b2);
                if (swp) { s[tid] = b2; s[ixj] = a; }
            }
            __syncthreads();
        }
    }
    float zs = -s[tid];

    cs1[tid] = zs; cs2[tid] = zs * zs;
    __syncthreads();
    for (int off = 1; off < 256; off <<= 1) {
        float a1 = 0.f, a2 = 0.f;
        if (tid >= off) { a1 = cs1[tid - off]; a2 = cs2[tid - off]; }
        __syncthreads();
        if (tid >= off) { cs1[tid] += a1; cs2[tid] += a2; }
        __syncthreads();
    }

    float rho   = (float)(tid + 1);
    float mean  = cs1[tid] / rho;
    float msq   = cs2[tid] / rho;
    float ssv   = rho * (msq - mean * mean);
    float delta = (1.0f - ssv) / rho;
    float sq    = (delta > 0.f) ? sqrtf(delta) : 0.f;
    float tau   = mean - sq;
    taus[tid] = tau;
    red[tid]  = (tau <= zs) ? 1.f : 0.f;
    __syncthreads();
    for (int off = 128; off > 0; off >>= 1) {
        if (tid < off) red[tid] += red[tid + off];
        __syncthreads();
    }
    int kcnt = (int)red[0];
    float tau_star = taus[kcnt - 1];
    float y = fmaxf(z - tau_star, 0.f);
    int t = row >> 9, b = row & 511;
    out[((size_t)b * Tc + t) * Vd + tid] = y * y;
}

extern "C" void kernel_launch(void* const* d_in, const int* in_sizes, int n_in,
                              void* d_out, int out_size)
{
    const float* char_enc = (const float*)d_in[0];
    const float* char_hn0 = (const float*)d_in[1];
    const float* char_cn0 = (const float*)d_in[2];
    const float* tag_enc  = (const float*)d_in[3];
    const float* tag_hn0  = (const float*)d_in[4];
    const float* tag_cn0  = (const float*)d_in[5];
    const float* tos      = (const float*)d_in[6];
    const float* w_ih     = (const float*)d_in[7];
    const float* w_hh     = (const float*)d_in[8];
    const float* b_ih     = (const float*)d_in[9];
    const float* b_hh     = (const float*)d_in[10];
    const float* cwq = (const float*)d_in[11];
    const float* cwk = (const float*)d_in[12];
    const float* cwv = (const float*)d_in[13];
    const float* cbq = (const float*)d_in[14];
    const float* cbk = (const float*)d_in[15];
    const float* cbv = (const float*)d_in[16];
    const float* cwo = (const float*)d_in[17];
    const float* cbo = (const float*)d_in[18];
    const float* twq = (const float*)d_in[19];
    const float* twk = (const float*)d_in[20];
    const float* twv = (const float*)d_in[21];
    const float* tbq = (const float*)d_in[22];
    const float* tbk = (const float*)d_in[23];
    const float* tbv = (const float*)d_in[24];
    const float* two_ = (const float*)d_in[25];
    const float* tbo = (const float*)d_in[26];
    const float* out_w = (const float*)d_in[27];
    const float* out_b = (const float*)d_in[28];
    float* out = (float*)d_out;

    float *xg, *h0, *c0, *hs, *qc, *kc, *vc, *qt, *kt, *vt, *oc, *ot, *lg;
    float *bias2, *Wc, *Wt, *cwoT, *twoT, *bcomb;
    cudaGetSymbolAddress((void**)&xg,    g_xgates);
    cudaGetSymbolAddress((void**)&h0,    g_h0);
    cudaGetSymbolAddress((void**)&c0,    g_c);
    cudaGetSymbolAddress((void**)&hs,    g_hs);
    cudaGetSymbolAddress((void**)&qc,    g_qc);
    cudaGetSymbolAddress((void**)&kc,    g_kc);
    cudaGetSymbolAddress((void**)&vc,    g_vc);
    cudaGetSymbolAddress((void**)&qt,    g_qt);
    cudaGetSymbolAddress((void**)&kt,    g_kt);
    cudaGetSymbolAddress((void**)&vt,    g_vt);
    cudaGetSymbolAddress((void**)&oc,    g_oc);
    cudaGetSymbolAddress((void**)&ot,    g_ot);
    cudaGetSymbolAddress((void**)&lg,    g_lg);
    cudaGetSymbolAddress((void**)&bias2, g_bias2);
    cudaGetSymbolAddress((void**)&Wc,    g_Wc);
    cudaGetSymbolAddress((void**)&Wt,    g_Wt);
    cudaGetSymbolAddress((void**)&cwoT,  g_cwoT);
    cudaGetSymbolAddress((void**)&twoT,  g_twoT);
    cudaGetSymbolAddress((void**)&bcomb, g_bcomb);

    __nv_bfloat16 *whhH, *whhL, *wihH, *wihL, *cwkH, *cwkL, *cwvH, *cwvL, *cwqH, *cwqL;
    __nv_bfloat16 *twkH, *twkL, *twvH, *twvL, *twqH, *twqL, *WcH, *WcL, *WtH, *WtL;
    cudaGetSymbolAddress((void**)&whhH, g_whhH); cudaGetSymbolAddress((void**)&whhL, g_whhL);
    cudaGetSymbolAddress((void**)&wihH, g_wihH); cudaGetSymbolAddress((void**)&wihL, g_wihL);
    cudaGetSymbolAddress((void**)&cwkH, g_cwkH); cudaGetSymbolAddress((void**)&cwkL, g_cwkL);
    cudaGetSymbolAddress((void**)&cwvH, g_cwvH); cudaGetSymbolAddress((void**)&cwvL, g_cwvL);
    cudaGetSymbolAddress((void**)&cwqH, g_cwqH); cudaGetSymbolAddress((void**)&cwqL, g_cwqL);
    cudaGetSymbolAddress((void**)&twkH, g_twkH); cudaGetSymbolAddress((void**)&twkL, g_twkL);
    cudaGetSymbolAddress((void**)&twvH, g_twvH); cudaGetSymbolAddress((void**)&twvL, g_twvL);
    cudaGetSymbolAddress((void**)&twqH, g_twqH); cudaGetSymbolAddress((void**)&twqL, g_twqL);
    cudaGetSymbolAddress((void**)&WcH,  g_WcH);  cudaGetSymbolAddress((void**)&WcL,  g_WcL);
    cudaGetSymbolAddress((void**)&WtH,  g_WtH);  cudaGetSymbolAddress((void**)&WtL,  g_WtL);

    const float qscale = 1.0f / sqrtf(512.0f);
    const int smem_g = 30720 * 4;   // 122880

    cudaFuncSetAttribute(mma_gemm2<0>, cudaFuncAttributeMaxDynamicSharedMemorySize, smem_g);
    cudaFuncSetAttribute(mma_gemm2<1>, cudaFuncAttributeMaxDynamicSharedMemorySize, smem_g);
    cudaFuncSetAttribute(mma_gemm2<2>, cudaFuncAttributeMaxDynamicSharedMemorySize, smem_g);
    cudaFuncSetAttribute(lstm_persist, cudaFuncAttributeMaxDynamicSharedMemorySize, LP_SMEM_BYTES);

    // 1-3: conversions needed by the first GEMMs
    conv_split_k<<<2048, 256>>>(w_ih, wihH, wihL, 524288);
    conv_split_k<<<1024, 256>>>(cwk, cwkH, cwkL, 262144);
    conv_split_k<<<1024, 256>>>(cwv, cwvH, cwvL, 262144);

    // 4-6: big tensor GEMMs early (ncu capture targets)
    mma_gemm2<1><<<dim3(16, 128), 512, smem_g>>>(xg, tos, nullptr, wihH, wihL, nullptr, nullptr,
                                                 nullptr, 32768, 2048, 256, 256, 256, 1.0f);
    mma_gemm2<0><<<dim3(4, 128), 512, smem_g>>>(kc, char_enc, nullptr, cwkH, cwkL, nullptr, nullptr,
                                                cbk, 32768, 512, 512, 512, 512, 1.0f);
    mma_gemm2<0><<<dim3(4, 128), 512, smem_g>>>(vc, char_enc, nullptr, cwvH, cwvL, nullptr, nullptr,
                                                cbv, 32768, 512, 512, 512, 512, 1.0f);

    // small precomputes
    init_h0c0<<<1024, 256>>>(char_hn0, tag_hn0, char_cn0, tag_cn0, h0, c0);
    bias_add2048<<<8, 256>>>(b_ih, b_hh, bias2);
    transpose512<<<dim3(16, 16), 256>>>(cwo, cwoT);
    transpose512<<<dim3(16, 16), 256>>>(two_, twoT);
    comb_bias<<<1, 256>>>(out_w, out_b, cbo, tbo, bcomb);

    // folded head weights (fp32), then convert
    gemm3<<<dim3(8, 2), 256>>>(Wc, out_w,       cwoT, 256, 512, 512, 1024);
    gemm3<<<dim3(8, 2), 256>>>(Wt, out_w + 512, twoT, 256, 512, 512, 1024);

    // remaining weight conversions
    conv_split_k<<<4096, 256>>>(w_hh, whhH, whhL, 1048576);
    conv_split_k<<<1024, 256>>>(cwq, cwqH, cwqL, 262144);
    conv_split_k<<<1024, 256>>>(twk, twkH, twkL, 262144);
    conv_split_k<<<1024, 256>>>(twv, twvH, twvL, 262144);
    conv_split_k<<<1024, 256>>>(twq, twqH, twqL, 262144);
    conv_split_k<<<512, 256>>>(Wc, WcH, WcL, 131072);
    conv_split_k<<<512, 256>>>(Wt, WtH, WtL, 131072);

    // tag-side projections
    mma_gemm2<0><<<dim3(4, 32), 512, smem_g>>>(kt, tag_enc, nullptr, twkH, twkL, nullptr, nullptr,
                                               tbk, 8192, 512, 512, 512, 512, 1.0f);
    mma_gemm2<0><<<dim3(4, 32), 512, smem_g>>>(vt, tag_enc, nullptr, twvH, twvL, nullptr, nullptr,
                                               tbv, 8192, 512, 512, 512, 512, 1.0f);

    // persistent LSTM (one launch, 128 CTAs, internal 64-step loop)
    lstm_persist<<<dim3(32, 4), 256, LP_SMEM_BYTES>>>(h0, whhH, whhL, xg, bias2, c0, hs);

    // q projections
    mma_gemm2<0><<<dim3(4, 128), 512, smem_g>>>(qc, hs, nullptr, cwqH, cwqL, nullptr, nullptr,
                                                cbq, 32768, 512, 512, 512, 512, qscale);
    mma_gemm2<0><<<dim3(4, 128), 512, smem_g>>>(qt, hs, nullptr, twqH, twqL, nullptr, nullptr,
                                                tbq, 32768, 512, 512, 512, 512, qscale);

    // attention
    attn_kernel<64><<<512, 256>>>(qc, kc, vc, oc);
    attn_kernel<16><<<512, 256>>>(qt, kt, vt, ot);

    // logits = oc @ Wc^T + ot @ Wt^T + bcomb (concat GEMM, K=1024)
    mma_gemm2<2><<<dim3(2, 128), 512, smem_g>>>(lg, oc, ot, WcH, WcL, WtH, WtL,
                                                bcomb, 32768, 256, 1024, 512, 512, 1.0f);

    // entmax + transpose to (B,T,V)
    entmax_kernel<<<32768, 256>>>(lg, out);
}

// round 14
// speedup vs baseline: 1.0138x; 1.0138x over previous
#include <cuda_runtime.h>
#include <cuda_bf16.h>
#include <math.h>
#include <stdint.h>

#define Bsz 512
#define Tc  64
#define Ed  512
#define Vd  256

__device__ float g_xgates[67108864];   // (T,B,4E)
__device__ float g_h0    [262144];
__device__ float g_c     [262144];
__device__ float g_hs    [16777216];   // (T,B,E)
__device__ float g_qc    [16777216];
__device__ float g_kc    [16777216];
__device__ float g_vc    [16777216];
__device__ float g_qt    [16777216];
__device__ float g_kt    [4194304];
__device__ float g_vt    [4194304];
__device__ float g_oc    [16777216];
__device__ float g_ot    [16777216];
__device__ float g_lg    [8388608];    // (T,B,V)
__device__ float g_bias2 [2048];
__device__ float g_Wc    [131072];     // (V,E)
__device__ float g_Wt    [131072];
__device__ float g_cwoT  [262144];
__device__ float g_twoT  [262144];
__device__ float g_bcomb [256];

__device__ __nv_bfloat16 g_whhH[1048576], g_whhL[1048576];
__device__ __nv_bfloat16 g_wihH[524288],  g_wihL[524288];
__device__ __nv_bfloat16 g_cwkH[262144],  g_cwkL[262144];
__device__ __nv_bfloat16 g_cwvH[262144],  g_cwvL[262144];
__device__ __nv_bfloat16 g_cwqH[262144],  g_cwqL[262144];
__device__ __nv_bfloat16 g_twkH[262144],  g_twkL[262144];
__device__ __nv_bfloat16 g_twvH[262144],  g_twvL[262144];
__device__ __nv_bfloat16 g_twqH[262144],  g_twqL[262144];
__device__ __nv_bfloat16 g_WcH[131072],   g_WcL[131072];
__device__ __nv_bfloat16 g_WtH[131072],   g_WtL[131072];

__device__ unsigned g_cnt;
__device__ volatile unsigned g_epoch;

// ======================= helpers ===========================================
__device__ __forceinline__ void ffma2(unsigned long long& d, unsigned long long a,
                                      unsigned long long b) {
    asm("fma.rn.f32x2 %0, %1, %2, %0;" : "+l"(d) : "l"(a), "l"(b));
}
__device__ __forceinline__ unsigned long long pack2(float x, float y) {
    unsigned long long r;
    asm("mov.b64 %0, {%1, %2};" : "=l"(r) : "r"(__float_as_uint(x)), "r"(__float_as_uint(y)));
    return r;
}
__device__ __forceinline__ void unpack2(unsigned long long d, float& lo, float& hi) {
    unsigned int l, h;
    asm("mov.b64 {%0, %1}, %2;" : "=r"(l), "=r"(h) : "l"(d));
    lo = __uint_as_float(l); hi = __uint_as_float(h);
}
__device__ __forceinline__ float sigmoidf_(float x) { return 1.0f / (1.0f + expf(-x)); }

__device__ __forceinline__ void mma16816(float* c, const uint32_t* a, uint32_t b0, uint32_t b1) {
    asm volatile(
        "mma.sync.aligned.m16n8k16.row.col.f32.bf16.bf16.f32 "
        "{%0,%1,%2,%3}, {%4,%5,%6,%7}, {%8,%9}, {%0,%1,%2,%3};"
        : "+f"(c[0]), "+f"(c[1]), "+f"(c[2]), "+f"(c[3])
        : "r"(a[0]), "r"(a[1]), "r"(a[2]), "r"(a[3]), "r"(b0), "r"(b1));
}
__device__ __forceinline__ void ldsm_x4(uint32_t* r, uint32_t addr) {
    asm volatile("ldmatrix.sync.aligned.m8n8.x4.shared.b16 {%0,%1,%2,%3}, [%4];"
                 : "=r"(r[0]), "=r"(r[1]), "=r"(r[2]), "=r"(r[3]) : "r"(addr));
}
__device__ __forceinline__ void ldsm_x2(uint32_t& r0, uint32_t& r1, uint32_t addr) {
    asm volatile("ldmatrix.sync.aligned.m8n8.x2.shared.b16 {%0,%1}, [%2];"
                 : "=r"(r0), "=r"(r1) : "r"(addr));
}
__device__ __forceinline__ void cvt_split4(float4 v, uint2& hi, uint2& lo) {
    __nv_bfloat16 h0 = __float2bfloat16(v.x), h1 = __float2bfloat16(v.y);
    __nv_bfloat16 h2 = __float2bfloat16(v.z), h3 = __float2bfloat16(v.w);
    __nv_bfloat16 l0 = __float2bfloat16(v.x - __bfloat162float(h0));
    __nv_bfloat16 l1 = __float2bfloat16(v.y - __bfloat162float(h1));
    __nv_bfloat16 l2 = __float2bfloat16(v.z - __bfloat162float(h2));
    __nv_bfloat16 l3 = __float2bfloat16(v.w - __bfloat162float(h3));
    hi.x = (uint32_t)__bfloat16_as_ushort(h0) | ((uint32_t)__bfloat16_as_ushort(h1) << 16);
    hi.y = (uint32_t)__bfloat16_as_ushort(h2) | ((uint32_t)__bfloat16_as_ushort(h3) << 16);
    lo.x = (uint32_t)__bfloat16_as_ushort(l0) | ((uint32_t)__bfloat16_as_ushort(l1) << 16);
    lo.y = (uint32_t)__bfloat16_as_ushort(l2) | ((uint32_t)__bfloat16_as_ushort(l3) << 16);
}

__global__ void __launch_bounds__(256) conv_split_k(
    const float* __restrict__ s, __nv_bfloat16* __restrict__ h,
    __nv_bfloat16* __restrict__ l, int n)
{
    int i = blockIdx.x * 256 + threadIdx.x;
    if (i < n) {
        float v = s[i];
        __nv_bfloat16 hv = __float2bfloat16(v);
        h[i] = hv;
        l[i] = __float2bfloat16(v - __bfloat162float(hv));
    }
}

// ---------------------------------------------------------------------------
// mma.sync GEMM (NT), CTA 256x128, 512 threads / 16 warps (4m x 4n),
// warp tile 64x32, K-chunk 32. Plane-major MMA order (dep distance 8).
// ---------------------------------------------------------------------------
template <int MODE>
__global__ void __launch_bounds__(512) mma_gemm2(
    float* __restrict__ C, const float* __restrict__ A, const float* __restrict__ A2,
    const __nv_bfloat16* __restrict__ BH, const __nv_bfloat16* __restrict__ BL,
    const __nv_bfloat16* __restrict__ BH2, const __nv_bfloat16* __restrict__ BL2,
    const float* __restrict__ bias, int M, int N, int K, int lda, int ldb, float alpha)
{
    extern __shared__ uint32_t sm[];

    const int tid  = threadIdx.x;
    const int lane = tid & 31, wid = tid >> 5;
    const int wm = wid >> 2, wn = wid & 3;       // 4m x 4n
    const int m0 = blockIdx.y * 256, n0 = blockIdx.x * 128;
    const int gq = lane >> 2, pl = lane & 3;

    const uint32_t sb4 = (uint32_t)__cvta_generic_to_shared(sm);
    const int arow  = (lane & 7) + ((lane >> 3) & 1) * 8;
    const int akoff = (lane >> 4) * 4;
    const int brow  = lane & 7;
    const int bkoff = ((lane >> 3) & 1) * 4;

    float c[4][4][4];
#pragma unroll
    for (int i = 0; i < 4; i++)
#pragma unroll
        for (int j = 0; j < 4; j++)
#pragma unroll
            for (int q = 0; q < 4; q++) c[i][j][q] = 0.f;

    float4 avr[4];
    uint4 bhr, blr;

    auto gload = [&](int ch) {
        const float* Ae = A;
        const __nv_bfloat16 *bh = BH, *bl = BL;
        int k0 = ch << 5;
        if (MODE == 2 && k0 >= 512) { Ae = A2; bh = BH2; bl = BL2; k0 -= 512; }
#pragma unroll
        for (int i = 0; i < 4; i++) {
            int f = tid + i * 512, r = f >> 3, cq = f & 7;
            if constexpr (MODE == 1) {
                int gm = m0 + r, tt = gm >> 9, bb = gm & 511;
                avr[i] = tt ? *reinterpret_cast<const float4*>(Ae + (size_t)bb * 16384 + tt * 256 + k0 + cq * 4)
                            : make_float4(0.f, 0.f, 0.f, 0.f);
            } else {
                avr[i] = *reinterpret_cast<const float4*>(Ae + (size_t)(m0 + r) * lda + k0 + cq * 4);
            }
        }
        {
            int r = tid >> 2, cq = tid & 3;
            bhr = *reinterpret_cast<const uint4*>(bh + (size_t)(n0 + r) * ldb + k0 + cq * 8);
            blr = *reinterpret_cast<const uint4*>(bl + (size_t)(n0 + r) * ldb + k0 + cq * 8);
        }
    };
    auto sstore = [&](int buf) {
        const int ab = buf * 5120;
#pragma unroll
        for (int i = 0; i < 4; i++) {
            int f = tid + i * 512, r = f >> 3, cq = f & 7;
            uint2 hi, lo;
            cvt_split4(avr[i], hi, lo);
            int idx = ab + r * 20 + cq * 2;
            *reinterpret_cast<uint2*>(&sm[idx])         = hi;
            *reinterpret_cast<uint2*>(&sm[10240 + idx]) = lo;
        }
        {
            int r = tid >> 2, cq = tid & 3;
            int idx = buf * 2560 + r * 20 + cq * 4;
            *reinterpret_cast<uint4*>(&sm[20480 + idx]) = bhr;
            *reinterpret_cast<uint4*>(&sm[25600 + idx]) = blr;
        }
    };

    const int nch = K >> 5;
    gload(0);
    sstore(0);
    __syncthreads();

    for (int ch = 0; ch < nch; ch++) {
        const int buf = ch & 1;
        const bool more = (ch + 1 < nch);
        if (more) gload(ch + 1);
        const int ab = buf * 5120;
        const int bb = buf * 2560;
#pragma unroll
        for (int s = 0; s < 2; s++) {
            uint32_t bh0[4], bh1[4], bl0[4], bl1[4];
#pragma unroll
            for (int nf = 0; nf < 4; nf++) {
                uint32_t baddr = sb4 + 4u * (uint32_t)(20480 + bb + (wn * 32 + nf * 8 + brow) * 20 + s * 8 + bkoff);
                ldsm_x2(bh0[nf], bh1[nf], baddr);
                ldsm_x2(bl0[nf], bl1[nf], baddr + 5120u * 4u);
            }
            // process mf in pairs, plane-major (dep distance 8 between reuses of c)
#pragma unroll
            for (int mp = 0; mp < 2; mp++) {
                const int mf0 = mp * 2, mf1 = mp * 2 + 1;
                uint32_t a0[4], a1[4];
                uint32_t aaddr0 = sb4 + 4u * (uint32_t)(ab + (wm * 64 + mf0 * 16 + arow) * 20 + s * 8 + akoff);
                uint32_t aaddr1 = sb4 + 4u * (uint32_t)(ab + (wm * 64 + mf1 * 16 + arow) * 20 + s * 8 + akoff);
                ldsm_x4(a0, aaddr0);
                ldsm_x4(a1, aaddr1);
#pragma unroll
                for (int nf = 0; nf < 4; nf++) mma16816(c[mf0][nf], a0, bh0[nf], bh1[nf]);
#pragma unroll
                for (int nf = 0; nf < 4; nf++) mma16816(c[mf1][nf], a1, bh0[nf], bh1[nf]);
#pragma unroll
                for (int nf = 0; nf < 4; nf++) mma16816(c[mf0][nf], a0, bl0[nf], bl1[nf]);
#pragma unroll
                for (int nf = 0; nf < 4; nf++) mma16816(c[mf1][nf], a1, bl0[nf], bl1[nf]);
                ldsm_x4(a0, aaddr0 + 10240u * 4u);
                ldsm_x4(a1, aaddr1 + 10240u * 4u);
#pragma unroll
                for (int nf = 0; nf < 4; nf++) mma16816(c[mf0][nf], a0, bh0[nf], bh1[nf]);
#pragma unroll
                for (int nf = 0; nf < 4; nf++) mma16816(c[mf1][nf], a1, bh0[nf], bh1[nf]);
            }
        }
        if (more) {
            sstore(buf ^ 1);
            __syncthreads();
        }
    }

#pragma unroll
    for (int mf = 0; mf < 4; mf++) {
#pragma unroll
        for (int nf = 0; nf < 4; nf++) {
            int r  = m0 + wm * 64 + mf * 16 + gq;
            int cc = n0 + wn * 32 + nf * 8 + pl * 2;
            float b0 = 0.f, b1 = 0.f;
            if (bias) { b0 = bias[cc]; b1 = bias[cc + 1]; }
            *reinterpret_cast<float2*>(&C[(size_t)r * N + cc]) =
                make_float2(alpha * (c[mf][nf][0] + b0), alpha * (c[mf][nf][1] + b1));
            *reinterpret_cast<float2*>(&C[(size_t)(r + 8) * N + cc]) =
                make_float2(alpha * (c[mf][nf][2] + b0), alpha * (c[mf][nf][3] + b1));
        }
    }
}

// ---------------------------------------------------------------------------
// Persistent LSTM (reverted to R12's proven inner loop)
// ---------------------------------------------------------------------------
#define LP_BH 0
#define LP_BL 16640
#define LP_A  33280
#define LP_SMEM_BYTES (43520 * 4)

__device__ __forceinline__ void grid_barrier128(int tid) {
    __threadfence();
    __syncthreads();
    if (tid == 0) {
        unsigned e = g_epoch;
        if (atomicAdd(&g_cnt, 1u) == 127u) {
            g_cnt = 0;
            __threadfence();
            g_epoch = e + 1;
        } else {
            while (g_epoch == e) { }
        }
    }
    __syncthreads();
}

__global__ void __launch_bounds__(256) lstm_persist(
    const float* __restrict__ h0,
    const __nv_bfloat16* __restrict__ whhH, const __nv_bfloat16* __restrict__ whhL,
    const float* __restrict__ xg, const float* __restrict__ bias2,
    const float* __restrict__ c0, float* __restrict__ hs)
{
    extern __shared__ uint32_t sm[];
    const int tid  = threadIdx.x;
    const int lane = tid & 31, wid = tid >> 5;
    const int wm = wid >> 2, wn = wid & 3;
    const int e0 = blockIdx.x * 16;
    const int m0 = blockIdx.y * 128;
    const int gq = lane >> 2, pl = lane & 3;

    const uint32_t sb4 = (uint32_t)__cvta_generic_to_shared(sm);
    const int arow  = (lane & 7) + ((lane >> 3) & 1) * 8;
    const int akoff = (lane >> 4) * 4;
    const int brow  = lane & 7;
    const int bkoff = ((lane >> 3) & 1) * 4;

#pragma unroll
    for (int i = 0; i < 16; i++) {
        int f = tid + i * 256;
        int r = f >> 6, q = f & 63;
        int gr = (r >> 4) * 512 + e0 + (r & 15);
        *reinterpret_cast<uint4*>(&sm[LP_BH + r * 260 + q * 4]) =
            *reinterpret_cast<const uint4*>(whhH + (size_t)gr * 512 + q * 8);
        *reinterpret_cast<uint4*>(&sm[LP_BL + r * 260 + q * 4]) =
            *reinterpret_cast<const uint4*>(whhL + (size_t)gr * 512 + q * 8);
    }

    float creg[8];
#pragma unroll
    for (int ir = 0; ir < 8; ir++) {
        int idx = tid + ir * 256;
        int row = idx >> 4, e = idx & 15;
        creg[ir] = c0[(size_t)(m0 + row) * 512 + e0 + e];
    }
    __syncthreads();

    for (int t = 0; t < 64; t++) {
        const float* hprev = (t == 0) ? h0 : (hs + (size_t)(t - 1) * 262144);
        const float* xg_t  = xg + (size_t)t * 1048576;
        float* hout        = hs + (size_t)t * 262144;

        float c[4][2][4];
#pragma unroll
        for (int i = 0; i < 4; i++)
#pragma unroll
            for (int j = 0; j < 2; j++)
#pragma unroll
                for (int q = 0; q < 4; q++) c[i][j][q] = 0.f;

        float4 avr[4];
        auto gloadA = [&](int ch) {
            int k0 = ch << 5;
#pragma unroll
            for (int i = 0; i < 4; i++) {
                int f = tid + i * 256, r = f >> 3, cq = f & 7;
                avr[i] = *reinterpret_cast<const float4*>(hprev + (size_t)(m0 + r) * 512 + k0 + cq * 4);
            }
        };
        auto sstoreA = [&](int buf) {
            const int ab = LP_A + buf * 5120;
#pragma unroll
            for (int i = 0; i < 4; i++) {
                int f = tid + i * 256, r = f >> 3, cq = f & 7;
                uint2 hi, lo;
                cvt_split4(avr[i], hi, lo);
                int idx = ab + r * 20 + cq * 2;
                *reinterpret_cast<uint2*>(&sm[idx])        = hi;
                *reinterpret_cast<uint2*>(&sm[2560 + idx]) = lo;
            }
        };

        gloadA(0);
        sstoreA(0);
        __syncthreads();

        for (int ch = 0; ch < 16; ch++) {
            const int buf = ch & 1;
            const bool more = (ch < 15);
            if (more) gloadA(ch + 1);
            const int ab = LP_A + buf * 5120;
#pragma unroll
            for (int s = 0; s < 2; s++) {
                uint32_t ah[4][4], al4[4][4];
#pragma unroll
                for (int mf = 0; mf < 4; mf++) {
                    uint32_t addr = sb4 + 4u * (uint32_t)(ab + (wm * 64 + mf * 16 + arow) * 20 + s * 8 + akoff);
                    ldsm_x4(ah[mf], addr);
                    ldsm_x4(al4[mf], addr + 2560u * 4u);
                }
#pragma unroll
                for (int nf = 0; nf < 2; nf++) {
                    uint32_t baddr = sb4 + 4u * (uint32_t)((wn * 16 + nf * 8 + brow) * 260 + ch * 16 + s * 8 + bkoff);
                    uint32_t bh0, bh1, bl0, bl1;
                    ldsm_x2(bh0, bh1, baddr + LP_BH * 4u);
                    ldsm_x2(bl0, bl1, baddr + LP_BL * 4u);
#pragma unroll
                    for (int mf = 0; mf < 4; mf++) {
                        mma16816(c[mf][nf], ah[mf], bh0, bh1);
                        mma16816(c[mf][nf], ah[mf], bl0, bl1);
                        mma16816(c[mf][nf], al4[mf], bh0, bh1);
                    }
                }
            }
            if (more) {
                sstoreA(buf ^ 1);
                __syncthreads();
            }
        }

        __syncthreads();
        float* Gs = reinterpret_cast<float*>(&sm[LP_A]);
#pragma unroll
        for (int mf = 0; mf < 4; mf++) {
#pragma unroll
            for (int nf = 0; nf < 2; nf++) {
                int rr = wm * 64 + mf * 16 + gq;
                int cc = wn * 16 + nf * 8 + pl * 2;
                Gs[rr * 64 + cc]           = c[mf][nf][0];
                Gs[rr * 64 + cc + 1]       = c[mf][nf][1];
                Gs[(rr + 8) * 64 + cc]     = c[mf][nf][2];
                Gs[(rr + 8) * 64 + cc + 1] = c[mf][nf][3];
            }
        }
        __syncthreads();

#pragma unroll
        for (int ir = 0; ir < 8; ir++) {
            int idx = tid + ir * 256;
            int row = idx >> 4, e = idx & 15;
            int b = m0 + row, ni = e0 + e;
            const float* xr = xg_t + (size_t)b * 2048;
            float gi = Gs[row * 64 + e]      + bias2[ni]        + xr[ni];
            float gf = Gs[row * 64 + 16 + e] + bias2[ni + 512]  + xr[ni + 512];
            float gg = Gs[row * 64 + 32 + e] + bias2[ni + 1024] + xr[ni + 1024];
            float go = Gs[row * 64 + 48 + e] + bias2[ni + 1536] + xr[ni + 1536];
            float cc2 = sigmoidf_(gf) * creg[ir] + sigmoidf_(gi) * tanhf(gg);
            creg[ir] = cc2;
            hout[(size_t)b * 512 + ni] = sigmoidf_(go) * tanhf(cc2);
        }

        if (t < 63) grid_barrier128(tid);
    }
}

// ======================= SIMT gemm (Wc/Wt precompute only) ==================
__global__ void __launch_bounds__(256) gemm3(
    float* __restrict__ C, const float* __restrict__ A,
    const float* __restrict__ Bw, int M, int N, int K, int lda)
{
    __shared__ float As[2][16][128];
    __shared__ float Bs[2][16][64];

    const int tid = threadIdx.x;
    const int m0  = blockIdx.y * 128;
    const int n0  = blockIdx.x * 64;
    const int ty  = tid >> 4;
    const int tx  = tid & 15;
    const int r0 = tid >> 2;
    const int r1 = r0 + 64;
    const int c4 = (tid & 3) << 2;

    float4 pa0, pa1, pb;
    auto loadG = [&](int k0) {
        int gk = k0 + c4;
        pa0 = *reinterpret_cast<const float4*>(A + (size_t)(m0 + r0) * lda + gk);
        pa1 = *reinterpret_cast<const float4*>(A + (size_t)(m0 + r1) * lda + gk);
        pb = *reinterpret_cast<const float4*>(Bw + (size_t)(n0 + r0) * K + gk);
    };
    auto storeS = [&](int buf) {
        As[buf][c4 + 0][r0] = pa0.x; As[buf][c4 + 1][r0] = pa0.y;
        As[buf][c4 + 2][r0] = pa0.z; As[buf][c4 + 3][r0] = pa0.w;
        As[buf][c4 + 0][r1] = pa1.x; As[buf][c4 + 1][r1] = pa1.y;
        As[buf][c4 + 2][r1] = pa1.z; As[buf][c4 + 3][r1] = pa1.w;
        Bs[buf][c4 + 0][r0] = pb.x;  Bs[buf][c4 + 1][r0] = pb.y;
        Bs[buf][c4 + 2][r0] = pb.z;  Bs[buf][c4 + 3][r0] = pb.w;
    };

    unsigned long long acc[4][4];
#pragma unroll
    for (int i = 0; i < 4; i++)
#pragma unroll
        for (int j = 0; j < 4; j++) acc[i][j] = 0ull;

    loadG(0); storeS(0); __syncthreads();

    const int nt = K >> 4;
    for (int kt = 0; kt < nt; kt++) {
        const int cur = kt & 1;
        if (kt + 1 < nt) loadG((kt + 1) << 4);
#pragma unroll
        for (int kk = 0; kk < 16; ++kk) {
            const ulonglong2* ap = reinterpret_cast<const ulonglong2*>(&As[cur][kk][ty * 8]);
            ulonglong2 u0 = ap[0], u1 = ap[1];
            unsigned long long a2[4] = {u0.x, u0.y, u1.x, u1.y};
            float4 b = *reinterpret_cast<const float4*>(&Bs[cur][kk][tx * 4]);
            unsigned long long bd[4] = {pack2(b.x, b.x), pack2(b.y, b.y),
                                        pack2(b.z, b.z), pack2(b.w, b.w)};
#pragma unroll
            for (int i = 0; i < 4; i++)
#pragma unroll
                for (int j = 0; j < 4; j++) ffma2(acc[i][j], a2[i], bd[j]);
        }
        if (kt + 1 < nt) { storeS(cur ^ 1); __syncthreads(); }
    }

#pragma unroll
    for (int i = 0; i < 4; i++) {
        const int gm = m0 + ty * 8 + 2 * i;
#pragma unroll
        for (int j = 0; j < 4; j++) {
            float lo, hi;
            unpack2(acc[i][j], lo, hi);
            const int gn = n0 + tx * 4 + j;
            C[(size_t)gm * N + gn]       = lo;
            C[(size_t)(gm + 1) * N + gn] = hi;
        }
    }
}

__global__ void __launch_bounds__(256) init_h0c0(
    const float* __restrict__ chn, const float* __restrict__ thn,
    const float* __restrict__ ccn, const float* __restrict__ tcn,
    float* __restrict__ h0, float* __restrict__ c0)
{
    int idx = blockIdx.x * 256 + threadIdx.x;
    int bb = idx >> 9, e = idx & 511;
    h0[idx] = (e < 256) ? chn[bb * 256 + e] : thn[bb * 256 + e - 256];
    c0[idx] = (e < 256) ? ccn[bb * 256 + e] : tcn[bb * 256 + e - 256];
}

__global__ void __launch_bounds__(256) bias_add2048(
    const float* __restrict__ a, const float* __restrict__ b, float* __restrict__ o)
{
    int i = blockIdx.x * 256 + threadIdx.x;
    o[i] = a[i] + b[i];
}

__global__ void __launch_bounds__(256) transpose512(
    const float* __restrict__ in, float* __restrict__ out)
{
    __shared__ float t[32][33];
    int tx = threadIdx.x & 31, ty = threadIdx.x >> 5;
    int x0 = blockIdx.x * 32, y0 = blockIdx.y * 32;
#pragma unroll
    for (int iy = 0; iy < 4; iy++)
        t[ty + iy * 8][tx] = in[(size_t)(y0 + ty + iy * 8) * 512 + x0 + tx];
    __syncthreads();
#pragma unroll
    for (int iy = 0; iy < 4; iy++)
        out[(size_t)(x0 + ty + iy * 8) * 512 + y0 + tx] = t[tx][ty + iy * 8];
}

__global__ void __launch_bounds__(256) comb_bias(
    const float* __restrict__ out_w, const float* __restrict__ out_b,
    const float* __restrict__ cbo, const float* __restrict__ tbo,
    float* __restrict__ bp)
{
    int v = threadIdx.x;
    float s = out_b[v];
    const float* row = out_w + (size_t)v * 1024;
    for (int e = 0; e < 512; e++) s += row[e] * cbo[e] + row[512 + e] * tbo[e];
    bp[v] = s;
}

template <int S>
__global__ void __launch_bounds__(256) attn_kernel(
    const float* __restrict__ q, const float* __restrict__ k,
    const float* __restrict__ v, float* __restrict__ o)
{
    constexpr int TN = S / 16;
    __shared__ union SU {
        struct { float qs[16][64]; float ks[16][S]; } a;
        float vs[S][64];
    } u;
    __shared__ float sc[64][S];

    const int b = blockIdx.x;
    const int tid = threadIdx.x;
    const int ty = tid >> 4, tx = tid & 15;

    float acc[4][TN];
#pragma unroll
    for (int r = 0; r < 4; r++)
#pragma unroll
        for (int j = 0; j < TN; j++) acc[r][j] = 0.f;

    for (int k0 = 0; k0 < Ed; k0 += 16) {
        {
            int r = tid >> 2, c4 = (tid & 3) << 2;
            float4 val = *reinterpret_cast<const float4*>(q + ((size_t)r * Bsz + b) * Ed + k0 + c4);
            u.a.qs[c4+0][r] = val.x; u.a.qs[c4+1][r] = val.y;
            u.a.qs[c4+2][r] = val.z; u.a.qs[c4+3][r] = val.w;
        }
        if (tid < S * 4) {
            int r = tid >> 2, c4 = (tid & 3) << 2;
            float4 val = *reinterpret_cast<const float4*>(k + ((size_t)b * S + r) * Ed + k0 + c4);
            u.a.ks[c4+0][r] = val.x; u.a.ks[c4+1][r] = val.y;
            u.a.ks[c4+2][r] = val.z; u.a.ks[c4+3][r] = val.w;
        }
        __syncthreads();
#pragma unroll
        for (int kk = 0; kk < 16; kk++) {
            float av[4], bv[TN];
#pragma unroll
            for (int r = 0; r < 4; r++) av[r] = u.a.qs[kk][ty * 4 + r];
#pragma unroll
            for (int j = 0; j < TN; j++) bv[j] = u.a.ks[kk][tx * TN + j];
#pragma unroll
            for (int r = 0; r < 4; r++)
#pragma unroll
                for (int j = 0; j < TN; j++) acc[r][j] += av[r] * bv[j];
        }
        __syncthreads();
    }
#pragma unroll
    for (int r = 0; r < 4; r++)
#pragma unroll
        for (int j = 0; j < TN; j++) sc[ty * 4 + r][tx * TN + j] = acc[r][j];
    __syncthreads();

    if (tid < 64) {
        float mx = -3.4e38f;
        for (int s = 0; s < S; s++) mx = fmaxf(mx, sc[tid][s]);
        float sum = 0.f;
        for (int s = 0; s < S; s++) { float e = expf(sc[tid][s] - mx); sc[tid][s] = e; sum += e; }
        float inv = 1.f / sum;
        for (int s = 0; s < S; s++) sc[tid][s] *= inv;
    }
    __syncthreads();

    for (int n0 = 0; n0 < Ed; n0 += 64) {
#pragma unroll
        for (int it = 0; it < (S * 16) / 256; ++it) {
            int f = tid + it * 256;
            int r = f >> 4, c4 = (f & 15) << 2;
            *reinterpret_cast<float4*>(&u.vs[r][c4]) =
                *reinterpret_cast<const float4*>(v + ((size_t)b * S + r) * Ed + n0 + c4);
        }
        __syncthreads();
        float oa[4][4] = {};
        for (int sk = 0; sk < S; sk++) {
            float p[4];
#pragma unroll
            for (int r = 0; r < 4; r++) p[r] = sc[ty * 4 + r][sk];
            float4 vv = *reinterpret_cast<const float4*>(&u.vs[sk][tx * 4]);
            float vf[4] = {vv.x, vv.y, vv.z, vv.w};
#pragma unroll
            for (int r = 0; r < 4; r++)
#pragma unroll
                for (int j = 0; j < 4; j++) oa[r][j] += p[r] * vf[j];
        }
#pragma unroll
        for (int r = 0; r < 4; r++) {
            size_t base = ((size_t)(ty * 4 + r) * Bsz + b) * Ed + n0 + tx * 4;
            *reinterpret_cast<float4*>(&o[base]) = make_float4(oa[r][0], oa[r][1], oa[r][2], oa[r][3]);
        }
        __syncthreads();
    }
}

__global__ void __launch_bounds__(256) entmax_kernel(
    const float* __restrict__ logits, float* __restrict__ out)
{
    __shared__ float s[256], cs1[256], cs2[256], taus[256], red[256];
    const int row = blockIdx.x;
    const int tid = threadIdx.x;

    float z = logits[(size_t)row * 256 + tid] * 0.5f;
    red[tid] = z;
    __syncthreads();
    for (int off = 128; off > 0; off >>= 1) {
        if (tid < off) red[tid] = fmaxf(red[tid], red[tid + off]);
        __syncthreads();
    }
    z -= red[0];
    __syncthreads();

    s[tid] = -z;
    __syncthreads();
    for (int kk = 2; kk <= 256; kk <<= 1) {
        for (int j = kk >> 1; j > 0; j >>= 1) {
            int ixj = tid ^ j;
            if (ixj > tid) {
                float a = s[tid], b2 = s[ixj];
                bool swp = ((tid & kk) == 0) ? (a > b2) : (a < b2);
                if (swp) { s[tid] = b2; s[ixj] = a; }
            }
            __syncthreads();
        }
    }
    float zs = -s[tid];

    cs1[tid] = zs; cs2[tid] = zs * zs;
    __syncthreads();
    for (int off = 1; off < 256; off <<= 1) {
        float a1 = 0.f, a2 = 0.f;
        if (tid >= off) { a1 = cs1[tid - off]; a2 = cs2[tid - off]; }
        __syncthreads();
        if (tid >= off) { cs1[tid] += a1; cs2[tid] += a2; }
        __syncthreads();
    }

    float rho   = (float)(tid + 1);
    float mean  = cs1[tid] / rho;
    float msq   = cs2[tid] / rho;
    float ssv   = rho * (msq - mean * mean);
    float delta = (1.0f - ssv) / rho;
    float sq    = (delta > 0.f) ? sqrtf(delta) : 0.f;
    float tau   = mean - sq;
    taus[tid] = tau;
    red[tid]  = (tau <= zs) ? 1.f : 0.f;
    __syncthreads();
    for (int off = 128; off > 0; off >>= 1) {
        if (tid < off) red[tid] += red[tid + off];
        __syncthreads();
    }
    int kcnt = (int)red[0];
    float tau_star = taus[kcnt - 1];
    float y = fmaxf(z - tau_star, 0.f);
    int t = row >> 9, b = row & 511;
    out[((size_t)b * Tc + t) * Vd + tid] = y * y;
}

extern "C" void kernel_launch(void* const* d_in, const int* in_sizes, int n_in,
                              void* d_out, int out_size)
{
    const float* char_enc = (const float*)d_in[0];
    const float* char_hn0 = (const float*)d_in[1];
    const float* char_cn0 = (const float*)d_in[2];
    const float* tag_enc  = (const float*)d_in[3];
    const float* tag_hn0  = (const float*)d_in[4];
    const float* tag_cn0  = (const float*)d_in[5];
    const float* tos      = (const float*)d_in[6];
    const float* w_ih     = (const float*)d_in[7];
    const float* w_hh     = (const float*)d_in[8];
    const float* b_ih     = (const float*)d_in[9];
    const float* b_hh     = (const float*)d_in[10];
    const float* cwq = (const float*)d_in[11];
    const float* cwk = (const float*)d_in[12];
    const float* cwv = (const float*)d_in[13];
    const float* cbq = (const float*)d_in[14];
    const float* cbk = (const float*)d_in[15];
    const float* cbv = (const float*)d_in[16];
    const float* cwo = (const float*)d_in[17];
    const float* cbo = (const float*)d_in[18];
    const float* twq = (const float*)d_in[19];
    const float* twk = (const float*)d_in[20];
    const float* twv = (const float*)d_in[21];
    const float* tbq = (const float*)d_in[22];
    const float* tbk = (const float*)d_in[23];
    const float* tbv = (const float*)d_in[24];
    const float* two_ = (const float*)d_in[25];
    const float* tbo = (const float*)d_in[26];
    const float* out_w = (const float*)d_in[27];
    const float* out_b = (const float*)d_in[28];
    float* out = (float*)d_out;

    float *xg, *h0, *c0, *hs, *qc, *kc, *vc, *qt, *kt, *vt, *oc, *ot, *lg;
    float *bias2, *Wc, *Wt, *cwoT, *twoT, *bcomb;
    cudaGetSymbolAddress((void**)&xg,    g_xgates);
    cudaGetSymbolAddress((void**)&h0,    g_h0);
    cudaGetSymbolAddress((void**)&c0,    g_c);
    cudaGetSymbolAddress((void**)&hs,    g_hs);
    cudaGetSymbolAddress((void**)&qc,    g_qc);
    cudaGetSymbolAddress((void**)&kc,    g_kc);
    cudaGetSymbolAddress((void**)&vc,    g_vc);
    cudaGetSymbolAddress((void**)&qt,    g_qt);
    cudaGetSymbolAddress((void**)&kt,    g_kt);
    cudaGetSymbolAddress((void**)&vt,    g_vt);
    cudaGetSymbolAddress((void**)&oc,    g_oc);
    cudaGetSymbolAddress((void**)&ot,    g_ot);
    cudaGetSymbolAddress((void**)&lg,    g_lg);
    cudaGetSymbolAddress((void**)&bias2, g_bias2);
    cudaGetSymbolAddress((void**)&Wc,    g_Wc);
    cudaGetSymbolAddress((void**)&Wt,    g_Wt);
    cudaGetSymbolAddress((void**)&cwoT,  g_cwoT);
    cudaGetSymbolAddress((void**)&twoT,  g_twoT);
    cudaGetSymbolAddress((void**)&bcomb, g_bcomb);

    __nv_bfloat16 *whhH, *whhL, *wihH, *wihL, *cwkH, *cwkL, *cwvH, *cwvL, *cwqH, *cwqL;
    __nv_bfloat16 *twkH, *twkL, *twvH, *twvL, *twqH, *twqL, *WcH, *WcL, *WtH, *WtL;
    cudaGetSymbolAddress((void**)&whhH, g_whhH); cudaGetSymbolAddress((void**)&whhL, g_whhL);
    cudaGetSymbolAddress((void**)&wihH, g_wihH); cudaGetSymbolAddress((void**)&wihL, g_wihL);
    cudaGetSymbolAddress((void**)&cwkH, g_cwkH); cudaGetSymbolAddress((void**)&cwkL, g_cwkL);
    cudaGetSymbolAddress((void**)&cwvH, g_cwvH); cudaGetSymbolAddress((void**)&cwvL, g_cwvL);
    cudaGetSymbolAddress((void**)&cwqH, g_cwqH); cudaGetSymbolAddress((void**)&cwqL, g_cwqL);
    cudaGetSymbolAddress((void**)&twkH, g_twkH); cudaGetSymbolAddress((void**)&twkL, g_twkL);
    cudaGetSymbolAddress((void**)&twvH, g_twvH); cudaGetSymbolAddress((void**)&twvL, g_twvL);
    cudaGetSymbolAddress((void**)&twqH, g_twqH); cudaGetSymbolAddress((void**)&twqL, g_twqL);
    cudaGetSymbolAddress((void**)&WcH,  g_WcH);  cudaGetSymbolAddress((void**)&WcL,  g_WcL);
    cudaGetSymbolAddress((void**)&WtH,  g_WtH);  cudaGetSymbolAddress((void**)&WtL,  g_WtL);

    const float qscale = 1.0f / sqrtf(512.0f);
    const int smem_g = 30720 * 4;   // 122880

    cudaFuncSetAttribute(mma_gemm2<0>, cudaFuncAttributeMaxDynamicSharedMemorySize, smem_g);
    cudaFuncSetAttribute(mma_gemm2<1>, cudaFuncAttributeMaxDynamicSharedMemorySize, smem_g);
    cudaFuncSetAttribute(mma_gemm2<2>, cudaFuncAttributeMaxDynamicSharedMemorySize, smem_g);
    cudaFuncSetAttribute(lstm_persist, cudaFuncAttributeMaxDynamicSharedMemorySize, LP_SMEM_BYTES);

    // 1-3: conversions needed by the first GEMMs
    conv_split_k<<<2048, 256>>>(w_ih, wihH, wihL, 524288);
    conv_split_k<<<1024, 256>>>(cwk, cwkH, cwkL, 262144);
    conv_split_k<<<1024, 256>>>(cwv, cwvH, cwvL, 262144);

    // 4-6: big tensor GEMMs early (ncu capture targets)
    mma_gemm2<1><<<dim3(16, 128), 512, smem_g>>>(xg, tos, nullptr, wihH, wihL, nullptr, nullptr,
                                                 nullptr, 32768, 2048, 256, 256, 256, 1.0f);
    mma_gemm2<0><<<dim3(4, 128), 512, smem_g>>>(kc, char_enc, nullptr, cwkH, cwkL, nullptr, nullptr,
                                                cbk, 32768, 512, 512, 512, 512, 1.0f);
    mma_gemm2<0><<<dim3(4, 128), 512, smem_g>>>(vc, char_enc, nullptr, cwvH, cwvL, nullptr, nullptr,
                                                cbv, 32768, 512, 512, 512, 512, 1.0f);

    // small precomputes
    init_h0c0<<<1024, 256>>>(char_hn0, tag_hn0, char_cn0, tag_cn0, h0, c0);
    bias_add2048<<<8, 256>>>(b_ih, b_hh, bias2);
    transpose512<<<dim3(16, 16), 256>>>(cwo, cwoT);
    transpose512<<<dim3(16, 16), 256>>>(two_, twoT);
    comb_bias<<<1, 256>>>(out_w, out_b, cbo, tbo, bcomb);

    // folded head weights (fp32), then convert
    gemm3<<<dim3(8, 2), 256>>>(Wc, out_w,       cwoT, 256, 512, 512, 1024);
    gemm3<<<dim3(8, 2), 256>>>(Wt, out_w + 512, twoT, 256, 512, 512, 1024);

    // remaining weight conversions
    conv_split_k<<<4096, 256>>>(w_hh, whhH, whhL, 1048576);
    conv_split_k<<<1024, 256>>>(cwq, cwqH, cwqL, 262144);
    conv_split_k<<<1024, 256>>>(twk, twkH, twkL, 262144);
    conv_split_k<<<1024, 256>>>(twv, twvH, twvL, 262144);
    conv_split_k<<<1024, 256>>>(twq, twqH, twqL, 262144);
    conv_split_k<<<512, 256>>>(Wc, WcH, WcL, 131072);
    conv_split_k<<<512, 256>>>(Wt, WtH, WtL, 131072);

    // tag-side projections
    mma_gemm2<0><<<dim3(4, 32), 512, smem_g>>>(kt, tag_enc, nullptr, twkH, twkL, nullptr, nullptr,
                                               tbk, 8192, 512, 512, 512, 512, 1.0f);
    mma_gemm2<0><<<dim3(4, 32), 512, smem_g>>>(vt, tag_enc, nullptr, twvH, twvL, nullptr, nullptr,
                                               tbv, 8192, 512, 512, 512, 512, 1.0f);

    // persistent LSTM (one launch, 128 CTAs, internal 64-step loop)
    lstm_persist<<<dim3(32, 4), 256, LP_SMEM_BYTES>>>(h0, whhH, whhL, xg, bias2, c0, hs);

    // q projections
    mma_gemm2<0><<<dim3(4, 128), 512, smem_g>>>(qc, hs, nullptr, cwqH, cwqL, nullptr, nullptr,
                                                cbq, 32768, 512, 512, 512, 512, qscale);
    mma_gemm2<0><<<dim3(4, 128), 512, smem_g>>>(qt, hs, nullptr, twqH, twqL, nullptr, nullptr,
                                                tbq, 32768, 512, 512, 512, 512, qscale);

    // attention
    attn_kernel<64><<<512, 256>>>(qc, kc, vc, oc);
    attn_kernel<16><<<512, 256>>>(qt, kt, vt, ot);

    // logits = oc @ Wc^T + ot @ Wt^T + bcomb (concat GEMM, K=1024)
    mma_gemm2<2><<<dim3(2, 128), 512, smem_g>>>(lg, oc, ot, WcH, WcL, WtH, WtL,
                                                bcomb, 32768, 256, 1024, 512, 512, 1.0f);

    // entmax + transpose to (B,T,V)
    entmax_kernel<<<32768, 256>>>(lg, out);
}

// round 15
// speedup vs baseline: 1.0771x; 1.0625x over previous
#include <cuda_runtime.h>
#include <cuda_bf16.h>
#include <math.h>
#include <stdint.h>

#define Bsz 512
#define Tc  64
#define Ed  512
#define Vd  256

__device__ float g_xgates[67108864];   // (T,B,4E)
__device__ float g_h0    [262144];
__device__ float g_c     [262144];
__device__ float g_hs    [16777216];   // (T,B,E)
__device__ float g_qc    [16777216];
__device__ float g_kc    [16777216];
__device__ float g_vc    [16777216];
__device__ float g_qt    [16777216];
__device__ float g_kt    [4194304];
__device__ float g_vt    [4194304];
__device__ float g_oc    [16777216];
__device__ float g_ot    [16777216];
__device__ float g_lg    [8388608];    // (T,B,V)
__device__ float g_bias2 [2048];
__device__ float g_Wc    [131072];     // (V,E)
__device__ float g_Wt    [131072];
__device__ float g_cwoT  [262144];
__device__ float g_twoT  [262144];
__device__ float g_bcomb [256];

__device__ __nv_bfloat16 g_whhH[1048576], g_whhL[1048576];
__device__ __nv_bfloat16 g_wihH[524288],  g_wihL[524288];
__device__ __nv_bfloat16 g_cwkH[262144],  g_cwkL[262144];
__device__ __nv_bfloat16 g_cwvH[262144],  g_cwvL[262144];
__device__ __nv_bfloat16 g_cwqH[262144],  g_cwqL[262144];
__device__ __nv_bfloat16 g_twkH[262144],  g_twkL[262144];
__device__ __nv_bfloat16 g_twvH[262144],  g_twvL[262144];
__device__ __nv_bfloat16 g_twqH[262144],  g_twqL[262144];
__device__ __nv_bfloat16 g_WcH[131072],   g_WcL[131072];
__device__ __nv_bfloat16 g_WtH[131072],   g_WtL[131072];

__device__ unsigned g_cnt;
__device__ volatile unsigned g_epoch;

// ======================= helpers ===========================================
__device__ __forceinline__ void ffma2(unsigned long long& d, unsigned long long a,
                                      unsigned long long b) {
    asm("fma.rn.f32x2 %0, %1, %2, %0;" : "+l"(d) : "l"(a), "l"(b));
}
__device__ __forceinline__ unsigned long long pack2(float x, float y) {
    unsigned long long r;
    asm("mov.b64 %0, {%1, %2};" : "=l"(r) : "r"(__float_as_uint(x)), "r"(__float_as_uint(y)));
    return r;
}
__device__ __forceinline__ void unpack2(unsigned long long d, float& lo, float& hi) {
    unsigned int l, h;
    asm("mov.b64 {%0, %1}, %2;" : "=r"(l), "=r"(h) : "l"(d));
    lo = __uint_as_float(l); hi = __uint_as_float(h);
}
__device__ __forceinline__ float sigmoidf_(float x) { return 1.0f / (1.0f + expf(-x)); }

__device__ __forceinline__ void mma16816(float* c, const uint32_t* a, uint32_t b0, uint32_t b1) {
    asm volatile(
        "mma.sync.aligned.m16n8k16.row.col.f32.bf16.bf16.f32 "
        "{%0,%1,%2,%3}, {%4,%5,%6,%7}, {%8,%9}, {%0,%1,%2,%3};"
        : "+f"(c[0]), "+f"(c[1]), "+f"(c[2]), "+f"(c[3])
        : "r"(a[0]), "r"(a[1]), "r"(a[2]), "r"(a[3]), "r"(b0), "r"(b1));
}
__device__ __forceinline__ void ldsm_x4(uint32_t* r, uint32_t addr) {
    asm volatile("ldmatrix.sync.aligned.m8n8.x4.shared.b16 {%0,%1,%2,%3}, [%4];"
                 : "=r"(r[0]), "=r"(r[1]), "=r"(r[2]), "=r"(r[3]) : "r"(addr));
}
__device__ __forceinline__ void ldsm_x2(uint32_t& r0, uint32_t& r1, uint32_t addr) {
    asm volatile("ldmatrix.sync.aligned.m8n8.x2.shared.b16 {%0,%1}, [%2];"
                 : "=r"(r0), "=r"(r1) : "r"(addr));
}
__device__ __forceinline__ void cvt_split4(float4 v, uint2& hi, uint2& lo) {
    __nv_bfloat16 h0 = __float2bfloat16(v.x), h1 = __float2bfloat16(v.y);
    __nv_bfloat16 h2 = __float2bfloat16(v.z), h3 = __float2bfloat16(v.w);
    __nv_bfloat16 l0 = __float2bfloat16(v.x - __bfloat162float(h0));
    __nv_bfloat16 l1 = __float2bfloat16(v.y - __bfloat162float(h1));
    __nv_bfloat16 l2 = __float2bfloat16(v.z - __bfloat162float(h2));
    __nv_bfloat16 l3 = __float2bfloat16(v.w - __bfloat162float(h3));
    hi.x = (uint32_t)__bfloat16_as_ushort(h0) | ((uint32_t)__bfloat16_as_ushort(h1) << 16);
    hi.y = (uint32_t)__bfloat16_as_ushort(h2) | ((uint32_t)__bfloat16_as_ushort(h3) << 16);
    lo.x = (uint32_t)__bfloat16_as_ushort(l0) | ((uint32_t)__bfloat16_as_ushort(l1) << 16);
    lo.y = (uint32_t)__bfloat16_as_ushort(l2) | ((uint32_t)__bfloat16_as_ushort(l3) << 16);
}

__global__ void __launch_bounds__(256) conv_split_k(
    const float* __restrict__ s, __nv_bfloat16* __restrict__ h,
    __nv_bfloat16* __restrict__ l, int n)
{
    int i = blockIdx.x * 256 + threadIdx.x;
    if (i < n) {
        float v = s[i];
        __nv_bfloat16 hv = __float2bfloat16(v);
        h[i] = hv;
        l[i] = __float2bfloat16(v - __bfloat162float(hv));
    }
}

// ---------------------------------------------------------------------------
// mma.sync GEMM (NT), CTA 256x128, 512 threads / 16 warps (4m x 4n),
// warp tile 64x32, K-chunk 32. Plane-major MMA order (dep distance 8).
// ---------------------------------------------------------------------------
template <int MODE>
__global__ void __launch_bounds__(512) mma_gemm2(
    float* __restrict__ C, const float* __restrict__ A, const float* __restrict__ A2,
    const __nv_bfloat16* __restrict__ BH, const __nv_bfloat16* __restrict__ BL,
    const __nv_bfloat16* __restrict__ BH2, const __nv_bfloat16* __restrict__ BL2,
    const float* __restrict__ bias, int M, int N, int K, int lda, int ldb, float alpha)
{
    extern __shared__ uint32_t sm[];

    const int tid  = threadIdx.x;
    const int lane = tid & 31, wid = tid >> 5;
    const int wm = wid >> 2, wn = wid & 3;
    const int m0 = blockIdx.y * 256, n0 = blockIdx.x * 128;
    const int gq = lane >> 2, pl = lane & 3;

    const uint32_t sb4 = (uint32_t)__cvta_generic_to_shared(sm);
    const int arow  = (lane & 7) + ((lane >> 3) & 1) * 8;
    const int akoff = (lane >> 4) * 4;
    const int brow  = lane & 7;
    const int bkoff = ((lane >> 3) & 1) * 4;

    float c[4][4][4];
#pragma unroll
    for (int i = 0; i < 4; i++)
#pragma unroll
        for (int j = 0; j < 4; j++)
#pragma unroll
            for (int q = 0; q < 4; q++) c[i][j][q] = 0.f;

    float4 avr[4];
    uint4 bhr, blr;

    auto gload = [&](int ch) {
        const float* Ae = A;
        const __nv_bfloat16 *bh = BH, *bl = BL;
        int k0 = ch << 5;
        if (MODE == 2 && k0 >= 512) { Ae = A2; bh = BH2; bl = BL2; k0 -= 512; }
#pragma unroll
        for (int i = 0; i < 4; i++) {
            int f = tid + i * 512, r = f >> 3, cq = f & 7;
            if constexpr (MODE == 1) {
                int gm = m0 + r, tt = gm >> 9, bb = gm & 511;
                avr[i] = tt ? *reinterpret_cast<const float4*>(Ae + (size_t)bb * 16384 + tt * 256 + k0 + cq * 4)
                            : make_float4(0.f, 0.f, 0.f, 0.f);
            } else {
                avr[i] = *reinterpret_cast<const float4*>(Ae + (size_t)(m0 + r) * lda + k0 + cq * 4);
            }
        }
        {
            int r = tid >> 2, cq = tid & 3;
            bhr = *reinterpret_cast<const uint4*>(bh + (size_t)(n0 + r) * ldb + k0 + cq * 8);
            blr = *reinterpret_cast<const uint4*>(bl + (size_t)(n0 + r) * ldb + k0 + cq * 8);
        }
    };
    auto sstore = [&](int buf) {
        const int ab = buf * 5120;
#pragma unroll
        for (int i = 0; i < 4; i++) {
            int f = tid + i * 512, r = f >> 3, cq = f & 7;
            uint2 hi, lo;
            cvt_split4(avr[i], hi, lo);
            int idx = ab + r * 20 + cq * 2;
            *reinterpret_cast<uint2*>(&sm[idx])         = hi;
            *reinterpret_cast<uint2*>(&sm[10240 + idx]) = lo;
        }
        {
            int r = tid >> 2, cq = tid & 3;
            int idx = buf * 2560 + r * 20 + cq * 4;
            *reinterpret_cast<uint4*>(&sm[20480 + idx]) = bhr;
            *reinterpret_cast<uint4*>(&sm[25600 + idx]) = blr;
        }
    };

    const int nch = K >> 5;
    gload(0);
    sstore(0);
    __syncthreads();

    for (int ch = 0; ch < nch; ch++) {
        const int buf = ch & 1;
        const bool more = (ch + 1 < nch);
        if (more) gload(ch + 1);
        const int ab = buf * 5120;
        const int bb = buf * 2560;
#pragma unroll
        for (int s = 0; s < 2; s++) {
            uint32_t bh0[4], bh1[4], bl0[4], bl1[4];
#pragma unroll
            for (int nf = 0; nf < 4; nf++) {
                uint32_t baddr = sb4 + 4u * (uint32_t)(20480 + bb + (wn * 32 + nf * 8 + brow) * 20 + s * 8 + bkoff);
                ldsm_x2(bh0[nf], bh1[nf], baddr);
                ldsm_x2(bl0[nf], bl1[nf], baddr + 5120u * 4u);
            }
#pragma unroll
            for (int mp = 0; mp < 2; mp++) {
                const int mf0 = mp * 2, mf1 = mp * 2 + 1;
                uint32_t a0[4], a1[4];
                uint32_t aaddr0 = sb4 + 4u * (uint32_t)(ab + (wm * 64 + mf0 * 16 + arow) * 20 + s * 8 + akoff);
                uint32_t aaddr1 = sb4 + 4u * (uint32_t)(ab + (wm * 64 + mf1 * 16 + arow) * 20 + s * 8 + akoff);
                ldsm_x4(a0, aaddr0);
                ldsm_x4(a1, aaddr1);
#pragma unroll
                for (int nf = 0; nf < 4; nf++) mma16816(c[mf0][nf], a0, bh0[nf], bh1[nf]);
#pragma unroll
                for (int nf = 0; nf < 4; nf++) mma16816(c[mf1][nf], a1, bh0[nf], bh1[nf]);
#pragma unroll
                for (int nf = 0; nf < 4; nf++) mma16816(c[mf0][nf], a0, bl0[nf], bl1[nf]);
#pragma unroll
                for (int nf = 0; nf < 4; nf++) mma16816(c[mf1][nf], a1, bl0[nf], bl1[nf]);
                ldsm_x4(a0, aaddr0 + 10240u * 4u);
                ldsm_x4(a1, aaddr1 + 10240u * 4u);
#pragma unroll
                for (int nf = 0; nf < 4; nf++) mma16816(c[mf0][nf], a0, bh0[nf], bh1[nf]);
#pragma unroll
                for (int nf = 0; nf < 4; nf++) mma16816(c[mf1][nf], a1, bh0[nf], bh1[nf]);
            }
        }
        if (more) {
            sstore(buf ^ 1);
            __syncthreads();
        }
    }

#pragma unroll
    for (int mf = 0; mf < 4; mf++) {
#pragma unroll
        for (int nf = 0; nf < 4; nf++) {
            int r  = m0 + wm * 64 + mf * 16 + gq;
            int cc = n0 + wn * 32 + nf * 8 + pl * 2;
            float b0 = 0.f, b1 = 0.f;
            if (bias) { b0 = bias[cc]; b1 = bias[cc + 1]; }
            *reinterpret_cast<float2*>(&C[(size_t)r * N + cc]) =
                make_float2(alpha * (c[mf][nf][0] + b0), alpha * (c[mf][nf][1] + b1));
            *reinterpret_cast<float2*>(&C[(size_t)(r + 8) * N + cc]) =
                make_float2(alpha * (c[mf][nf][2] + b0), alpha * (c[mf][nf][3] + b1));
        }
    }
}

// ---------------------------------------------------------------------------
// Persistent LSTM (R12's proven inner loop)
// ---------------------------------------------------------------------------
#define LP_BH 0
#define LP_BL 16640
#define LP_A  33280
#define LP_SMEM_BYTES (43520 * 4)

__device__ __forceinline__ void grid_barrier128(int tid) {
    __threadfence();
    __syncthreads();
    if (tid == 0) {
        unsigned e = g_epoch;
        if (atomicAdd(&g_cnt, 1u) == 127u) {
            g_cnt = 0;
            __threadfence();
            g_epoch = e + 1;
        } else {
            while (g_epoch == e) { }
        }
    }
    __syncthreads();
}

__global__ void __launch_bounds__(256) lstm_persist(
    const float* __restrict__ h0,
    const __nv_bfloat16* __restrict__ whhH, const __nv_bfloat16* __restrict__ whhL,
    const float* __restrict__ xg, const float* __restrict__ bias2,
    const float* __restrict__ c0, float* __restrict__ hs)
{
    extern __shared__ uint32_t sm[];
    const int tid  = threadIdx.x;
    const int lane = tid & 31, wid = tid >> 5;
    const int wm = wid >> 2, wn = wid & 3;
    const int e0 = blockIdx.x * 16;
    const int m0 = blockIdx.y * 128;
    const int gq = lane >> 2, pl = lane & 3;

    const uint32_t sb4 = (uint32_t)__cvta_generic_to_shared(sm);
    const int arow  = (lane & 7) + ((lane >> 3) & 1) * 8;
    const int akoff = (lane >> 4) * 4;
    const int brow  = lane & 7;
    const int bkoff = ((lane >> 3) & 1) * 4;

#pragma unroll
    for (int i = 0; i < 16; i++) {
        int f = tid + i * 256;
        int r = f >> 6, q = f & 63;
        int gr = (r >> 4) * 512 + e0 + (r & 15);
        *reinterpret_cast<uint4*>(&sm[LP_BH + r * 260 + q * 4]) =
            *reinterpret_cast<const uint4*>(whhH + (size_t)gr * 512 + q * 8);
        *reinterpret_cast<uint4*>(&sm[LP_BL + r * 260 + q * 4]) =
            *reinterpret_cast<const uint4*>(whhL + (size_t)gr * 512 + q * 8);
    }

    float creg[8];
#pragma unroll
    for (int ir = 0; ir < 8; ir++) {
        int idx = tid + ir * 256;
        int row = idx >> 4, e = idx & 15;
        creg[ir] = c0[(size_t)(m0 + row) * 512 + e0 + e];
    }
    __syncthreads();

    for (int t = 0; t < 64; t++) {
        const float* hprev = (t == 0) ? h0 : (hs + (size_t)(t - 1) * 262144);
        const float* xg_t  = xg + (size_t)t * 1048576;
        float* hout        = hs + (size_t)t * 262144;

        float c[4][2][4];
#pragma unroll
        for (int i = 0; i < 4; i++)
#pragma unroll
            for (int j = 0; j < 2; j++)
#pragma unroll
                for (int q = 0; q < 4; q++) c[i][j][q] = 0.f;

        float4 avr[4];
        auto gloadA = [&](int ch) {
            int k0 = ch << 5;
#pragma unroll
            for (int i = 0; i < 4; i++) {
                int f = tid + i * 256, r = f >> 3, cq = f & 7;
                avr[i] = *reinterpret_cast<const float4*>(hprev + (size_t)(m0 + r) * 512 + k0 + cq * 4);
            }
        };
        auto sstoreA = [&](int buf) {
            const int ab = LP_A + buf * 5120;
#pragma unroll
            for (int i = 0; i < 4; i++) {
                int f = tid + i * 256, r = f >> 3, cq = f & 7;
                uint2 hi, lo;
                cvt_split4(avr[i], hi, lo);
                int idx = ab + r * 20 + cq * 2;
                *reinterpret_cast<uint2*>(&sm[idx])        = hi;
                *reinterpret_cast<uint2*>(&sm[2560 + idx]) = lo;
            }
        };

        gloadA(0);
        sstoreA(0);
        __syncthreads();

        for (int ch = 0; ch < 16; ch++) {
            const int buf = ch & 1;
            const bool more = (ch < 15);
            if (more) gloadA(ch + 1);
            const int ab = LP_A + buf * 5120;
#pragma unroll
            for (int s = 0; s < 2; s++) {
                uint32_t ah[4][4], al4[4][4];
#pragma unroll
                for (int mf = 0; mf < 4; mf++) {
                    uint32_t addr = sb4 + 4u * (uint32_t)(ab + (wm * 64 + mf * 16 + arow) * 20 + s * 8 + akoff);
                    ldsm_x4(ah[mf], addr);
                    ldsm_x4(al4[mf], addr + 2560u * 4u);
                }
#pragma unroll
                for (int nf = 0; nf < 2; nf++) {
                    uint32_t baddr = sb4 + 4u * (uint32_t)((wn * 16 + nf * 8 + brow) * 260 + ch * 16 + s * 8 + bkoff);
                    uint32_t bh0, bh1, bl0, bl1;
                    ldsm_x2(bh0, bh1, baddr + LP_BH * 4u);
                    ldsm_x2(bl0, bl1, baddr + LP_BL * 4u);
#pragma unroll
                    for (int mf = 0; mf < 4; mf++) {
                        mma16816(c[mf][nf], ah[mf], bh0, bh1);
                        mma16816(c[mf][nf], ah[mf], bl0, bl1);
                        mma16816(c[mf][nf], al4[mf], bh0, bh1);
                    }
                }
            }
            if (more) {
                sstoreA(buf ^ 1);
                __syncthreads();
            }
        }

        __syncthreads();
        float* Gs = reinterpret_cast<float*>(&sm[LP_A]);
#pragma unroll
        for (int mf = 0; mf < 4; mf++) {
#pragma unroll
            for (int nf = 0; nf < 2; nf++) {
                int rr = wm * 64 + mf * 16 + gq;
                int cc = wn * 16 + nf * 8 + pl * 2;
                Gs[rr * 64 + cc]           = c[mf][nf][0];
                Gs[rr * 64 + cc + 1]       = c[mf][nf][1];
                Gs[(rr + 8) * 64 + cc]     = c[mf][nf][2];
                Gs[(rr + 8) * 64 + cc + 1] = c[mf][nf][3];
            }
        }
        __syncthreads();

#pragma unroll
        for (int ir = 0; ir < 8; ir++) {
            int idx = tid + ir * 256;
            int row = idx >> 4, e = idx & 15;
            int b = m0 + row, ni = e0 + e;
            const float* xr = xg_t + (size_t)b * 2048;
            float gi = Gs[row * 64 + e]      + bias2[ni]        + xr[ni];
            float gf = Gs[row * 64 + 16 + e] + bias2[ni + 512]  + xr[ni + 512];
            float gg = Gs[row * 64 + 32 + e] + bias2[ni + 1024] + xr[ni + 1024];
            float go = Gs[row * 64 + 48 + e] + bias2[ni + 1536] + xr[ni + 1536];
            float cc2 = sigmoidf_(gf) * creg[ir] + sigmoidf_(gi) * tanhf(gg);
            creg[ir] = cc2;
            hout[(size_t)b * 512 + ni] = sigmoidf_(go) * tanhf(cc2);
        }

        if (t < 63) grid_barrier128(tid);
    }
}

// ======================= SIMT gemm (Wc/Wt precompute only) ==================
__global__ void __launch_bounds__(256) gemm3(
    float* __restrict__ C, const float* __restrict__ A,
    const float* __restrict__ Bw, int M, int N, int K, int lda)
{
    __shared__ float As[2][16][128];
    __shared__ float Bs[2][16][64];

    const int tid = threadIdx.x;
    const int m0  = blockIdx.y * 128;
    const int n0  = blockIdx.x * 64;
    const int ty  = tid >> 4;
    const int tx  = tid & 15;
    const int r0 = tid >> 2;
    const int r1 = r0 + 64;
    const int c4 = (tid & 3) << 2;

    float4 pa0, pa1, pb;
    auto loadG = [&](int k0) {
        int gk = k0 + c4;
        pa0 = *reinterpret_cast<const float4*>(A + (size_t)(m0 + r0) * lda + gk);
        pa1 = *reinterpret_cast<const float4*>(A + (size_t)(m0 + r1) * lda + gk);
        pb = *reinterpret_cast<const float4*>(Bw + (size_t)(n0 + r0) * K + gk);
    };
    auto storeS = [&](int buf) {
        As[buf][c4 + 0][r0] = pa0.x; As[buf][c4 + 1][r0] = pa0.y;
        As[buf][c4 + 2][r0] = pa0.z; As[buf][c4 + 3][r0] = pa0.w;
        As[buf][c4 + 0][r1] = pa1.x; As[buf][c4 + 1][r1] = pa1.y;
        As[buf][c4 + 2][r1] = pa1.z; As[buf][c4 + 3][r1] = pa1.w;
        Bs[buf][c4 + 0][r0] = pb.x;  Bs[buf][c4 + 1][r0] = pb.y;
        Bs[buf][c4 + 2][r0] = pb.z;  Bs[buf][c4 + 3][r0] = pb.w;
    };

    unsigned long long acc[4][4];
#pragma unroll
    for (int i = 0; i < 4; i++)
#pragma unroll
        for (int j = 0; j < 4; j++) acc[i][j] = 0ull;

    loadG(0); storeS(0); __syncthreads();

    const int nt = K >> 4;
    for (int kt = 0; kt < nt; kt++) {
        const int cur = kt & 1;
        if (kt + 1 < nt) loadG((kt + 1) << 4);
#pragma unroll
        for (int kk = 0; kk < 16; ++kk) {
            const ulonglong2* ap = reinterpret_cast<const ulonglong2*>(&As[cur][kk][ty * 8]);
            ulonglong2 u0 = ap[0], u1 = ap[1];
            unsigned long long a2[4] = {u0.x, u0.y, u1.x, u1.y};
            float4 b = *reinterpret_cast<const float4*>(&Bs[cur][kk][tx * 4]);
            unsigned long long bd[4] = {pack2(b.x, b.x), pack2(b.y, b.y),
                                        pack2(b.z, b.z), pack2(b.w, b.w)};
#pragma unroll
            for (int i = 0; i < 4; i++)
#pragma unroll
                for (int j = 0; j < 4; j++) ffma2(acc[i][j], a2[i], bd[j]);
        }
        if (kt + 1 < nt) { storeS(cur ^ 1); __syncthreads(); }
    }

#pragma unroll
    for (int i = 0; i < 4; i++) {
        const int gm = m0 + ty * 8 + 2 * i;
#pragma unroll
        for (int j = 0; j < 4; j++) {
            float lo, hi;
            unpack2(acc[i][j], lo, hi);
            const int gn = n0 + tx * 4 + j;
            C[(size_t)gm * N + gn]       = lo;
            C[(size_t)(gm + 1) * N + gn] = hi;
        }
    }
}

__global__ void __launch_bounds__(256) init_h0c0(
    const float* __restrict__ chn, const float* __restrict__ thn,
    const float* __restrict__ ccn, const float* __restrict__ tcn,
    float* __restrict__ h0, float* __restrict__ c0)
{
    int idx = blockIdx.x * 256 + threadIdx.x;
    int bb = idx >> 9, e = idx & 511;
    h0[idx] = (e < 256) ? chn[bb * 256 + e] : thn[bb * 256 + e - 256];
    c0[idx] = (e < 256) ? ccn[bb * 256 + e] : tcn[bb * 256 + e - 256];
}

__global__ void __launch_bounds__(256) bias_add2048(
    const float* __restrict__ a, const float* __restrict__ b, float* __restrict__ o)
{
    int i = blockIdx.x * 256 + threadIdx.x;
    o[i] = a[i] + b[i];
}

__global__ void __launch_bounds__(256) transpose512(
    const float* __restrict__ in, float* __restrict__ out)
{
    __shared__ float t[32][33];
    int tx = threadIdx.x & 31, ty = threadIdx.x >> 5;
    int x0 = blockIdx.x * 32, y0 = blockIdx.y * 32;
#pragma unroll
    for (int iy = 0; iy < 4; iy++)
        t[ty + iy * 8][tx] = in[(size_t)(y0 + ty + iy * 8) * 512 + x0 + tx];
    __syncthreads();
#pragma unroll
    for (int iy = 0; iy < 4; iy++)
        out[(size_t)(x0 + ty + iy * 8) * 512 + y0 + tx] = t[tx][ty + iy * 8];
}

__global__ void __launch_bounds__(256) comb_bias(
    const float* __restrict__ out_w, const float* __restrict__ out_b,
    const float* __restrict__ cbo, const float* __restrict__ tbo,
    float* __restrict__ bp)
{
    int v = threadIdx.x;
    float s = out_b[v];
    const float* row = out_w + (size_t)v * 1024;
    for (int e = 0; e < 512; e++) s += row[e] * cbo[e] + row[512 + e] * tbo[e];
    bp[v] = s;
}

template <int S>
__global__ void __launch_bounds__(256) attn_kernel(
    const float* __restrict__ q, const float* __restrict__ k,
    const float* __restrict__ v, float* __restrict__ o)
{
    constexpr int TN = S / 16;
    __shared__ union SU {
        struct { float qs[16][64]; float ks[16][S]; } a;
        float vs[S][64];
    } u;
    __shared__ float sc[64][S];

    const int b = blockIdx.x;
    const int tid = threadIdx.x;
    const int ty = tid >> 4, tx = tid & 15;

    float acc[4][TN];
#pragma unroll
    for (int r = 0; r < 4; r++)
#pragma unroll
        for (int j = 0; j < TN; j++) acc[r][j] = 0.f;

    for (int k0 = 0; k0 < Ed; k0 += 16) {
        {
            int r = tid >> 2, c4 = (tid & 3) << 2;
            float4 val = *reinterpret_cast<const float4*>(q + ((size_t)r * Bsz + b) * Ed + k0 + c4);
            u.a.qs[c4+0][r] = val.x; u.a.qs[c4+1][r] = val.y;
            u.a.qs[c4+2][r] = val.z; u.a.qs[c4+3][r] = val.w;
        }
        if (tid < S * 4) {
            int r = tid >> 2, c4 = (tid & 3) << 2;
            float4 val = *reinterpret_cast<const float4*>(k + ((size_t)b * S + r) * Ed + k0 + c4);
            u.a.ks[c4+0][r] = val.x; u.a.ks[c4+1][r] = val.y;
            u.a.ks[c4+2][r] = val.z; u.a.ks[c4+3][r] = val.w;
        }
        __syncthreads();
#pragma unroll
        for (int kk = 0; kk < 16; kk++) {
            float av[4], bv[TN];
#pragma unroll
            for (int r = 0; r < 4; r++) av[r] = u.a.qs[kk][ty * 4 + r];
#pragma unroll
            for (int j = 0; j < TN; j++) bv[j] = u.a.ks[kk][tx * TN + j];
#pragma unroll
            for (int r = 0; r < 4; r++)
#pragma unroll
                for (int j = 0; j < TN; j++) acc[r][j] += av[r] * bv[j];
        }
        __syncthreads();
    }
#pragma unroll
    for (int r = 0; r < 4; r++)
#pragma unroll
        for (int j = 0; j < TN; j++) sc[ty * 4 + r][tx * TN + j] = acc[r][j];
    __syncthreads();

    if (tid < 64) {
        float mx = -3.4e38f;
        for (int s = 0; s < S; s++) mx = fmaxf(mx, sc[tid][s]);
        float sum = 0.f;
        for (int s = 0; s < S; s++) { float e = expf(sc[tid][s] - mx); sc[tid][s] = e; sum += e; }
        float inv = 1.f / sum;
        for (int s = 0; s < S; s++) sc[tid][s] *= inv;
    }
    __syncthreads();

    for (int n0 = 0; n0 < Ed; n0 += 64) {
#pragma unroll
        for (int it = 0; it < (S * 16) / 256; ++it) {
            int f = tid + it * 256;
            int r = f >> 4, c4 = (f & 15) << 2;
            *reinterpret_cast<float4*>(&u.vs[r][c4]) =
                *reinterpret_cast<const float4*>(v + ((size_t)b * S + r) * Ed + n0 + c4);
        }
        __syncthreads();
        float oa[4][4] = {};
        for (int sk = 0; sk < S; sk++) {
            float p[4];
#pragma unroll
            for (int r = 0; r < 4; r++) p[r] = sc[ty * 4 + r][sk];
            float4 vv = *reinterpret_cast<const float4*>(&u.vs[sk][tx * 4]);
            float vf[4] = {vv.x, vv.y, vv.z, vv.w};
#pragma unroll
            for (int r = 0; r < 4; r++)
#pragma unroll
                for (int j = 0; j < 4; j++) oa[r][j] += p[r] * vf[j];
        }
#pragma unroll
        for (int r = 0; r < 4; r++) {
            size_t base = ((size_t)(ty * 4 + r) * Bsz + b) * Ed + n0 + tx * 4;
            *reinterpret_cast<float4*>(&o[base]) = make_float4(oa[r][0], oa[r][1], oa[r][2], oa[r][3]);
        }
        __syncthreads();
    }
}

// ---------------------------------------------------------------------------
// Warp-level exact 1.5-entmax: 1 warp per row, 8 elems/lane in registers,
// barrier-free bitonic sort (register stages + shfl stages), warp-scan cumsum.
// logits (T,B,V) -> out (B,T,V). Block = 8 warps = 8 rows; grid = 4096.
// ---------------------------------------------------------------------------
__global__ void __launch_bounds__(256) entmax_warp(
    const float* __restrict__ logits, float* __restrict__ out)
{
    __shared__ float smw[8][256];
    const int w = threadIdx.x >> 5, lane = threadIdx.x & 31;
    const int row = blockIdx.x * 8 + w;
    const float* lrow = logits + (size_t)row * 256;

    float v[8], zo[8];
    float m = -3.4e38f;
#pragma unroll
    for (int i = 0; i < 8; i++) {
        float z = lrow[lane + 32 * i] * 0.5f;
        zo[i] = z;
        m = fmaxf(m, z);
    }
#pragma unroll
    for (int off = 16; off; off >>= 1) m = fmaxf(m, __shfl_xor_sync(0xffffffffu, m, off));
#pragma unroll
    for (int i = 0; i < 8; i++) { zo[i] -= m; v[i] = -zo[i]; }

    // bitonic ascending sort of v over e = lane + 32*i
#pragma unroll
    for (int k = 2; k <= 256; k <<= 1) {
#pragma unroll
        for (int j = 128; j >= 1; j >>= 1) {
            if (j >= k) continue;
            if (j >= 32) {
                const int d = j >> 5;
#pragma unroll
                for (int i = 0; i < 8; i++) {
                    if ((i & d) == 0) {
                        int i2 = i | d;
                        bool up = (((i << 5) & k) == 0);
                        float a = v[i], b = v[i2];
                        float mn = fminf(a, b), mx = fmaxf(a, b);
                        v[i]  = up ? mn : mx;
                        v[i2] = up ? mx : mn;
                    }
                }
            } else {
#pragma unroll
                for (int i = 0; i < 8; i++) {
                    float pv = __shfl_xor_sync(0xffffffffu, v[i], j);
                    int e = lane + (i << 5);
                    bool up = ((e & k) == 0);
                    bool islow = ((lane & j) == 0);
                    v[i] = (up == islow) ? fminf(v[i], pv) : fmaxf(v[i], pv);
                }
            }
        }
    }

    // zs (descending z) to smem, re-read contiguous per lane
#pragma unroll
    for (int i = 0; i < 8; i++) smw[w][lane + (i << 5)] = -v[i];
    __syncwarp();
    float c[8];
    {
        float4 t0 = *reinterpret_cast<float4*>(&smw[w][lane * 8]);
        float4 t1 = *reinterpret_cast<float4*>(&smw[w][lane * 8 + 4]);
        c[0]=t0.x; c[1]=t0.y; c[2]=t0.z; c[3]=t0.w;
        c[4]=t1.x; c[5]=t1.y; c[6]=t1.z; c[7]=t1.w;
    }
    __syncwarp();

    // inclusive cumsum of c and c^2 over global index g = lane*8 + j
    float s1 = 0.f, s2 = 0.f, p1[8], p2[8];
#pragma unroll
    for (int j = 0; j < 8; j++) { s1 += c[j]; s2 += c[j] * c[j]; p1[j] = s1; p2[j] = s2; }
    float o1 = s1, o2 = s2;
#pragma unroll
    for (int off = 1; off < 32; off <<= 1) {
        float a1 = __shfl_up_sync(0xffffffffu, o1, off);
        float a2 = __shfl_up_sync(0xffffffffu, o2, off);
        if (lane >= off) { o1 += a1; o2 += a2; }
    }
    o1 -= s1; o2 -= s2;  // exclusive offsets

    float tau[8];
    int cnt = 0;
#pragma unroll
    for (int j = 0; j < 8; j++) {
        float cs1 = o1 + p1[j], cs2 = o2 + p2[j];
        float rho = (float)(lane * 8 + j + 1);
        float mean = cs1 / rho, msq = cs2 / rho;
        float ssv = rho * (msq - mean * mean);
        float delta = (1.0f - ssv) / rho;
        float sq = (delta > 0.f) ? sqrtf(delta) : 0.f;
        tau[j] = mean - sq;
        cnt += (tau[j] <= c[j]) ? 1 : 0;
    }
#pragma unroll
    for (int off = 16; off; off >>= 1) cnt += __shfl_xor_sync(0xffffffffu, cnt, off);

    *reinterpret_cast<float4*>(&smw[w][lane * 8])     = make_float4(tau[0], tau[1], tau[2], tau[3]);
    *reinterpret_cast<float4*>(&smw[w][lane * 8 + 4]) = make_float4(tau[4], tau[5], tau[6], tau[7]);
    __syncwarp();
    float tau_star = smw[w][cnt - 1];

    int t = row >> 9, b = row & 511;
    float* orow = out + ((size_t)b * Tc + t) * 256;
#pragma unroll
    for (int i = 0; i < 8; i++) {
        float y = fmaxf(zo[i] - tau_star, 0.f);
        orow[lane + (i << 5)] = y * y;
    }
}

extern "C" void kernel_launch(void* const* d_in, const int* in_sizes, int n_in,
                              void* d_out, int out_size)
{
    const float* char_enc = (const float*)d_in[0];
    const float* char_hn0 = (const float*)d_in[1];
    const float* char_cn0 = (const float*)d_in[2];
    const float* tag_enc  = (const float*)d_in[3];
    const float* tag_hn0  = (const float*)d_in[4];
    const float* tag_cn0  = (const float*)d_in[5];
    const float* tos      = (const float*)d_in[6];
    const float* w_ih     = (const float*)d_in[7];
    const float* w_hh     = (const float*)d_in[8];
    const float* b_ih     = (const float*)d_in[9];
    const float* b_hh     = (const float*)d_in[10];
    const float* cwq = (const float*)d_in[11];
    const float* cwk = (const float*)d_in[12];
    const float* cwv = (const float*)d_in[13];
    const float* cbq = (const float*)d_in[14];
    const float* cbk = (const float*)d_in[15];
    const float* cbv = (const float*)d_in[16];
    const float* cwo = (const float*)d_in[17];
    const float* cbo = (const float*)d_in[18];
    const float* twq = (const float*)d_in[19];
    const float* twk = (const float*)d_in[20];
    const float* twv = (const float*)d_in[21];
    const float* tbq = (const float*)d_in[22];
    const float* tbk = (const float*)d_in[23];
    const float* tbv = (const float*)d_in[24];
    const float* two_ = (const float*)d_in[25];
    const float* tbo = (const float*)d_in[26];
    const float* out_w = (const float*)d_in[27];
    const float* out_b = (const float*)d_in[28];
    float* out = (float*)d_out;

    float *xg, *h0, *c0, *hs, *qc, *kc, *vc, *qt, *kt, *vt, *oc, *ot, *lg;
    float *bias2, *Wc, *Wt, *cwoT, *twoT, *bcomb;
    cudaGetSymbolAddress((void**)&xg,    g_xgates);
    cudaGetSymbolAddress((void**)&h0,    g_h0);
    cudaGetSymbolAddress((void**)&c0,    g_c);
    cudaGetSymbolAddress((void**)&hs,    g_hs);
    cudaGetSymbolAddress((void**)&qc,    g_qc);
    cudaGetSymbolAddress((void**)&kc,    g_kc);
    cudaGetSymbolAddress((void**)&vc,    g_vc);
    cudaGetSymbolAddress((void**)&qt,    g_qt);
    cudaGetSymbolAddress((void**)&kt,    g_kt);
    cudaGetSymbolAddress((void**)&vt,    g_vt);
    cudaGetSymbolAddress((void**)&oc,    g_oc);
    cudaGetSymbolAddress((void**)&ot,    g_ot);
    cudaGetSymbolAddress((void**)&lg,    g_lg);
    cudaGetSymbolAddress((void**)&bias2, g_bias2);
    cudaGetSymbolAddress((void**)&Wc,    g_Wc);
    cudaGetSymbolAddress((void**)&Wt,    g_Wt);
    cudaGetSymbolAddress((void**)&cwoT,  g_cwoT);
    cudaGetSymbolAddress((void**)&twoT,  g_twoT);
    cudaGetSymbolAddress((void**)&bcomb, g_bcomb);

    __nv_bfloat16 *whhH, *whhL, *wihH, *wihL, *cwkH, *cwkL, *cwvH, *cwvL, *cwqH, *cwqL;
    __nv_bfloat16 *twkH, *twkL, *twvH, *twvL, *twqH, *twqL, *WcH, *WcL, *WtH, *WtL;
    cudaGetSymbolAddress((void**)&whhH, g_whhH); cudaGetSymbolAddress((void**)&whhL, g_whhL);
    cudaGetSymbolAddress((void**)&wihH, g_wihH); cudaGetSymbolAddress((void**)&wihL, g_wihL);
    cudaGetSymbolAddress((void**)&cwkH, g_cwkH); cudaGetSymbolAddress((void**)&cwkL, g_cwkL);
    cudaGetSymbolAddress((void**)&cwvH, g_cwvH); cudaGetSymbolAddress((void**)&cwvL, g_cwvL);
    cudaGetSymbolAddress((void**)&cwqH, g_cwqH); cudaGetSymbolAddress((void**)&cwqL, g_cwqL);
    cudaGetSymbolAddress((void**)&twkH, g_twkH); cudaGetSymbolAddress((void**)&twkL, g_twkL);
    cudaGetSymbolAddress((void**)&twvH, g_twvH); cudaGetSymbolAddress((void**)&twvL, g_twvL);
    cudaGetSymbolAddress((void**)&twqH, g_twqH); cudaGetSymbolAddress((void**)&twqL, g_twqL);
    cudaGetSymbolAddress((void**)&WcH,  g_WcH);  cudaGetSymbolAddress((void**)&WcL,  g_WcL);
    cudaGetSymbolAddress((void**)&WtH,  g_WtH);  cudaGetSymbolAddress((void**)&WtL,  g_WtL);

    const float qscale = 1.0f / sqrtf(512.0f);
    const int smem_g = 30720 * 4;   // 122880

    cudaFuncSetAttribute(mma_gemm2<0>, cudaFuncAttributeMaxDynamicSharedMemorySize, smem_g);
    cudaFuncSetAttribute(mma_gemm2<1>, cudaFuncAttributeMaxDynamicSharedMemorySize, smem_g);
    cudaFuncSetAttribute(mma_gemm2<2>, cudaFuncAttributeMaxDynamicSharedMemorySize, smem_g);
    cudaFuncSetAttribute(lstm_persist, cudaFuncAttributeMaxDynamicSharedMemorySize, LP_SMEM_BYTES);

    // 1-3: conversions needed by the first GEMMs
    conv_split_k<<<2048, 256>>>(w_ih, wihH, wihL, 524288);
    conv_split_k<<<1024, 256>>>(cwk, cwkH, cwkL, 262144);
    conv_split_k<<<1024, 256>>>(cwv, cwvH, cwvL, 262144);

    // 4-6: big tensor GEMMs early (ncu capture targets)
    mma_gemm2<1><<<dim3(16, 128), 512, smem_g>>>(xg, tos, nullptr, wihH, wihL, nullptr, nullptr,
                                                 nullptr, 32768, 2048, 256, 256, 256, 1.0f);
    mma_gemm2<0><<<dim3(4, 128), 512, smem_g>>>(kc, char_enc, nullptr, cwkH, cwkL, nullptr, nullptr,
                                                cbk, 32768, 512, 512, 512, 512, 1.0f);
    mma_gemm2<0><<<dim3(4, 128), 512, smem_g>>>(vc, char_enc, nullptr, cwvH, cwvL, nullptr, nullptr,
                                                cbv, 32768, 512, 512, 512, 512, 1.0f);

    // small precomputes
    init_h0c0<<<1024, 256>>>(char_hn0, tag_hn0, char_cn0, tag_cn0, h0, c0);
    bias_add2048<<<8, 256>>>(b_ih, b_hh, bias2);
    transpose512<<<dim3(16, 16), 256>>>(cwo, cwoT);
    transpose512<<<dim3(16, 16), 256>>>(two_, twoT);
    comb_bias<<<1, 256>>>(out_w, out_b, cbo, tbo, bcomb);

    // folded head weights (fp32), then convert
    gemm3<<<dim3(8, 2), 256>>>(Wc, out_w,       cwoT, 256, 512, 512, 1024);
    gemm3<<<dim3(8, 2), 256>>>(Wt, out_w + 512, twoT, 256, 512, 512, 1024);

    // remaining weight conversions
    conv_split_k<<<4096, 256>>>(w_hh, whhH, whhL, 1048576);
    conv_split_k<<<1024, 256>>>(cwq, cwqH, cwqL, 262144);
    conv_split_k<<<1024, 256>>>(twk, twkH, twkL, 262144);
    conv_split_k<<<1024, 256>>>(twv, twvH, twvL, 262144);
    conv_split_k<<<1024, 256>>>(twq, twqH, twqL, 262144);
    conv_split_k<<<512, 256>>>(Wc, WcH, WcL, 131072);
    conv_split_k<<<512, 256>>>(Wt, WtH, WtL, 131072);

    // tag-side projections
    mma_gemm2<0><<<dim3(4, 32), 512, smem_g>>>(kt, tag_enc, nullptr, twkH, twkL, nullptr, nullptr,
                                               tbk, 8192, 512, 512, 512, 512, 1.0f);
    mma_gemm2<0><<<dim3(4, 32), 512, smem_g>>>(vt, tag_enc, nullptr, twvH, twvL, nullptr, nullptr,
                                               tbv, 8192, 512, 512, 512, 512, 1.0f);

    // persistent LSTM (one launch, 128 CTAs, internal 64-step loop)
    lstm_persist<<<dim3(32, 4), 256, LP_SMEM_BYTES>>>(h0, whhH, whhL, xg, bias2, c0, hs);

    // q projections
    mma_gemm2<0><<<dim3(4, 128), 512, smem_g>>>(qc, hs, nullptr, cwqH, cwqL, nullptr, nullptr,
                                                cbq, 32768, 512, 512, 512, 512, qscale);
    mma_gemm2<0><<<dim3(4, 128), 512, smem_g>>>(qt, hs, nullptr, twqH, twqL, nullptr, nullptr,
                                                tbq, 32768, 512, 512, 512, 512, qscale);

    // attention
    attn_kernel<64><<<512, 256>>>(qc, kc, vc, oc);
    attn_kernel<16><<<512, 256>>>(qt, kt, vt, ot);

    // logits = oc @ Wc^T + ot @ Wt^T + bcomb (concat GEMM, K=1024)
    mma_gemm2<2><<<dim3(2, 128), 512, smem_g>>>(lg, oc, ot, WcH, WcL, WtH, WtL,
                                                bcomb, 32768, 256, 1024, 512, 512, 1.0f);

    // warp-level entmax + transpose to (B,T,V)
    entmax_warp<<<4096, 256>>>(lg, out);
}

// round 16
// speedup vs baseline: 1.0901x; 1.0120x over previous
#include <cuda_runtime.h>
#include <cuda_bf16.h>
#include <math.h>
#include <stdint.h>

#define Bsz 512
#define Tc  64
#define Ed  512
#define Vd  256

__device__ float g_xgates[67108864];   // (T,B,4E)
__device__ float g_h0    [262144];
__device__ float g_c     [262144];
__device__ float g_hs    [16777216];   // (T,B,E)
__device__ float g_qc    [16777216];
__device__ float g_kc    [16777216];
__device__ float g_vc    [16777216];
__device__ float g_qt    [16777216];
__device__ float g_kt    [4194304];
__device__ float g_vt    [4194304];
__device__ float g_oc    [16777216];
__device__ float g_ot    [16777216];
__device__ float g_lg    [8388608];    // (T,B,V)
__device__ float g_bias2 [2048];
__device__ float g_Wc    [131072];     // (V,E)
__device__ float g_Wt    [131072];
__device__ float g_cwoT  [262144];
__device__ float g_twoT  [262144];
__device__ float g_bcomb [256];

__device__ __nv_bfloat16 g_whhH[1048576], g_whhL[1048576];
__device__ __nv_bfloat16 g_wihH[524288],  g_wihL[524288];
__device__ __nv_bfloat16 g_cwkH[262144],  g_cwkL[262144];
__device__ __nv_bfloat16 g_cwvH[262144],  g_cwvL[262144];
__device__ __nv_bfloat16 g_cwqH[262144],  g_cwqL[262144];
__device__ __nv_bfloat16 g_twkH[262144],  g_twkL[262144];
__device__ __nv_bfloat16 g_twvH[262144],  g_twvL[262144];
__device__ __nv_bfloat16 g_twqH[262144],  g_twqL[262144];
__device__ __nv_bfloat16 g_WcH[131072],   g_WcL[131072];
__device__ __nv_bfloat16 g_WtH[131072],   g_WtL[131072];

__device__ unsigned g_cnt;
__device__ volatile unsigned g_epoch;

// ======================= helpers ===========================================
__device__ __forceinline__ void ffma2(unsigned long long& d, unsigned long long a,
                                      unsigned long long b) {
    asm("fma.rn.f32x2 %0, %1, %2, %0;" : "+l"(d) : "l"(a), "l"(b));
}
__device__ __forceinline__ unsigned long long pack2(float x, float y) {
    unsigned long long r;
    asm("mov.b64 %0, {%1, %2};" : "=l"(r) : "r"(__float_as_uint(x)), "r"(__float_as_uint(y)));
    return r;
}
__device__ __forceinline__ void unpack2(unsigned long long d, float& lo, float& hi) {
    unsigned int l, h;
    asm("mov.b64 {%0, %1}, %2;" : "=r"(l), "=r"(h) : "l"(d));
    lo = __uint_as_float(l); hi = __uint_as_float(h);
}
__device__ __forceinline__ float sigmoidf_(float x) { return 1.0f / (1.0f + expf(-x)); }

__device__ __forceinline__ void mma16816(float* c, const uint32_t* a, uint32_t b0, uint32_t b1) {
    asm volatile(
        "mma.sync.aligned.m16n8k16.row.col.f32.bf16.bf16.f32 "
        "{%0,%1,%2,%3}, {%4,%5,%6,%7}, {%8,%9}, {%0,%1,%2,%3};"
        : "+f"(c[0]), "+f"(c[1]), "+f"(c[2]), "+f"(c[3])
        : "r"(a[0]), "r"(a[1]), "r"(a[2]), "r"(a[3]), "r"(b0), "r"(b1));
}
__device__ __forceinline__ void ldsm_x4(uint32_t* r, uint32_t addr) {
    asm volatile("ldmatrix.sync.aligned.m8n8.x4.shared.b16 {%0,%1,%2,%3}, [%4];"
                 : "=r"(r[0]), "=r"(r[1]), "=r"(r[2]), "=r"(r[3]) : "r"(addr));
}
__device__ __forceinline__ void ldsm_x2(uint32_t& r0, uint32_t& r1, uint32_t addr) {
    asm volatile("ldmatrix.sync.aligned.m8n8.x2.shared.b16 {%0,%1}, [%2];"
                 : "=r"(r0), "=r"(r1) : "r"(addr));
}
__device__ __forceinline__ void cvt_split4(float4 v, uint2& hi, uint2& lo) {
    __nv_bfloat16 h0 = __float2bfloat16(v.x), h1 = __float2bfloat16(v.y);
    __nv_bfloat16 h2 = __float2bfloat16(v.z), h3 = __float2bfloat16(v.w);
    __nv_bfloat16 l0 = __float2bfloat16(v.x - __bfloat162float(h0));
    __nv_bfloat16 l1 = __float2bfloat16(v.y - __bfloat162float(h1));
    __nv_bfloat16 l2 = __float2bfloat16(v.z - __bfloat162float(h2));
    __nv_bfloat16 l3 = __float2bfloat16(v.w - __bfloat162float(h3));
    hi.x = (uint32_t)__bfloat16_as_ushort(h0) | ((uint32_t)__bfloat16_as_ushort(h1) << 16);
    hi.y = (uint32_t)__bfloat16_as_ushort(h2) | ((uint32_t)__bfloat16_as_ushort(h3) << 16);
    lo.x = (uint32_t)__bfloat16_as_ushort(l0) | ((uint32_t)__bfloat16_as_ushort(l1) << 16);
    lo.y = (uint32_t)__bfloat16_as_ushort(l2) | ((uint32_t)__bfloat16_as_ushort(l3) << 16);
}
__device__ __forceinline__ void conv_one(const float* s, __nv_bfloat16* h,
                                         __nv_bfloat16* l, int i) {
    float v = s[i];
    __nv_bfloat16 hv = __float2bfloat16(v);
    h[i] = hv;
    l[i] = __float2bfloat16(v - __bfloat162float(hv));
}

// merged conversion of the 8 input weight matrices (one launch)
__global__ void __launch_bounds__(256) conv_all(
    const float* wih, const float* cwk, const float* cwv, const float* cwq,
    const float* twk, const float* twv, const float* twq, const float* whh,
    __nv_bfloat16* wihH, __nv_bfloat16* wihL,
    __nv_bfloat16* cwkH, __nv_bfloat16* cwkL,
    __nv_bfloat16* cwvH, __nv_bfloat16* cwvL,
    __nv_bfloat16* cwqH, __nv_bfloat16* cwqL,
    __nv_bfloat16* twkH, __nv_bfloat16* twkL,
    __nv_bfloat16* twvH, __nv_bfloat16* twvL,
    __nv_bfloat16* twqH, __nv_bfloat16* twqL,
    __nv_bfloat16* whhH, __nv_bfloat16* whhL)
{
    int i = blockIdx.x * 256 + threadIdx.x;    // grid covers 3145728
    if (i < 524288)        conv_one(wih, wihH, wihL, i);
    else if (i < 786432)   conv_one(cwk, cwkH, cwkL, i - 524288);
    else if (i < 1048576)  conv_one(cwv, cwvH, cwvL, i - 786432);
    else if (i < 1310720)  conv_one(cwq, cwqH, cwqL, i - 1048576);
    else if (i < 1572864)  conv_one(twk, twkH, twkL, i - 1310720);
    else if (i < 1835008)  conv_one(twv, twvH, twvL, i - 1572864);
    else if (i < 2097152)  conv_one(twq, twqH, twqL, i - 1835008);
    else                   conv_one(whh, whhH, whhL, i - 2097152);
}

__global__ void __launch_bounds__(256) conv2(
    const float* Wc, const float* Wt,
    __nv_bfloat16* WcH, __nv_bfloat16* WcL,
    __nv_bfloat16* WtH, __nv_bfloat16* WtL)
{
    int i = blockIdx.x * 256 + threadIdx.x;    // grid covers 262144
    if (i < 131072) conv_one(Wc, WcH, WcL, i);
    else            conv_one(Wt, WtH, WtL, i - 131072);
}

// ---------------------------------------------------------------------------
// mma.sync GEMM (NT), CTA 256x128, 512 threads / 16 warps (4m x 4n),
// warp tile 64x32, K-chunk 32. Plane-major MMA order (dep distance 8).
// ---------------------------------------------------------------------------
template <int MODE>
__global__ void __launch_bounds__(512) mma_gemm2(
    float* __restrict__ C, const float* __restrict__ A, const float* __restrict__ A2,
    const __nv_bfloat16* __restrict__ BH, const __nv_bfloat16* __restrict__ BL,
    const __nv_bfloat16* __restrict__ BH2, const __nv_bfloat16* __restrict__ BL2,
    const float* __restrict__ bias, int M, int N, int K, int lda, int ldb, float alpha)
{
    extern __shared__ uint32_t sm[];

    const int tid  = threadIdx.x;
    const int lane = tid & 31, wid = tid >> 5;
    const int wm = wid >> 2, wn = wid & 3;
    const int m0 = blockIdx.y * 256, n0 = blockIdx.x * 128;
    const int gq = lane >> 2, pl = lane & 3;

    const uint32_t sb4 = (uint32_t)__cvta_generic_to_shared(sm);
    const int arow  = (lane & 7) + ((lane >> 3) & 1) * 8;
    const int akoff = (lane >> 4) * 4;
    const int brow  = lane & 7;
    const int bkoff = ((lane >> 3) & 1) * 4;

    float c[4][4][4];
#pragma unroll
    for (int i = 0; i < 4; i++)
#pragma unroll
        for (int j = 0; j < 4; j++)
#pragma unroll
            for (int q = 0; q < 4; q++) c[i][j][q] = 0.f;

    float4 avr[4];
    uint4 bhr, blr;

    auto gload = [&](int ch) {
        const float* Ae = A;
        const __nv_bfloat16 *bh = BH, *bl = BL;
        int k0 = ch << 5;
        if (MODE == 2 && k0 >= 512) { Ae = A2; bh = BH2; bl = BL2; k0 -= 512; }
#pragma unroll
        for (int i = 0; i < 4; i++) {
            int f = tid + i * 512, r = f >> 3, cq = f & 7;
            if constexpr (MODE == 1) {
                int gm = m0 + r, tt = gm >> 9, bb = gm & 511;
                avr[i] = tt ? *reinterpret_cast<const float4*>(Ae + (size_t)bb * 16384 + tt * 256 + k0 + cq * 4)
                            : make_float4(0.f, 0.f, 0.f, 0.f);
            } else {
                avr[i] = *reinterpret_cast<const float4*>(Ae + (size_t)(m0 + r) * lda + k0 + cq * 4);
            }
        }
        {
            int r = tid >> 2, cq = tid & 3;
            bhr = *reinterpret_cast<const uint4*>(bh + (size_t)(n0 + r) * ldb + k0 + cq * 8);
            blr = *reinterpret_cast<const uint4*>(bl + (size_t)(n0 + r) * ldb + k0 + cq * 8);
        }
    };
    auto sstore = [&](int buf) {
        const int ab = buf * 5120;
#pragma unroll
        for (int i = 0; i < 4; i++) {
            int f = tid + i * 512, r = f >> 3, cq = f & 7;
            uint2 hi, lo;
            cvt_split4(avr[i], hi, lo);
            int idx = ab + r * 20 + cq * 2;
            *reinterpret_cast<uint2*>(&sm[idx])         = hi;
            *reinterpret_cast<uint2*>(&sm[10240 + idx]) = lo;
        }
        {
            int r = tid >> 2, cq = tid & 3;
            int idx = buf * 2560 + r * 20 + cq * 4;
            *reinterpret_cast<uint4*>(&sm[20480 + idx]) = bhr;
            *reinterpret_cast<uint4*>(&sm[25600 + idx]) = blr;
        }
    };

    const int nch = K >> 5;
    gload(0);
    sstore(0);
    __syncthreads();

    for (int ch = 0; ch < nch; ch++) {
        const int buf = ch & 1;
        const bool more = (ch + 1 < nch);
        if (more) gload(ch + 1);
        const int ab = buf * 5120;
        const int bb = buf * 2560;
#pragma unroll
        for (int s = 0; s < 2; s++) {
            uint32_t bh0[4], bh1[4], bl0[4], bl1[4];
#pragma unroll
            for (int nf = 0; nf < 4; nf++) {
                uint32_t baddr = sb4 + 4u * (uint32_t)(20480 + bb + (wn * 32 + nf * 8 + brow) * 20 + s * 8 + bkoff);
                ldsm_x2(bh0[nf], bh1[nf], baddr);
                ldsm_x2(bl0[nf], bl1[nf], baddr + 5120u * 4u);
            }
#pragma unroll
            for (int mp = 0; mp < 2; mp++) {
                const int mf0 = mp * 2, mf1 = mp * 2 + 1;
                uint32_t a0[4], a1[4];
                uint32_t aaddr0 = sb4 + 4u * (uint32_t)(ab + (wm * 64 + mf0 * 16 + arow) * 20 + s * 8 + akoff);
                uint32_t aaddr1 = sb4 + 4u * (uint32_t)(ab + (wm * 64 + mf1 * 16 + arow) * 20 + s * 8 + akoff);
                ldsm_x4(a0, aaddr0);
                ldsm_x4(a1, aaddr1);
#pragma unroll
                for (int nf = 0; nf < 4; nf++) mma16816(c[mf0][nf], a0, bh0[nf], bh1[nf]);
#pragma unroll
                for (int nf = 0; nf < 4; nf++) mma16816(c[mf1][nf], a1, bh0[nf], bh1[nf]);
#pragma unroll
                for (int nf = 0; nf < 4; nf++) mma16816(c[mf0][nf], a0, bl0[nf], bl1[nf]);
#pragma unroll
                for (int nf = 0; nf < 4; nf++) mma16816(c[mf1][nf], a1, bl0[nf], bl1[nf]);
                ldsm_x4(a0, aaddr0 + 10240u * 4u);
                ldsm_x4(a1, aaddr1 + 10240u * 4u);
#pragma unroll
                for (int nf = 0; nf < 4; nf++) mma16816(c[mf0][nf], a0, bh0[nf], bh1[nf]);
#pragma unroll
                for (int nf = 0; nf < 4; nf++) mma16816(c[mf1][nf], a1, bh0[nf], bh1[nf]);
            }
        }
        if (more) {
            sstore(buf ^ 1);
            __syncthreads();
        }
    }

#pragma unroll
    for (int mf = 0; mf < 4; mf++) {
#pragma unroll
        for (int nf = 0; nf < 4; nf++) {
            int r  = m0 + wm * 64 + mf * 16 + gq;
            int cc = n0 + wn * 32 + nf * 8 + pl * 2;
            float b0 = 0.f, b1 = 0.f;
            if (bias) { b0 = bias[cc]; b1 = bias[cc + 1]; }
            *reinterpret_cast<float2*>(&C[(size_t)r * N + cc]) =
                make_float2(alpha * (c[mf][nf][0] + b0), alpha * (c[mf][nf][1] + b1));
            *reinterpret_cast<float2*>(&C[(size_t)(r + 8) * N + cc]) =
                make_float2(alpha * (c[mf][nf][2] + b0), alpha * (c[mf][nf][3] + b1));
        }
    }
}

// ---------------------------------------------------------------------------
// Persistent LSTM, K-chunk 64 (half the syncs vs R15). R12 MMA order.
// smem u32: BH 0..16640, BL 16640..33280, A 33280 (2 bufs x (hi 5120 + lo 5120)).
// ---------------------------------------------------------------------------
#define LP_BH 0
#define LP_BL 16640
#define LP_A  33280
#define LP_SMEM_BYTES (53760 * 4)

__device__ __forceinline__ void grid_barrier128(int tid) {
    __threadfence();
    __syncthreads();
    if (tid == 0) {
        unsigned e = g_epoch;
        if (atomicAdd(&g_cnt, 1u) == 127u) {
            g_cnt = 0;
            __threadfence();
            g_epoch = e + 1;
        } else {
            while (g_epoch == e) { }
        }
    }
    __syncthreads();
}

__global__ void __launch_bounds__(256) lstm_persist(
    const float* __restrict__ h0,
    const __nv_bfloat16* __restrict__ whhH, const __nv_bfloat16* __restrict__ whhL,
    const float* __restrict__ xg, const float* __restrict__ bias2,
    const float* __restrict__ c0, float* __restrict__ hs)
{
    extern __shared__ uint32_t sm[];
    const int tid  = threadIdx.x;
    const int lane = tid & 31, wid = tid >> 5;
    const int wm = wid >> 2, wn = wid & 3;
    const int e0 = blockIdx.x * 16;
    const int m0 = blockIdx.y * 128;
    const int gq = lane >> 2, pl = lane & 3;

    const uint32_t sb4 = (uint32_t)__cvta_generic_to_shared(sm);
    const int arow  = (lane & 7) + ((lane >> 3) & 1) * 8;
    const int akoff = (lane >> 4) * 4;
    const int brow  = lane & 7;
    const int bkoff = ((lane >> 3) & 1) * 4;

#pragma unroll
    for (int i = 0; i < 16; i++) {
        int f = tid + i * 256;
        int r = f >> 6, q = f & 63;
        int gr = (r >> 4) * 512 + e0 + (r & 15);
        *reinterpret_cast<uint4*>(&sm[LP_BH + r * 260 + q * 4]) =
            *reinterpret_cast<const uint4*>(whhH + (size_t)gr * 512 + q * 8);
        *reinterpret_cast<uint4*>(&sm[LP_BL + r * 260 + q * 4]) =
            *reinterpret_cast<const uint4*>(whhL + (size_t)gr * 512 + q * 8);
    }

    float creg[8];
#pragma unroll
    for (int ir = 0; ir < 8; ir++) {
        int idx = tid + ir * 256;
        int row = idx >> 4, e = idx & 15;
        creg[ir] = c0[(size_t)(m0 + row) * 512 + e0 + e];
    }
    __syncthreads();

    for (int t = 0; t < 64; t++) {
        const float* hprev = (t == 0) ? h0 : (hs + (size_t)(t - 1) * 262144);
        const float* xg_t  = xg + (size_t)t * 1048576;
        float* hout        = hs + (size_t)t * 262144;

        float c[4][2][4];
#pragma unroll
        for (int i = 0; i < 4; i++)
#pragma unroll
            for (int j = 0; j < 2; j++)
#pragma unroll
                for (int q = 0; q < 4; q++) c[i][j][q] = 0.f;

        float4 avr[8];
        auto gloadA = [&](int ch) {     // 64-k chunk: 128 rows x 64 floats
            int k0 = ch << 6;
#pragma unroll
            for (int i = 0; i < 8; i++) {
                int f = tid + i * 256, r = f >> 4, cq = f & 15;
                avr[i] = *reinterpret_cast<const float4*>(hprev + (size_t)(m0 + r) * 512 + k0 + cq * 4);
            }
        };
        auto sstoreA = [&](int buf) {
            const int base = LP_A + buf * 10240;
#pragma unroll
            for (int i = 0; i < 8; i++) {
                int f = tid + i * 256, r = f >> 4, cq = f & 15;
                uint2 hi, lo;
                cvt_split4(avr[i], hi, lo);
                int idx = base + (cq >> 3) * 2560 + r * 20 + (cq & 7) * 2;
                *reinterpret_cast<uint2*>(&sm[idx])        = hi;
                *reinterpret_cast<uint2*>(&sm[5120 + idx]) = lo;
            }
        };

        gloadA(0);
        sstoreA(0);
        __syncthreads();

        for (int ch = 0; ch < 8; ch++) {
            const int buf = ch & 1;
            const bool more = (ch < 7);
            if (more) gloadA(ch + 1);
#pragma unroll
            for (int sub = 0; sub < 2; sub++) {
                const int chh = ch * 2 + sub;
                const int ab = LP_A + buf * 10240 + sub * 2560;
#pragma unroll
                for (int s = 0; s < 2; s++) {
                    uint32_t ah[4][4], al4[4][4];
#pragma unroll
                    for (int mf = 0; mf < 4; mf++) {
                        uint32_t addr = sb4 + 4u * (uint32_t)(ab + (wm * 64 + mf * 16 + arow) * 20 + s * 8 + akoff);
                        ldsm_x4(ah[mf], addr);
                        ldsm_x4(al4[mf], addr + 5120u * 4u);
                    }
#pragma unroll
                    for (int nf = 0; nf < 2; nf++) {
                        uint32_t baddr = sb4 + 4u * (uint32_t)((wn * 16 + nf * 8 + brow) * 260 + chh * 16 + s * 8 + bkoff);
                        uint32_t bh0, bh1, bl0, bl1;
                        ldsm_x2(bh0, bh1, baddr + LP_BH * 4u);
                        ldsm_x2(bl0, bl1, baddr + LP_BL * 4u);
#pragma unroll
                        for (int mf = 0; mf < 4; mf++) {
                            mma16816(c[mf][nf], ah[mf], bh0, bh1);
                            mma16816(c[mf][nf], ah[mf], bl0, bl1);
                            mma16816(c[mf][nf], al4[mf], bh0, bh1);
                        }
                    }
                }
            }
            if (more) {
                sstoreA(buf ^ 1);
                __syncthreads();
            }
        }

        __syncthreads();
        float* Gs = reinterpret_cast<float*>(&sm[LP_A]);
#pragma unroll
        for (int mf = 0; mf < 4; mf++) {
#pragma unroll
            for (int nf = 0; nf < 2; nf++) {
                int rr = wm * 64 + mf * 16 + gq;
                int cc = wn * 16 + nf * 8 + pl * 2;
                Gs[rr * 64 + cc]           = c[mf][nf][0];
                Gs[rr * 64 + cc + 1]       = c[mf][nf][1];
                Gs[(rr + 8) * 64 + cc]     = c[mf][nf][2];
                Gs[(rr + 8) * 64 + cc + 1] = c[mf][nf][3];
            }
        }
        __syncthreads();

#pragma unroll
        for (int ir = 0; ir < 8; ir++) {
            int idx = tid + ir * 256;
            int row = idx >> 4, e = idx & 15;
            int b = m0 + row, ni = e0 + e;
            const float* xr = xg_t + (size_t)b * 2048;
            float gi = Gs[row * 64 + e]      + bias2[ni]        + xr[ni];
            float gf = Gs[row * 64 + 16 + e] + bias2[ni + 512]  + xr[ni + 512];
            float gg = Gs[row * 64 + 32 + e] + bias2[ni + 1024] + xr[ni + 1024];
            float go = Gs[row * 64 + 48 + e] + bias2[ni + 1536] + xr[ni + 1536];
            float cc2 = sigmoidf_(gf) * creg[ir] + sigmoidf_(gi) * tanhf(gg);
            creg[ir] = cc2;
            hout[(size_t)b * 512 + ni] = sigmoidf_(go) * tanhf(cc2);
        }

        if (t < 63) grid_barrier128(tid);
    }
}

// ======================= SIMT gemm (Wc/Wt precompute only) ==================
__global__ void __launch_bounds__(256) gemm3(
    float* __restrict__ C, const float* __restrict__ A,
    const float* __restrict__ Bw, int M, int N, int K, int lda)
{
    __shared__ float As[2][16][128];
    __shared__ float Bs[2][16][64];

    const int tid = threadIdx.x;
    const int m0  = blockIdx.y * 128;
    const int n0  = blockIdx.x * 64;
    const int ty  = tid >> 4;
    const int tx  = tid & 15;
    const int r0 = tid >> 2;
    const int r1 = r0 + 64;
    const int c4 = (tid & 3) << 2;

    float4 pa0, pa1, pb;
    auto loadG = [&](int k0) {
        int gk = k0 + c4;
        pa0 = *reinterpret_cast<const float4*>(A + (size_t)(m0 + r0) * lda + gk);
        pa1 = *reinterpret_cast<const float4*>(A + (size_t)(m0 + r1) * lda + gk);
        pb = *reinterpret_cast<const float4*>(Bw + (size_t)(n0 + r0) * K + gk);
    };
    auto storeS = [&](int buf) {
        As[buf][c4 + 0][r0] = pa0.x; As[buf][c4 + 1][r0] = pa0.y;
        As[buf][c4 + 2][r0] = pa0.z; As[buf][c4 + 3][r0] = pa0.w;
        As[buf][c4 + 0][r1] = pa1.x; As[buf][c4 + 1][r1] = pa1.y;
        As[buf][c4 + 2][r1] = pa1.z; As[buf][c4 + 3][r1] = pa1.w;
        Bs[buf][c4 + 0][r0] = pb.x;  Bs[buf][c4 + 1][r0] = pb.y;
        Bs[buf][c4 + 2][r0] = pb.z;  Bs[buf][c4 + 3][r0] = pb.w;
    };

    unsigned long long acc[4][4];
#pragma unroll
    for (int i = 0; i < 4; i++)
#pragma unroll
        for (int j = 0; j < 4; j++) acc[i][j] = 0ull;

    loadG(0); storeS(0); __syncthreads();

    const int nt = K >> 4;
    for (int kt = 0; kt < nt; kt++) {
        const int cur = kt & 1;
        if (kt + 1 < nt) loadG((kt + 1) << 4);
#pragma unroll
        for (int kk = 0; kk < 16; ++kk) {
            const ulonglong2* ap = reinterpret_cast<const ulonglong2*>(&As[cur][kk][ty * 8]);
            ulonglong2 u0 = ap[0], u1 = ap[1];
            unsigned long long a2[4] = {u0.x, u0.y, u1.x, u1.y};
            float4 b = *reinterpret_cast<const float4*>(&Bs[cur][kk][tx * 4]);
            unsigned long long bd[4] = {pack2(b.x, b.x), pack2(b.y, b.y),
                                        pack2(b.z, b.z), pack2(b.w, b.w)};
#pragma unroll
            for (int i = 0; i < 4; i++)
#pragma unroll
                for (int j = 0; j < 4; j++) ffma2(acc[i][j], a2[i], bd[j]);
        }
        if (kt + 1 < nt) { storeS(cur ^ 1); __syncthreads(); }
    }

#pragma unroll
    for (int i = 0; i < 4; i++) {
        const int gm = m0 + ty * 8 + 2 * i;
#pragma unroll
        for (int j = 0; j < 4; j++) {
            float lo, hi;
            unpack2(acc[i][j], lo, hi);
            const int gn = n0 + tx * 4 + j;
            C[(size_t)gm * N + gn]       = lo;
            C[(size_t)(gm + 1) * N + gn] = hi;
        }
    }
}

__global__ void __launch_bounds__(256) init_h0c0(
    const float* __restrict__ chn, const float* __restrict__ thn,
    const float* __restrict__ ccn, const float* __restrict__ tcn,
    float* __restrict__ h0, float* __restrict__ c0)
{
    int idx = blockIdx.x * 256 + threadIdx.x;
    int bb = idx >> 9, e = idx & 511;
    h0[idx] = (e < 256) ? chn[bb * 256 + e] : thn[bb * 256 + e - 256];
    c0[idx] = (e < 256) ? ccn[bb * 256 + e] : tcn[bb * 256 + e - 256];
}

__global__ void __launch_bounds__(256) bias_add2048(
    const float* __restrict__ a, const float* __restrict__ b, float* __restrict__ o)
{
    int i = blockIdx.x * 256 + threadIdx.x;
    o[i] = a[i] + b[i];
}

__global__ void __launch_bounds__(256) transpose512(
    const float* __restrict__ in, float* __restrict__ out)
{
    __shared__ float t[32][33];
    int tx = threadIdx.x & 31, ty = threadIdx.x >> 5;
    int x0 = blockIdx.x * 32, y0 = blockIdx.y * 32;
#pragma unroll
    for (int iy = 0; iy < 4; iy++)
        t[ty + iy * 8][tx] = in[(size_t)(y0 + ty + iy * 8) * 512 + x0 + tx];
    __syncthreads();
#pragma unroll
    for (int iy = 0; iy < 4; iy++)
        out[(size_t)(x0 + ty + iy * 8) * 512 + y0 + tx] = t[tx][ty + iy * 8];
}

__global__ void __launch_bounds__(256) comb_bias(
    const float* __restrict__ out_w, const float* __restrict__ out_b,
    const float* __restrict__ cbo, const float* __restrict__ tbo,
    float* __restrict__ bp)
{
    int v = threadIdx.x;
    float s = out_b[v];
    const float* row = out_w + (size_t)v * 1024;
    for (int e = 0; e < 512; e++) s += row[e] * cbo[e] + row[512 + e] * tbo[e];
    bp[v] = s;
}

template <int S>
__global__ void __launch_bounds__(256) attn_kernel(
    const float* __restrict__ q, const float* __restrict__ k,
    const float* __restrict__ v, float* __restrict__ o)
{
    constexpr int TN = S / 16;
    __shared__ union SU {
        struct { float qs[16][64]; float ks[16][S]; } a;
        float vs[S][64];
    } u;
    __shared__ float sc[64][S];

    const int b = blockIdx.x;
    const int tid = threadIdx.x;
    const int ty = tid >> 4, tx = tid & 15;

    float acc[4][TN];
#pragma unroll
    for (int r = 0; r < 4; r++)
#pragma unroll
        for (int j = 0; j < TN; j++) acc[r][j] = 0.f;

    for (int k0 = 0; k0 < Ed; k0 += 16) {
        {
            int r = tid >> 2, c4 = (tid & 3) << 2;
            float4 val = *reinterpret_cast<const float4*>(q + ((size_t)r * Bsz + b) * Ed + k0 + c4);
            u.a.qs[c4+0][r] = val.x; u.a.qs[c4+1][r] = val.y;
            u.a.qs[c4+2][r] = val.z; u.a.qs[c4+3][r] = val.w;
        }
        if (tid < S * 4) {
            int r = tid >> 2, c4 = (tid & 3) << 2;
            float4 val = *reinterpret_cast<const float4*>(k + ((size_t)b * S + r) * Ed + k0 + c4);
            u.a.ks[c4+0][r] = val.x; u.a.ks[c4+1][r] = val.y;
            u.a.ks[c4+2][r] = val.z; u.a.ks[c4+3][r] = val.w;
        }
        __syncthreads();
#pragma unroll
        for (int kk = 0; kk < 16; kk++) {
            float av[4], bv[TN];
#pragma unroll
            for (int r = 0; r < 4; r++) av[r] = u.a.qs[kk][ty * 4 + r];
#pragma unroll
            for (int j = 0; j < TN; j++) bv[j] = u.a.ks[kk][tx * TN + j];
#pragma unroll
            for (int r = 0; r < 4; r++)
#pragma unroll
                for (int j = 0; j < TN; j++) acc[r][j] += av[r] * bv[j];
        }
        __syncthreads();
    }
#pragma unroll
    for (int r = 0; r < 4; r++)
#pragma unroll
        for (int j = 0; j < TN; j++) sc[ty * 4 + r][tx * TN + j] = acc[r][j];
    __syncthreads();

    if (tid < 64) {
        float mx = -3.4e38f;
        for (int s = 0; s < S; s++) mx = fmaxf(mx, sc[tid][s]);
        float sum = 0.f;
        for (int s = 0; s < S; s++) { float e = expf(sc[tid][s] - mx); sc[tid][s] = e; sum += e; }
        float inv = 1.f / sum;
        for (int s = 0; s < S; s++) sc[tid][s] *= inv;
    }
    __syncthreads();

    for (int n0 = 0; n0 < Ed; n0 += 64) {
#pragma unroll
        for (int it = 0; it < (S * 16) / 256; ++it) {
            int f = tid + it * 256;
            int r = f >> 4, c4 = (f & 15) << 2;
            *reinterpret_cast<float4*>(&u.vs[r][c4]) =
                *reinterpret_cast<const float4*>(v + ((size_t)b * S + r) * Ed + n0 + c4);
        }
        __syncthreads();
        float oa[4][4] = {};
        for (int sk = 0; sk < S; sk++) {
            float p[4];
#pragma unroll
            for (int r = 0; r < 4; r++) p[r] = sc[ty * 4 + r][sk];
            float4 vv = *reinterpret_cast<const float4*>(&u.vs[sk][tx * 4]);
            float vf[4] = {vv.x, vv.y, vv.z, vv.w};
#pragma unroll
            for (int r = 0; r < 4; r++)
#pragma unroll
                for (int j = 0; j < 4; j++) oa[r][j] += p[r] * vf[j];
        }
#pragma unroll
        for (int r = 0; r < 4; r++) {
            size_t base = ((size_t)(ty * 4 + r) * Bsz + b) * Ed + n0 + tx * 4;
            *reinterpret_cast<float4*>(&o[base]) = make_float4(oa[r][0], oa[r][1], oa[r][2], oa[r][3]);
        }
        __syncthreads();
    }
}

// ---------------------------------------------------------------------------
// Warp-level exact 1.5-entmax (R15, proven)
// ---------------------------------------------------------------------------
__global__ void __launch_bounds__(256) entmax_warp(
    const float* __restrict__ logits, float* __restrict__ out)
{
    __shared__ float smw[8][256];
    const int w = threadIdx.x >> 5, lane = threadIdx.x & 31;
    const int row = blockIdx.x * 8 + w;
    const float* lrow = logits + (size_t)row * 256;

    float v[8], zo[8];
    float m = -3.4e38f;
#pragma unroll
    for (int i = 0; i < 8; i++) {
        float z = lrow[lane + 32 * i] * 0.5f;
        zo[i] = z;
        m = fmaxf(m, z);
    }
#pragma unroll
    for (int off = 16; off; off >>= 1) m = fmaxf(m, __shfl_xor_sync(0xffffffffu, m, off));
#pragma unroll
    for (int i = 0; i < 8; i++) { zo[i] -= m; v[i] = -zo[i]; }

#pragma unroll
    for (int k = 2; k <= 256; k <<= 1) {
#pragma unroll
        for (int j = 128; j >= 1; j >>= 1) {
            if (j >= k) continue;
            if (j >= 32) {
                const int d = j >> 5;
#pragma unroll
                for (int i = 0; i < 8; i++) {
                    if ((i & d) == 0) {
                        int i2 = i | d;
                        bool up = (((i << 5) & k) == 0);
                        float a = v[i], b = v[i2];
                        float mn = fminf(a, b), mx = fmaxf(a, b);
                        v[i]  = up ? mn : mx;
                        v[i2] = up ? mx : mn;
                    }
                }
            } else {
#pragma unroll
                for (int i = 0; i < 8; i++) {
                    float pv = __shfl_xor_sync(0xffffffffu, v[i], j);
                    int e = lane + (i << 5);
                    bool up = ((e & k) == 0);
                    bool islow = ((lane & j) == 0);
                    v[i] = (up == islow) ? fminf(v[i], pv) : fmaxf(v[i], pv);
                }
            }
        }
    }

#pragma unroll
    for (int i = 0; i < 8; i++) smw[w][lane + (i << 5)] = -v[i];
    __syncwarp();
    float c[8];
    {
        float4 t0 = *reinterpret_cast<float4*>(&smw[w][lane * 8]);
        float4 t1 = *reinterpret_cast<float4*>(&smw[w][lane * 8 + 4]);
        c[0]=t0.x; c[1]=t0.y; c[2]=t0.z; c[3]=t0.w;
        c[4]=t1.x; c[5]=t1.y; c[6]=t1.z; c[7]=t1.w;
    }
    __syncwarp();

    float s1 = 0.f, s2 = 0.f, p1[8], p2[8];
#pragma unroll
    for (int j = 0; j < 8; j++) { s1 += c[j]; s2 += c[j] * c[j]; p1[j] = s1; p2[j] = s2; }
    float o1 = s1, o2 = s2;
#pragma unroll
    for (int off = 1; off < 32; off <<= 1) {
        float a1 = __shfl_up_sync(0xffffffffu, o1, off);
        float a2 = __shfl_up_sync(0xffffffffu, o2, off);
        if (lane >= off) { o1 += a1; o2 += a2; }
    }
    o1 -= s1; o2 -= s2;

    float tau[8];
    int cnt = 0;
#pragma unroll
    for (int j = 0; j < 8; j++) {
        float cs1 = o1 + p1[j], cs2 = o2 + p2[j];
        float rho = (float)(lane * 8 + j + 1);
        float mean = cs1 / rho, msq = cs2 / rho;
        float ssv = rho * (msq - mean * mean);
        float delta = (1.0f - ssv) / rho;
        float sq = (delta > 0.f) ? sqrtf(delta) : 0.f;
        tau[j] = mean - sq;
        cnt += (tau[j] <= c[j]) ? 1 : 0;
    }
#pragma unroll
    for (int off = 16; off; off >>= 1) cnt += __shfl_xor_sync(0xffffffffu, cnt, off);

    *reinterpret_cast<float4*>(&smw[w][lane * 8])     = make_float4(tau[0], tau[1], tau[2], tau[3]);
    *reinterpret_cast<float4*>(&smw[w][lane * 8 + 4]) = make_float4(tau[4], tau[5], tau[6], tau[7]);
    __syncwarp();
    float tau_star = smw[w][cnt - 1];

    int t = row >> 9, b = row & 511;
    float* orow = out + ((size_t)b * Tc + t) * 256;
#pragma unroll
    for (int i = 0; i < 8; i++) {
        float y = fmaxf(zo[i] - tau_star, 0.f);
        orow[lane + (i << 5)] = y * y;
    }
}

extern "C" void kernel_launch(void* const* d_in, const int* in_sizes, int n_in,
                              void* d_out, int out_size)
{
    const float* char_enc = (const float*)d_in[0];
    const float* char_hn0 = (const float*)d_in[1];
    const float* char_cn0 = (const float*)d_in[2];
    const float* tag_enc  = (const float*)d_in[3];
    const float* tag_hn0  = (const float*)d_in[4];
    const float* tag_cn0  = (const float*)d_in[5];
    const float* tos      = (const float*)d_in[6];
    const float* w_ih     = (const float*)d_in[7];
    const float* w_hh     = (const float*)d_in[8];
    const float* b_ih     = (const float*)d_in[9];
    const float* b_hh     = (const float*)d_in[10];
    const float* cwq = (const float*)d_in[11];
    const float* cwk = (const float*)d_in[12];
    const float* cwv = (const float*)d_in[13];
    const float* cbq = (const float*)d_in[14];
    const float* cbk = (const float*)d_in[15];
    const float* cbv = (const float*)d_in[16];
    const float* cwo = (const float*)d_in[17];
    const float* cbo = (const float*)d_in[18];
    const float* twq = (const float*)d_in[19];
    const float* twk = (const float*)d_in[20];
    const float* twv = (const float*)d_in[21];
    const float* tbq = (const float*)d_in[22];
    const float* tbk = (const float*)d_in[23];
    const float* tbv = (const float*)d_in[24];
    const float* two_ = (const float*)d_in[25];
    const float* tbo = (const float*)d_in[26];
    const float* out_w = (const float*)d_in[27];
    const float* out_b = (const float*)d_in[28];
    float* out = (float*)d_out;

    float *xg, *h0, *c0, *hs, *qc, *kc, *vc, *qt, *kt, *vt, *oc, *ot, *lg;
    float *bias2, *Wc, *Wt, *cwoT, *twoT, *bcomb;
    cudaGetSymbolAddress((void**)&xg,    g_xgates);
    cudaGetSymbolAddress((void**)&h0,    g_h0);
    cudaGetSymbolAddress((void**)&c0,    g_c);
    cudaGetSymbolAddress((void**)&hs,    g_hs);
    cudaGetSymbolAddress((void**)&qc,    g_qc);
    cudaGetSymbolAddress((void**)&kc,    g_kc);
    cudaGetSymbolAddress((void**)&vc,    g_vc);
    cudaGetSymbolAddress((void**)&qt,    g_qt);
    cudaGetSymbolAddress((void**)&kt,    g_kt);
    cudaGetSymbolAddress((void**)&vt,    g_vt);
    cudaGetSymbolAddress((void**)&oc,    g_oc);
    cudaGetSymbolAddress((void**)&ot,    g_ot);
    cudaGetSymbolAddress((void**)&lg,    g_lg);
    cudaGetSymbolAddress((void**)&bias2, g_bias2);
    cudaGetSymbolAddress((void**)&Wc,    g_Wc);
    cudaGetSymbolAddress((void**)&Wt,    g_Wt);
    cudaGetSymbolAddress((void**)&cwoT,  g_cwoT);
    cudaGetSymbolAddress((void**)&twoT,  g_twoT);
    cudaGetSymbolAddress((void**)&bcomb, g_bcomb);

    __nv_bfloat16 *whhH, *whhL, *wihH, *wihL, *cwkH, *cwkL, *cwvH, *cwvL, *cwqH, *cwqL;
    __nv_bfloat16 *twkH, *twkL, *twvH, *twvL, *twqH, *twqL, *WcH, *WcL, *WtH, *WtL;
    cudaGetSymbolAddress((void**)&whhH, g_whhH); cudaGetSymbolAddress((void**)&whhL, g_whhL);
    cudaGetSymbolAddress((void**)&wihH, g_wihH); cudaGetSymbolAddress((void**)&wihL, g_wihL);
    cudaGetSymbolAddress((void**)&cwkH, g_cwkH); cudaGetSymbolAddress((void**)&cwkL, g_cwkL);
    cudaGetSymbolAddress((void**)&cwvH, g_cwvH); cudaGetSymbolAddress((void**)&cwvL, g_cwvL);
    cudaGetSymbolAddress((void**)&cwqH, g_cwqH); cudaGetSymbolAddress((void**)&cwqL, g_cwqL);
    cudaGetSymbolAddress((void**)&twkH, g_twkH); cudaGetSymbolAddress((void**)&twkL, g_twkL);
    cudaGetSymbolAddress((void**)&twvH, g_twvH); cudaGetSymbolAddress((void**)&twvL, g_twvL);
    cudaGetSymbolAddress((void**)&twqH, g_twqH); cudaGetSymbolAddress((void**)&twqL, g_twqL);
    cudaGetSymbolAddress((void**)&WcH,  g_WcH);  cudaGetSymbolAddress((void**)&WcL,  g_WcL);
    cudaGetSymbolAddress((void**)&WtH,  g_WtH);  cudaGetSymbolAddress((void**)&WtL,  g_WtL);

    const float qscale = 1.0f / sqrtf(512.0f);
    const int smem_g = 30720 * 4;   // 122880

    cudaFuncSetAttribute(mma_gemm2<0>, cudaFuncAttributeMaxDynamicSharedMemorySize, smem_g);
    cudaFuncSetAttribute(mma_gemm2<1>, cudaFuncAttributeMaxDynamicSharedMemorySize, smem_g);
    cudaFuncSetAttribute(mma_gemm2<2>, cudaFuncAttributeMaxDynamicSharedMemorySize, smem_g);
    cudaFuncSetAttribute(lstm_persist, cudaFuncAttributeMaxDynamicSharedMemorySize, LP_SMEM_BYTES);

    // all input-weight conversions in ONE launch
    conv_all<<<12288, 256>>>(w_ih, cwk, cwv, cwq, twk, twv, twq, w_hh,
                             wihH, wihL, cwkH, cwkL, cwvH, cwvL, cwqH, cwqL,
                             twkH, twkL, twvH, twvL, twqH, twqL, whhH, whhL);

    // big tensor GEMMs early (ncu capture targets)
    mma_gemm2<1><<<dim3(16, 128), 512, smem_g>>>(xg, tos, nullptr, wihH, wihL, nullptr, nullptr,
                                                 nullptr, 32768, 2048, 256, 256, 256, 1.0f);
    mma_gemm2<0><<<dim3(4, 128), 512, smem_g>>>(kc, char_enc, nullptr, cwkH, cwkL, nullptr, nullptr,
                                                cbk, 32768, 512, 512, 512, 512, 1.0f);
    mma_gemm2<0><<<dim3(4, 128), 512, smem_g>>>(vc, char_enc, nullptr, cwvH, cwvL, nullptr, nullptr,
                                                cbv, 32768, 512, 512, 512, 512, 1.0f);

    // small precomputes
    init_h0c0<<<1024, 256>>>(char_hn0, tag_hn0, char_cn0, tag_cn0, h0, c0);
    bias_add2048<<<8, 256>>>(b_ih, b_hh, bias2);
    transpose512<<<dim3(16, 16), 256>>>(cwo, cwoT);
    transpose512<<<dim3(16, 16), 256>>>(two_, twoT);
    comb_bias<<<1, 256>>>(out_w, out_b, cbo, tbo, bcomb);

    // folded head weights (fp32), then convert (one launch)
    gemm3<<<dim3(8, 2), 256>>>(Wc, out_w,       cwoT, 256, 512, 512, 1024);
    gemm3<<<dim3(8, 2), 256>>>(Wt, out_w + 512, twoT, 256, 512, 512, 1024);
    conv2<<<1024, 256>>>(Wc, Wt, WcH, WcL, WtH, WtL);

    // tag-side projections
    mma_gemm2<0><<<dim3(4, 32), 512, smem_g>>>(kt, tag_enc, nullptr, twkH, twkL, nullptr, nullptr,
                                               tbk, 8192, 512, 512, 512, 512, 1.0f);
    mma_gemm2<0><<<dim3(4, 32), 512, smem_g>>>(vt, tag_enc, nullptr, twvH, twvL, nullptr, nullptr,
                                               tbv, 8192, 512, 512, 512, 512, 1.0f);

    // persistent LSTM (one launch, 128 CTAs, internal 64-step loop, K-chunk 64)
    lstm_persist<<<dim3(32, 4), 256, LP_SMEM_BYTES>>>(h0, whhH, whhL, xg, bias2, c0, hs);

    // q projections
    mma_gemm2<0><<<dim3(4, 128), 512, smem_g>>>(qc, hs, nullptr, cwqH, cwqL, nullptr, nullptr,
                                                cbq, 32768, 512, 512, 512, 512, qscale);
    mma_gemm2<0><<<dim3(4, 128), 512, smem_g>>>(qt, hs, nullptr, twqH, twqL, nullptr, nullptr,
                                                tbq, 32768, 512, 512, 512, 512, qscale);

    // attention
    attn_kernel<64><<<512, 256>>>(qc, kc, vc, oc);
    attn_kernel<16><<<512, 256>>>(qt, kt, vt, ot);

    // logits = oc @ Wc^T + ot @ Wt^T + bcomb (concat GEMM, K=1024)
    mma_gemm2<2><<<dim3(2, 128), 512, smem_g>>>(lg, oc, ot, WcH, WcL, WtH, WtL,
                                                bcomb, 32768, 256, 1024, 512, 512, 1.0f);

    // warp-level entmax + transpose to (B,T,V)
    entmax_warp<<<4096, 256>>>(lg, out);
}

// round 17
// speedup vs baseline: 1.1100x; 1.0183x over previous
#include <cuda_runtime.h>
#include <cuda_bf16.h>
#include <math.h>
#include <stdint.h>

#define Bsz 512
#define Tc  64
#define Ed  512
#define Vd  256

__device__ float g_xgates[67108864];   // (T,B,4E)
__device__ float g_h0    [262144];
__device__ float g_c     [262144];
__device__ float g_hs    [16777216];   // (T,B,E)
__device__ float g_q     [33554432];   // (T*B, 1024): qc|qt
__device__ float g_kvc   [33554432];   // (B*64, 1024): kc|vc
__device__ float g_kvt   [8388608];    // (B*16, 1024): kt|vt
__device__ float g_oct   [33554432];   // (T*B, 1024): oc|ot
__device__ float g_lg    [8388608];    // (T,B,V)
__device__ float g_bias2 [2048];
__device__ float g_Wc    [131072];     // (V,E) fp32 staging
__device__ float g_Wt    [131072];
__device__ float g_cwoT  [262144];
__device__ float g_twoT  [262144];
__device__ float g_bcomb [256];
__device__ float g_bq    [1024];
__device__ float g_bkvc  [1024];
__device__ float g_bkvt  [1024];

__device__ __nv_bfloat16 g_whhH[1048576], g_whhL[1048576];
__device__ __nv_bfloat16 g_wihH[524288],  g_wihL[524288];
__device__ __nv_bfloat16 g_wqH[524288],   g_wqL[524288];    // [cwq;twq]
__device__ __nv_bfloat16 g_wkvcH[524288], g_wkvcL[524288];  // [cwk;cwv]
__device__ __nv_bfloat16 g_wkvtH[524288], g_wkvtL[524288];  // [twk;twv]
__device__ __nv_bfloat16 g_WcomH[262144], g_WcomL[262144];  // 256 x 1024 (Wc|Wt per row)

__device__ unsigned g_cnt;
__device__ volatile unsigned g_epoch;

// ======================= helpers ===========================================
__device__ __forceinline__ void ffma2(unsigned long long& d, unsigned long long a,
                                      unsigned long long b) {
    asm("fma.rn.f32x2 %0, %1, %2, %0;" : "+l"(d) : "l"(a), "l"(b));
}
__device__ __forceinline__ unsigned long long pack2(float x, float y) {
    unsigned long long r;
    asm("mov.b64 %0, {%1, %2};" : "=l"(r) : "r"(__float_as_uint(x)), "r"(__float_as_uint(y)));
    return r;
}
__device__ __forceinline__ void unpack2(unsigned long long d, float& lo, float& hi) {
    unsigned int l, h;
    asm("mov.b64 {%0, %1}, %2;" : "=r"(l), "=r"(h) : "l"(d));
    lo = __uint_as_float(l); hi = __uint_as_float(h);
}
__device__ __forceinline__ float sigmoidf_(float x) { return 1.0f / (1.0f + expf(-x)); }

__device__ __forceinline__ void mma16816(float* c, const uint32_t* a, uint32_t b0, uint32_t b1) {
    asm volatile(
        "mma.sync.aligned.m16n8k16.row.col.f32.bf16.bf16.f32 "
        "{%0,%1,%2,%3}, {%4,%5,%6,%7}, {%8,%9}, {%0,%1,%2,%3};"
        : "+f"(c[0]), "+f"(c[1]), "+f"(c[2]), "+f"(c[3])
        : "r"(a[0]), "r"(a[1]), "r"(a[2]), "r"(a[3]), "r"(b0), "r"(b1));
}
__device__ __forceinline__ void ldsm_x4(uint32_t* r, uint32_t addr) {
    asm volatile("ldmatrix.sync.aligned.m8n8.x4.shared.b16 {%0,%1,%2,%3}, [%4];"
                 : "=r"(r[0]), "=r"(r[1]), "=r"(r[2]), "=r"(r[3]) : "r"(addr));
}
__device__ __forceinline__ void ldsm_x2(uint32_t& r0, uint32_t& r1, uint32_t addr) {
    asm volatile("ldmatrix.sync.aligned.m8n8.x2.shared.b16 {%0,%1}, [%2];"
                 : "=r"(r0), "=r"(r1) : "r"(addr));
}
__device__ __forceinline__ void cvt_split4(float4 v, uint2& hi, uint2& lo) {
    __nv_bfloat16 h0 = __float2bfloat16(v.x), h1 = __float2bfloat16(v.y);
    __nv_bfloat16 h2 = __float2bfloat16(v.z), h3 = __float2bfloat16(v.w);
    __nv_bfloat16 l0 = __float2bfloat16(v.x - __bfloat162float(h0));
    __nv_bfloat16 l1 = __float2bfloat16(v.y - __bfloat162float(h1));
    __nv_bfloat16 l2 = __float2bfloat16(v.z - __bfloat162float(h2));
    __nv_bfloat16 l3 = __float2bfloat16(v.w - __bfloat162float(h3));
    hi.x = (uint32_t)__bfloat16_as_ushort(h0) | ((uint32_t)__bfloat16_as_ushort(h1) << 16);
    hi.y = (uint32_t)__bfloat16_as_ushort(h2) | ((uint32_t)__bfloat16_as_ushort(h3) << 16);
    lo.x = (uint32_t)__bfloat16_as_ushort(l0) | ((uint32_t)__bfloat16_as_ushort(l1) << 16);
    lo.y = (uint32_t)__bfloat16_as_ushort(l2) | ((uint32_t)__bfloat16_as_ushort(l3) << 16);
}
__device__ __forceinline__ void conv_one(const float* s, __nv_bfloat16* h,
                                         __nv_bfloat16* l, int i) {
    float v = s[i];
    __nv_bfloat16 hv = __float2bfloat16(v);
    h[i] = hv;
    l[i] = __float2bfloat16(v - __bfloat162float(hv));
}

// merged conversion: packs weights into merged N-stacked layouts, one launch
__global__ void __launch_bounds__(256) conv_all(
    const float* wih, const float* cwk, const float* cwv, const float* cwq,
    const float* twk, const float* twv, const float* twq, const float* whh,
    __nv_bfloat16* wihH, __nv_bfloat16* wihL,
    __nv_bfloat16* wkvcH, __nv_bfloat16* wkvcL,
    __nv_bfloat16* wqH, __nv_bfloat16* wqL,
    __nv_bfloat16* wkvtH, __nv_bfloat16* wkvtL,
    __nv_bfloat16* whhH, __nv_bfloat16* whhL)
{
    int i = blockIdx.x * 256 + threadIdx.x;    // covers 3145728
    if (i < 524288)        conv_one(wih, wihH, wihL, i);
    else if (i < 786432)   conv_one(cwk, wkvcH, wkvcL, i - 524288);
    else if (i < 1048576)  conv_one(cwv, wkvcH + 262144, wkvcL + 262144, i - 786432);
    else if (i < 1310720)  conv_one(cwq, wqH, wqL, i - 1048576);
    else if (i < 1572864)  conv_one(twq, wqH + 262144, wqL + 262144, i - 1310720);
    else if (i < 1835008)  conv_one(twk, wkvtH, wkvtL, i - 1572864);
    else if (i < 2097152)  conv_one(twv, wkvtH + 262144, wkvtL + 262144, i - 1835008);
    else                   conv_one(whh, whhH, whhL, i - 2097152);
}

// interleave Wc|Wt per output row into 256x1024 planes
__global__ void __launch_bounds__(256) conv2(
    const float* Wc, const float* Wt,
    __nv_bfloat16* WcomH, __nv_bfloat16* WcomL)
{
    int i = blockIdx.x * 256 + threadIdx.x;    // covers 262144
    int v = i >> 10, k = i & 1023;
    float s = (k < 512) ? Wc[v * 512 + k] : Wt[v * 512 + k - 512];
    __nv_bfloat16 hv = __float2bfloat16(s);
    WcomH[i] = hv;
    WcomL[i] = __float2bfloat16(s - __bfloat162float(hv));
}

__global__ void __launch_bounds__(512) pack_bias(
    const float* cbq, const float* tbq, const float* cbk, const float* cbv,
    const float* tbk, const float* tbv,
    float* bq, float* bkvc, float* bkvt)
{
    int i = threadIdx.x;
    bq[i]   = cbq[i];  bq[512 + i]   = tbq[i];
    bkvc[i] = cbk[i];  bkvc[512 + i] = cbv[i];
    bkvt[i] = tbk[i];  bkvt[512 + i] = tbv[i];
}

// ---------------------------------------------------------------------------
// mma.sync GEMM (NT), CTA 256x128, 512 threads / 16 warps (4m x 4n),
// warp tile 64x32, K-chunk 32. Plane-major MMA, dep distance 16.
// MODE 0 normal; 1 xgates gather.
// ---------------------------------------------------------------------------
template <int MODE>
__global__ void __launch_bounds__(512) mma_gemm2(
    float* __restrict__ C, const float* __restrict__ A,
    const __nv_bfloat16* __restrict__ BH, const __nv_bfloat16* __restrict__ BL,
    const float* __restrict__ bias, int M, int N, int K, int lda, int ldb, float alpha)
{
    extern __shared__ uint32_t sm[];

    const int tid  = threadIdx.x;
    const int lane = tid & 31, wid = tid >> 5;
    const int wm = wid >> 2, wn = wid & 3;
    const int m0 = blockIdx.y * 256, n0 = blockIdx.x * 128;
    const int gq = lane >> 2, pl = lane & 3;

    const uint32_t sb4 = (uint32_t)__cvta_generic_to_shared(sm);
    const int arow  = (lane & 7) + ((lane >> 3) & 1) * 8;
    const int akoff = (lane >> 4) * 4;
    const int brow  = lane & 7;
    const int bkoff = ((lane >> 3) & 1) * 4;

    float c[4][4][4];
#pragma unroll
    for (int i = 0; i < 4; i++)
#pragma unroll
        for (int j = 0; j < 4; j++)
#pragma unroll
            for (int q = 0; q < 4; q++) c[i][j][q] = 0.f;

    float4 avr[4];
    uint4 bhr, blr;

    auto gload = [&](int ch) {
        int k0 = ch << 5;
#pragma unroll
        for (int i = 0; i < 4; i++) {
            int f = tid + i * 512, r = f >> 3, cq = f & 7;
            if constexpr (MODE == 1) {
                int gm = m0 + r, tt = gm >> 9, bb = gm & 511;
                avr[i] = tt ? *reinterpret_cast<const float4*>(A + (size_t)bb * 16384 + tt * 256 + k0 + cq * 4)
                            : make_float4(0.f, 0.f, 0.f, 0.f);
            } else {
                avr[i] = *reinterpret_cast<const float4*>(A + (size_t)(m0 + r) * lda + k0 + cq * 4);
            }
        }
        {
            int r = tid >> 2, cq = tid & 3;
            bhr = *reinterpret_cast<const uint4*>(BH + (size_t)(n0 + r) * ldb + k0 + cq * 8);
            blr = *reinterpret_cast<const uint4*>(BL + (size_t)(n0 + r) * ldb + k0 + cq * 8);
        }
    };
    auto sstore = [&](int buf) {
        const int ab = buf * 5120;
#pragma unroll
        for (int i = 0; i < 4; i++) {
            int f = tid + i * 512, r = f >> 3, cq = f & 7;
            uint2 hi, lo;
            cvt_split4(avr[i], hi, lo);
            int idx = ab + r * 20 + cq * 2;
            *reinterpret_cast<uint2*>(&sm[idx])         = hi;
            *reinterpret_cast<uint2*>(&sm[10240 + idx]) = lo;
        }
        {
            int r = tid >> 2, cq = tid & 3;
            int idx = buf * 2560 + r * 20 + cq * 4;
            *reinterpret_cast<uint4*>(&sm[20480 + idx]) = bhr;
            *reinterpret_cast<uint4*>(&sm[25600 + idx]) = blr;
        }
    };

    const int nch = K >> 5;
    gload(0);
    sstore(0);
    __syncthreads();

    for (int ch = 0; ch < nch; ch++) {
        const int buf = ch & 1;
        const bool more = (ch + 1 < nch);
        if (more) gload(ch + 1);
        const int ab = buf * 5120;
        const int bb = buf * 2560;
#pragma unroll
        for (int s = 0; s < 2; s++) {
            uint32_t bh0[4], bh1[4], bl0[4], bl1[4];
#pragma unroll
            for (int nf = 0; nf < 4; nf++) {
                uint32_t baddr = sb4 + 4u * (uint32_t)(20480 + bb + (wn * 32 + nf * 8 + brow) * 20 + s * 8 + bkoff);
                ldsm_x2(bh0[nf], bh1[nf], baddr);
                ldsm_x2(bl0[nf], bl1[nf], baddr + 5120u * 4u);
            }
            uint32_t a[4][4];
#pragma unroll
            for (int mf = 0; mf < 4; mf++) {
                uint32_t aaddr = sb4 + 4u * (uint32_t)(ab + (wm * 64 + mf * 16 + arow) * 20 + s * 8 + akoff);
                ldsm_x4(a[mf], aaddr);
            }
            // plane hh (dep distance 16)
#pragma unroll
            for (int mf = 0; mf < 4; mf++)
#pragma unroll
                for (int nf = 0; nf < 4; nf++) mma16816(c[mf][nf], a[mf], bh0[nf], bh1[nf]);
            // plane hl
#pragma unroll
            for (int mf = 0; mf < 4; mf++)
#pragma unroll
                for (int nf = 0; nf < 4; nf++) mma16816(c[mf][nf], a[mf], bl0[nf], bl1[nf]);
            // reload A as lo, plane lh
#pragma unroll
            for (int mf = 0; mf < 4; mf++) {
                uint32_t aaddr = sb4 + 4u * (uint32_t)(ab + (wm * 64 + mf * 16 + arow) * 20 + s * 8 + akoff);
                ldsm_x4(a[mf], aaddr + 10240u * 4u);
            }
#pragma unroll
            for (int mf = 0; mf < 4; mf++)
#pragma unroll
                for (int nf = 0; nf < 4; nf++) mma16816(c[mf][nf], a[mf], bh0[nf], bh1[nf]);
        }
        if (more) {
            sstore(buf ^ 1);
            __syncthreads();
        }
    }

#pragma unroll
    for (int mf = 0; mf < 4; mf++) {
#pragma unroll
        for (int nf = 0; nf < 4; nf++) {
            int r  = m0 + wm * 64 + mf * 16 + gq;
            int cc = n0 + wn * 32 + nf * 8 + pl * 2;
            float b0 = 0.f, b1 = 0.f;
            if (bias) { b0 = bias[cc]; b1 = bias[cc + 1]; }
            *reinterpret_cast<float2*>(&C[(size_t)r * N + cc]) =
                make_float2(alpha * (c[mf][nf][0] + b0), alpha * (c[mf][nf][1] + b1));
            *reinterpret_cast<float2*>(&C[(size_t)(r + 8) * N + cc]) =
                make_float2(alpha * (c[mf][nf][2] + b0), alpha * (c[mf][nf][3] + b1));
        }
    }
}

// ---------------------------------------------------------------------------
// Persistent LSTM, K-chunk 64 (R16, proven)
// ---------------------------------------------------------------------------
#define LP_BH 0
#define LP_BL 16640
#define LP_A  33280
#define LP_SMEM_BYTES (53760 * 4)

__device__ __forceinline__ void grid_barrier128(int tid) {
    __threadfence();
    __syncthreads();
    if (tid == 0) {
        unsigned e = g_epoch;
        if (atomicAdd(&g_cnt, 1u) == 127u) {
            g_cnt = 0;
            __threadfence();
            g_epoch = e + 1;
        } else {
            while (g_epoch == e) { }
        }
    }
    __syncthreads();
}

__global__ void __launch_bounds__(256) lstm_persist(
    const float* __restrict__ h0,
    const __nv_bfloat16* __restrict__ whhH, const __nv_bfloat16* __restrict__ whhL,
    const float* __restrict__ xg, const float* __restrict__ bias2,
    const float* __restrict__ c0, float* __restrict__ hs)
{
    extern __shared__ uint32_t sm[];
    const int tid  = threadIdx.x;
    const int lane = tid & 31, wid = tid >> 5;
    const int wm = wid >> 2, wn = wid & 3;
    const int e0 = blockIdx.x * 16;
    const int m0 = blockIdx.y * 128;
    const int gq = lane >> 2, pl = lane & 3;

    const uint32_t sb4 = (uint32_t)__cvta_generic_to_shared(sm);
    const int arow  = (lane & 7) + ((lane >> 3) & 1) * 8;
    const int akoff = (lane >> 4) * 4;
    const int brow  = lane & 7;
    const int bkoff = ((lane >> 3) & 1) * 4;

#pragma unroll
    for (int i = 0; i < 16; i++) {
        int f = tid + i * 256;
        int r = f >> 6, q = f & 63;
        int gr = (r >> 4) * 512 + e0 + (r & 15);
        *reinterpret_cast<uint4*>(&sm[LP_BH + r * 260 + q * 4]) =
            *reinterpret_cast<const uint4*>(whhH + (size_t)gr * 512 + q * 8);
        *reinterpret_cast<uint4*>(&sm[LP_BL + r * 260 + q * 4]) =
            *reinterpret_cast<const uint4*>(whhL + (size_t)gr * 512 + q * 8);
    }

    float creg[8];
#pragma unroll
    for (int ir = 0; ir < 8; ir++) {
        int idx = tid + ir * 256;
        int row = idx >> 4, e = idx & 15;
        creg[ir] = c0[(size_t)(m0 + row) * 512 + e0 + e];
    }
    __syncthreads();

    for (int t = 0; t < 64; t++) {
        const float* hprev = (t == 0) ? h0 : (hs + (size_t)(t - 1) * 262144);
        const float* xg_t  = xg + (size_t)t * 1048576;
        float* hout        = hs + (size_t)t * 262144;

        float c[4][2][4];
#pragma unroll
        for (int i = 0; i < 4; i++)
#pragma unroll
            for (int j = 0; j < 2; j++)
#pragma unroll
                for (int q = 0; q < 4; q++) c[i][j][q] = 0.f;

        float4 avr[8];
        auto gloadA = [&](int ch) {
            int k0 = ch << 6;
#pragma unroll
            for (int i = 0; i < 8; i++) {
                int f = tid + i * 256, r = f >> 4, cq = f & 15;
                avr[i] = *reinterpret_cast<const float4*>(hprev + (size_t)(m0 + r) * 512 + k0 + cq * 4);
            }
        };
        auto sstoreA = [&](int buf) {
            const int base = LP_A + buf * 10240;
#pragma unroll
            for (int i = 0; i < 8; i++) {
                int f = tid + i * 256, r = f >> 4, cq = f & 15;
                uint2 hi, lo;
                cvt_split4(avr[i], hi, lo);
                int idx = base + (cq >> 3) * 2560 + r * 20 + (cq & 7) * 2;
                *reinterpret_cast<uint2*>(&sm[idx])        = hi;
                *reinterpret_cast<uint2*>(&sm[5120 + idx]) = lo;
            }
        };

        gloadA(0);
        sstoreA(0);
        __syncthreads();

        for (int ch = 0; ch < 8; ch++) {
            const int buf = ch & 1;
            const bool more = (ch < 7);
            if (more) gloadA(ch + 1);
#pragma unroll
            for (int sub = 0; sub < 2; sub++) {
                const int chh = ch * 2 + sub;
                const int ab = LP_A + buf * 10240 + sub * 2560;
#pragma unroll
                for (int s = 0; s < 2; s++) {
                    uint32_t ah[4][4], al4[4][4];
#pragma unroll
                    for (int mf = 0; mf < 4; mf++) {
                        uint32_t addr = sb4 + 4u * (uint32_t)(ab + (wm * 64 + mf * 16 + arow) * 20 + s * 8 + akoff);
                        ldsm_x4(ah[mf], addr);
                        ldsm_x4(al4[mf], addr + 5120u * 4u);
                    }
#pragma unroll
                    for (int nf = 0; nf < 2; nf++) {
                        uint32_t baddr = sb4 + 4u * (uint32_t)((wn * 16 + nf * 8 + brow) * 260 + chh * 16 + s * 8 + bkoff);
                        uint32_t bh0, bh1, bl0, bl1;
                        ldsm_x2(bh0, bh1, baddr + LP_BH * 4u);
                        ldsm_x2(bl0, bl1, baddr + LP_BL * 4u);
#pragma unroll
                        for (int mf = 0; mf < 4; mf++) {
                            mma16816(c[mf][nf], ah[mf], bh0, bh1);
                            mma16816(c[mf][nf], ah[mf], bl0, bl1);
                            mma16816(c[mf][nf], al4[mf], bh0, bh1);
                        }
                    }
                }
            }
            if (more) {
                sstoreA(buf ^ 1);
                __syncthreads();
            }
        }

        __syncthreads();
        float* Gs = reinterpret_cast<float*>(&sm[LP_A]);
#pragma unroll
        for (int mf = 0; mf < 4; mf++) {
#pragma unroll
            for (int nf = 0; nf < 2; nf++) {
                int rr = wm * 64 + mf * 16 + gq;
                int cc = wn * 16 + nf * 8 + pl * 2;
                Gs[rr * 64 + cc]           = c[mf][nf][0];
                Gs[rr * 64 + cc + 1]       = c[mf][nf][1];
                Gs[(rr + 8) * 64 + cc]     = c[mf][nf][2];
                Gs[(rr + 8) * 64 + cc + 1] = c[mf][nf][3];
            }
        }
        __syncthreads();

#pragma unroll
        for (int ir = 0; ir < 8; ir++) {
            int idx = tid + ir * 256;
            int row = idx >> 4, e = idx & 15;
            int b = m0 + row, ni = e0 + e;
            const float* xr = xg_t + (size_t)b * 2048;
            float gi = Gs[row * 64 + e]      + bias2[ni]        + xr[ni];
            float gf = Gs[row * 64 + 16 + e] + bias2[ni + 512]  + xr[ni + 512];
            float gg = Gs[row * 64 + 32 + e] + bias2[ni + 1024] + xr[ni + 1024];
            float go = Gs[row * 64 + 48 + e] + bias2[ni + 1536] + xr[ni + 1536];
            float cc2 = sigmoidf_(gf) * creg[ir] + sigmoidf_(gi) * tanhf(gg);
            creg[ir] = cc2;
            hout[(size_t)b * 512 + ni] = sigmoidf_(go) * tanhf(cc2);
        }

        if (t < 63) grid_barrier128(tid);
    }
}

// ======================= SIMT gemm (Wc/Wt precompute only) ==================
__global__ void __launch_bounds__(256) gemm3(
    float* __restrict__ C, const float* __restrict__ A,
    const float* __restrict__ Bw, int M, int N, int K, int lda)
{
    __shared__ float As[2][16][128];
    __shared__ float Bs[2][16][64];

    const int tid = threadIdx.x;
    const int m0  = blockIdx.y * 128;
    const int n0  = blockIdx.x * 64;
    const int ty  = tid >> 4;
    const int tx  = tid & 15;
    const int r0 = tid >> 2;
    const int r1 = r0 + 64;
    const int c4 = (tid & 3) << 2;

    float4 pa0, pa1, pb;
    auto loadG = [&](int k0) {
        int gk = k0 + c4;
        pa0 = *reinterpret_cast<const float4*>(A + (size_t)(m0 + r0) * lda + gk);
        pa1 = *reinterpret_cast<const float4*>(A + (size_t)(m0 + r1) * lda + gk);
        pb = *reinterpret_cast<const float4*>(Bw + (size_t)(n0 + r0) * K + gk);
    };
    auto storeS = [&](int buf) {
        As[buf][c4 + 0][r0] = pa0.x; As[buf][c4 + 1][r0] = pa0.y;
        As[buf][c4 + 2][r0] = pa0.z; As[buf][c4 + 3][r0] = pa0.w;
        As[buf][c4 + 0][r1] = pa1.x; As[buf][c4 + 1][r1] = pa1.y;
        As[buf][c4 + 2][r1] = pa1.z; As[buf][c4 + 3][r1] = pa1.w;
        Bs[buf][c4 + 0][r0] = pb.x;  Bs[buf][c4 + 1][r0] = pb.y;
        Bs[buf][c4 + 2][r0] = pb.z;  Bs[buf][c4 + 3][r0] = pb.w;
    };

    unsigned long long acc[4][4];
#pragma unroll
    for (int i = 0; i < 4; i++)
#pragma unroll
        for (int j = 0; j < 4; j++) acc[i][j] = 0ull;

    loadG(0); storeS(0); __syncthreads();

    const int nt = K >> 4;
    for (int kt = 0; kt < nt; kt++) {
        const int cur = kt & 1;
        if (kt + 1 < nt) loadG((kt + 1) << 4);
#pragma unroll
        for (int kk = 0; kk < 16; ++kk) {
            const ulonglong2* ap = reinterpret_cast<const ulonglong2*>(&As[cur][kk][ty * 8]);
            ulonglong2 u0 = ap[0], u1 = ap[1];
            unsigned long long a2[4] = {u0.x, u0.y, u1.x, u1.y};
            float4 b = *reinterpret_cast<const float4*>(&Bs[cur][kk][tx * 4]);
            unsigned long long bd[4] = {pack2(b.x, b.x), pack2(b.y, b.y),
                                        pack2(b.z, b.z), pack2(b.w, b.w)};
#pragma unroll
            for (int i = 0; i < 4; i++)
#pragma unroll
                for (int j = 0; j < 4; j++) ffma2(acc[i][j], a2[i], bd[j]);
        }
        if (kt + 1 < nt) { storeS(cur ^ 1); __syncthreads(); }
    }

#pragma unroll
    for (int i = 0; i < 4; i++) {
        const int gm = m0 + ty * 8 + 2 * i;
#pragma unroll
        for (int j = 0; j < 4; j++) {
            float lo, hi;
            unpack2(acc[i][j], lo, hi);
            const int gn = n0 + tx * 4 + j;
            C[(size_t)gm * N + gn]       = lo;
            C[(size_t)(gm + 1) * N + gn] = hi;
        }
    }
}

__global__ void __launch_bounds__(256) init_h0c0(
    const float* __restrict__ chn, const float* __restrict__ thn,
    const float* __restrict__ ccn, const float* __restrict__ tcn,
    float* __restrict__ h0, float* __restrict__ c0)
{
    int idx = blockIdx.x * 256 + threadIdx.x;
    int bb = idx >> 9, e = idx & 511;
    h0[idx] = (e < 256) ? chn[bb * 256 + e] : thn[bb * 256 + e - 256];
    c0[idx] = (e < 256) ? ccn[bb * 256 + e] : tcn[bb * 256 + e - 256];
}

__global__ void __launch_bounds__(256) bias_add2048(
    const float* __restrict__ a, const float* __restrict__ b, float* __restrict__ o)
{
    int i = blockIdx.x * 256 + threadIdx.x;
    o[i] = a[i] + b[i];
}

__global__ void __launch_bounds__(256) transpose512(
    const float* __restrict__ in, float* __restrict__ out)
{
    __shared__ float t[32][33];
    int tx = threadIdx.x & 31, ty = threadIdx.x >> 5;
    int x0 = blockIdx.x * 32, y0 = blockIdx.y * 32;
#pragma unroll
    for (int iy = 0; iy < 4; iy++)
        t[ty + iy * 8][tx] = in[(size_t)(y0 + ty + iy * 8) * 512 + x0 + tx];
    __syncthreads();
#pragma unroll
    for (int iy = 0; iy < 4; iy++)
        out[(size_t)(x0 + ty + iy * 8) * 512 + y0 + tx] = t[tx][ty + iy * 8];
}

__global__ void __launch_bounds__(256) comb_bias(
    const float* __restrict__ out_w, const float* __restrict__ out_b,
    const float* __restrict__ cbo, const float* __restrict__ tbo,
    float* __restrict__ bp)
{
    int v = threadIdx.x;
    float s = out_b[v];
    const float* row = out_w + (size_t)v * 1024;
    for (int e = 0; e < 512; e++) s += row[e] * cbo[e] + row[512 + e] * tbo[e];
    bp[v] = s;
}

// ---------------------------------------------------------------------------
// Fused attention; merged buffers: q (row 1024, offset qoff), kv (row 1024:
// k at 0, v at 512), output into oct (row 1024, offset ooff).
// ---------------------------------------------------------------------------
template <int S>
__global__ void __launch_bounds__(256) attn_kernel(
    const float* __restrict__ q, int qoff, const float* __restrict__ kv,
    float* __restrict__ o, int ooff)
{
    constexpr int TN = S / 16;
    __shared__ union SU {
        struct { float qs[16][64]; float ks[16][S]; } a;
        float vs[S][64];
    } u;
    __shared__ float sc[64][S];

    const int b = blockIdx.x;
    const int tid = threadIdx.x;
    const int ty = tid >> 4, tx = tid & 15;

    float acc[4][TN];
#pragma unroll
    for (int r = 0; r < 4; r++)
#pragma unroll
        for (int j = 0; j < TN; j++) acc[r][j] = 0.f;

    for (int k0 = 0; k0 < Ed; k0 += 16) {
        {
            int r = tid >> 2, c4 = (tid & 3) << 2;
            float4 val = *reinterpret_cast<const float4*>(q + ((size_t)r * Bsz + b) * 1024 + qoff + k0 + c4);
            u.a.qs[c4+0][r] = val.x; u.a.qs[c4+1][r] = val.y;
            u.a.qs[c4+2][r] = val.z; u.a.qs[c4+3][r] = val.w;
        }
        if (tid < S * 4) {
            int r = tid >> 2, c4 = (tid & 3) << 2;
            float4 val = *reinterpret_cast<const float4*>(kv + ((size_t)b * S + r) * 1024 + k0 + c4);
            u.a.ks[c4+0][r] = val.x; u.a.ks[c4+1][r] = val.y;
            u.a.ks[c4+2][r] = val.z; u.a.ks[c4+3][r] = val.w;
        }
        __syncthreads();
#pragma unroll
        for (int kk = 0; kk < 16; kk++) {
            float av[4], bv[TN];
#pragma unroll
            for (int r = 0; r < 4; r++) av[r] = u.a.qs[kk][ty * 4 + r];
#pragma unroll
            for (int j = 0; j < TN; j++) bv[j] = u.a.ks[kk][tx * TN + j];
#pragma unroll
            for (int r = 0; r < 4; r++)
#pragma unroll
                for (int j = 0; j < TN; j++) acc[r][j] += av[r] * bv[j];
        }
        __syncthreads();
    }
#pragma unroll
    for (int r = 0; r < 4; r++)
#pragma unroll
        for (int j = 0; j < TN; j++) sc[ty * 4 + r][tx * TN + j] = acc[r][j];
    __syncthreads();

    if (tid < 64) {
        float mx = -3.4e38f;
        for (int s = 0; s < S; s++) mx = fmaxf(mx, sc[tid][s]);
        float sum = 0.f;
        for (int s = 0; s < S; s++) { float e = expf(sc[tid][s] - mx); sc[tid][s] = e; sum += e; }
        float inv = 1.f / sum;
        for (int s = 0; s < S; s++) sc[tid][s] *= inv;
    }
    __syncthreads();

    for (int n0 = 0; n0 < Ed; n0 += 64) {
#pragma unroll
        for (int it = 0; it < (S * 16) / 256; ++it) {
            int f = tid + it * 256;
            int r = f >> 4, c4 = (f & 15) << 2;
            *reinterpret_cast<float4*>(&u.vs[r][c4]) =
                *reinterpret_cast<const float4*>(kv + ((size_t)b * S + r) * 1024 + 512 + n0 + c4);
        }
        __syncthreads();
        float oa[4][4] = {};
        for (int sk = 0; sk < S; sk++) {
            float p[4];
#pragma unroll
            for (int r = 0; r < 4; r++) p[r] = sc[ty * 4 + r][sk];
            float4 vv = *reinterpret_cast<const float4*>(&u.vs[sk][tx * 4]);
            float vf[4] = {vv.x, vv.y, vv.z, vv.w};
#pragma unroll
            for (int r = 0; r < 4; r++)
#pragma unroll
                for (int j = 0; j < 4; j++) oa[r][j] += p[r] * vf[j];
        }
#pragma unroll
        for (int r = 0; r < 4; r++) {
            size_t base = ((size_t)(ty * 4 + r) * Bsz + b) * 1024 + ooff + n0 + tx * 4;
            *reinterpret_cast<float4*>(&o[base]) = make_float4(oa[r][0], oa[r][1], oa[r][2], oa[r][3]);
        }
        __syncthreads();
    }
}

// ---------------------------------------------------------------------------
// Warp-level exact 1.5-entmax (R15, proven)
// ---------------------------------------------------------------------------
__global__ void __launch_bounds__(256) entmax_warp(
    const float* __restrict__ logits, float* __restrict__ out)
{
    __shared__ float smw[8][256];
    const int w = threadIdx.x >> 5, lane = threadIdx.x & 31;
    const int row = blockIdx.x * 8 + w;
    const float* lrow = logits + (size_t)row * 256;

    float v[8], zo[8];
    float m = -3.4e38f;
#pragma unroll
    for (int i = 0; i < 8; i++) {
        float z = lrow[lane + 32 * i] * 0.5f;
        zo[i] = z;
        m = fmaxf(m, z);
    }
#pragma unroll
    for (int off = 16; off; off >>= 1) m = fmaxf(m, __shfl_xor_sync(0xffffffffu, m, off));
#pragma unroll
    for (int i = 0; i < 8; i++) { zo[i] -= m; v[i] = -zo[i]; }

#pragma unroll
    for (int k = 2; k <= 256; k <<= 1) {
#pragma unroll
        for (int j = 128; j >= 1; j >>= 1) {
            if (j >= k) continue;
            if (j >= 32) {
                const int d = j >> 5;
#pragma unroll
                for (int i = 0; i < 8; i++) {
                    if ((i & d) == 0) {
                        int i2 = i | d;
                        bool up = (((i << 5) & k) == 0);
                        float a = v[i], b = v[i2];
                        float mn = fminf(a, b), mx = fmaxf(a, b);
                        v[i]  = up ? mn : mx;
                        v[i2] = up ? mx : mn;
                    }
                }
            } else {
#pragma unroll
                for (int i = 0; i < 8; i++) {
                    float pv = __shfl_xor_sync(0xffffffffu, v[i], j);
                    int e = lane + (i << 5);
                    bool up = ((e & k) == 0);
                    bool islow = ((lane & j) == 0);
                    v[i] = (up == islow) ? fminf(v[i], pv) : fmaxf(v[i], pv);
                }
            }
        }
    }

#pragma unroll
    for (int i = 0; i < 8; i++) smw[w][lane + (i << 5)] = -v[i];
    __syncwarp();
    float c[8];
    {
        float4 t0 = *reinterpret_cast<float4*>(&smw[w][lane * 8]);
        float4 t1 = *reinterpret_cast<float4*>(&smw[w][lane * 8 + 4]);
        c[0]=t0.x; c[1]=t0.y; c[2]=t0.z; c[3]=t0.w;
        c[4]=t1.x; c[5]=t1.y; c[6]=t1.z; c[7]=t1.w;
    }
    __syncwarp();

    float s1 = 0.f, s2 = 0.f, p1[8], p2[8];
#pragma unroll
    for (int j = 0; j < 8; j++) { s1 += c[j]; s2 += c[j] * c[j]; p1[j] = s1; p2[j] = s2; }
    float o1 = s1, o2 = s2;
#pragma unroll
    for (int off = 1; off < 32; off <<= 1) {
        float a1 = __shfl_up_sync(0xffffffffu, o1, off);
        float a2 = __shfl_up_sync(0xffffffffu, o2, off);
        if (lane >= off) { o1 += a1; o2 += a2; }
    }
    o1 -= s1; o2 -= s2;

    float tau[8];
    int cnt = 0;
#pragma unroll
    for (int j = 0; j < 8; j++) {
        float cs1 = o1 + p1[j], cs2 = o2 + p2[j];
        float rho = (float)(lane * 8 + j + 1);
        float mean = cs1 / rho, msq = cs2 / rho;
        float ssv = rho * (msq - mean * mean);
        float delta = (1.0f - ssv) / rho;
        float sq = (delta > 0.f) ? sqrtf(delta) : 0.f;
        tau[j] = mean - sq;
        cnt += (tau[j] <= c[j]) ? 1 : 0;
    }
#pragma unroll
    for (int off = 16; off; off >>= 1) cnt += __shfl_xor_sync(0xffffffffu, cnt, off);

    *reinterpret_cast<float4*>(&smw[w][lane * 8])     = make_float4(tau[0], tau[1], tau[2], tau[3]);
    *reinterpret_cast<float4*>(&smw[w][lane * 8 + 4]) = make_float4(tau[4], tau[5], tau[6], tau[7]);
    __syncwarp();
    float tau_star = smw[w][cnt - 1];

    int t = row >> 9, b = row & 511;
    float* orow = out + ((size_t)b * Tc + t) * 256;
#pragma unroll
    for (int i = 0; i < 8; i++) {
        float y = fmaxf(zo[i] - tau_star, 0.f);
        orow[lane + (i << 5)] = y * y;
    }
}

extern "C" void kernel_launch(void* const* d_in, const int* in_sizes, int n_in,
                              void* d_out, int out_size)
{
    const float* char_enc = (const float*)d_in[0];
    const float* char_hn0 = (const float*)d_in[1];
    const float* char_cn0 = (const float*)d_in[2];
    const float* tag_enc  = (const float*)d_in[3];
    const float* tag_hn0  = (const float*)d_in[4];
    const float* tag_cn0  = (const float*)d_in[5];
    const float* tos      = (const float*)d_in[6];
    const float* w_ih     = (const float*)d_in[7];
    const float* w_hh     = (const float*)d_in[8];
    const float* b_ih     = (const float*)d_in[9];
    const float* b_hh     = (const float*)d_in[10];
    const float* cwq = (const float*)d_in[11];
    const float* cwk = (const float*)d_in[12];
    const float* cwv = (const float*)d_in[13];
    const float* cbq = (const float*)d_in[14];
    const float* cbk = (const float*)d_in[15];
    const float* cbv = (const float*)d_in[16];
    const float* cwo = (const float*)d_in[17];
    const float* cbo = (const float*)d_in[18];
    const float* twq = (const float*)d_in[19];
    const float* twk = (const float*)d_in[20];
    const float* twv = (const float*)d_in[21];
    const float* tbq = (const float*)d_in[22];
    const float* tbk = (const float*)d_in[23];
    const float* tbv = (const float*)d_in[24];
    const float* two_ = (const float*)d_in[25];
    const float* tbo = (const float*)d_in[26];
    const float* out_w = (const float*)d_in[27];
    const float* out_b = (const float*)d_in[28];
    float* out = (float*)d_out;

    float *xg, *h0, *c0, *hs, *qb, *kvc, *kvt, *oct, *lg;
    float *bias2, *Wc, *Wt, *cwoT, *twoT, *bcomb, *bq, *bkvc, *bkvt;
    cudaGetSymbolAddress((void**)&xg,    g_xgates);
    cudaGetSymbolAddress((void**)&h0,    g_h0);
    cudaGetSymbolAddress((void**)&c0,    g_c);
    cudaGetSymbolAddress((void**)&hs,    g_hs);
    cudaGetSymbolAddress((void**)&qb,    g_q);
    cudaGetSymbolAddress((void**)&kvc,   g_kvc);
    cudaGetSymbolAddress((void**)&kvt,   g_kvt);
    cudaGetSymbolAddress((void**)&oct,   g_oct);
    cudaGetSymbolAddress((void**)&lg,    g_lg);
    cudaGetSymbolAddress((void**)&bias2, g_bias2);
    cudaGetSymbolAddress((void**)&Wc,    g_Wc);
    cudaGetSymbolAddress((void**)&Wt,    g_Wt);
    cudaGetSymbolAddress((void**)&cwoT,  g_cwoT);
    cudaGetSymbolAddress((void**)&twoT,  g_twoT);
    cudaGetSymbolAddress((void**)&bcomb, g_bcomb);
    cudaGetSymbolAddress((void**)&bq,    g_bq);
    cudaGetSymbolAddress((void**)&bkvc,  g_bkvc);
    cudaGetSymbolAddress((void**)&bkvt,  g_bkvt);

    __nv_bfloat16 *whhH, *whhL, *wihH, *wihL, *wqH, *wqL;
    __nv_bfloat16 *wkvcH, *wkvcL, *wkvtH, *wkvtL, *WcomH, *WcomL;
    cudaGetSymbolAddress((void**)&whhH,  g_whhH);  cudaGetSymbolAddress((void**)&whhL,  g_whhL);
    cudaGetSymbolAddress((void**)&wihH,  g_wihH);  cudaGetSymbolAddress((void**)&wihL,  g_wihL);
    cudaGetSymbolAddress((void**)&wqH,   g_wqH);   cudaGetSymbolAddress((void**)&wqL,   g_wqL);
    cudaGetSymbolAddress((void**)&wkvcH, g_wkvcH); cudaGetSymbolAddress((void**)&wkvcL, g_wkvcL);
    cudaGetSymbolAddress((void**)&wkvtH, g_wkvtH); cudaGetSymbolAddress((void**)&wkvtL, g_wkvtL);
    cudaGetSymbolAddress((void**)&WcomH, g_WcomH); cudaGetSymbolAddress((void**)&WcomL, g_WcomL);

    const float qscale = 1.0f / sqrtf(512.0f);
    const int smem_g = 30720 * 4;   // 122880

    cudaFuncSetAttribute(mma_gemm2<0>, cudaFuncAttributeMaxDynamicSharedMemorySize, smem_g);
    cudaFuncSetAttribute(mma_gemm2<1>, cudaFuncAttributeMaxDynamicSharedMemorySize, smem_g);
    cudaFuncSetAttribute(lstm_persist, cudaFuncAttributeMaxDynamicSharedMemorySize, LP_SMEM_BYTES);

    // all input-weight conversions (merged layouts) in ONE launch
    conv_all<<<12288, 256>>>(w_ih, cwk, cwv, cwq, twk, twv, twq, w_hh,
                             wihH, wihL, wkvcH, wkvcL, wqH, wqL, wkvtH, wkvtL,
                             whhH, whhL);

    // big tensor GEMMs early (ncu capture targets)
    mma_gemm2<1><<<dim3(16, 128), 512, smem_g>>>(xg, tos, wihH, wihL, nullptr,
                                                 32768, 2048, 256, 256, 256, 1.0f);
    pack_bias<<<1, 512>>>(cbq, tbq, cbk, cbv, tbk, tbv, bq, bkvc, bkvt);
    mma_gemm2<0><<<dim3(8, 128), 512, smem_g>>>(kvc, char_enc, wkvcH, wkvcL, bkvc,
                                                32768, 1024, 512, 512, 512, 1.0f);

    // small precomputes
    init_h0c0<<<1024, 256>>>(char_hn0, tag_hn0, char_cn0, tag_cn0, h0, c0);
    bias_add2048<<<8, 256>>>(b_ih, b_hh, bias2);
    transpose512<<<dim3(16, 16), 256>>>(cwo, cwoT);
    transpose512<<<dim3(16, 16), 256>>>(two_, twoT);
    comb_bias<<<1, 256>>>(out_w, out_b, cbo, tbo, bcomb);

    // folded head weights (fp32), then interleave+convert (one launch)
    gemm3<<<dim3(8, 2), 256>>>(Wc, out_w,       cwoT, 256, 512, 512, 1024);
    gemm3<<<dim3(8, 2), 256>>>(Wt, out_w + 512, twoT, 256, 512, 512, 1024);
    conv2<<<1024, 256>>>(Wc, Wt, WcomH, WcomL);

    // tag-side projections (merged kt|vt)
    mma_gemm2<0><<<dim3(8, 32), 512, smem_g>>>(kvt, tag_enc, wkvtH, wkvtL, bkvt,
                                               8192, 1024, 512, 512, 512, 1.0f);

    // persistent LSTM (one launch, 128 CTAs, internal 64-step loop, K-chunk 64)
    lstm_persist<<<dim3(32, 4), 256, LP_SMEM_BYTES>>>(h0, whhH, whhL, xg, bias2, c0, hs);

    // merged q projection (qc|qt)
    mma_gemm2<0><<<dim3(8, 128), 512, smem_g>>>(qb, hs, wqH, wqL, bq,
                                                32768, 1024, 512, 512, 512, qscale);

    // attention (writes oc|ot halves of oct)
    attn_kernel<64><<<512, 256>>>(qb, 0,   kvc, oct, 0);
    attn_kernel<16><<<512, 256>>>(qb, 512, kvt, oct, 512);

    // logits = oct @ Wcom^T + bcomb  (plain K=1024 GEMM)
    mma_gemm2<0><<<dim3(2, 128), 512, smem_g>>>(lg, oct, WcomH, WcomL, bcomb,
                                                32768, 256, 1024, 1024, 1024, 1.0f);

    // warp-level entmax + transpose to (B,T,V)
    entmax_warp<<<4096, 256>>>(lg, out);
}